// round 5
// baseline (speedup 1.0000x reference)
#include <cuda_runtime.h>
#include <cstdint>
#include <cfloat>

// Problem constants (fixed shapes for MergeNN_38903813767173)
#define B_ 2048
#define N_ 20000
#define D_ 64
#define DY_ 32
#define L_ 100
#define ETA_ 0.01f

#define TJ 64
#define TI 64
#define NSLAB 25
#define SLABROWS 800          // 25*800 = 20000 exactly; 13 chunks of 64 (tail 32)
#define NCHUNK 13
#define NSLAB2 (2 * NSLAB)    // phaseC partials split by i-parity

#define XAP 36                // split x/es tile stride (half-width 32 + pad)
#define SSP 68                // row-major star/f chunk stride (16B-aligned rows for cp.async)
#define MSP 68

typedef unsigned long long ull;

__device__ __forceinline__ ull pack2(float lo, float hi) {
    ull r; asm("mov.b64 %0, {%1, %2};" : "=l"(r) : "f"(lo), "f"(hi)); return r;
}
__device__ __forceinline__ void unpack2(ull v, float& lo, float& hi) {
    asm("mov.b64 {%0, %1}, %2;" : "=f"(lo), "=f"(hi) : "l"(v));
}
__device__ __forceinline__ void ffma2(ull& d, ull a, ull b) {
    asm("fma.rn.f32x2 %0, %1, %2, %0;" : "+l"(d) : "l"(a), "l"(b));
}
__device__ __forceinline__ unsigned su32(const void* p) {
    return (unsigned)__cvta_generic_to_shared(p);
}
#define CPA16(dst, src) \
    asm volatile("cp.async.ca.shared.global [%0], [%1], 16;" :: "r"(dst), "l"(src))
#define CP_COMMIT() asm volatile("cp.async.commit_group;")
#define CP_WAIT0()  asm volatile("cp.async.wait_group 0;" ::: "memory")

// ---------------- scratch (device globals; no allocations allowed) ----------
__device__ float g_nx[B_];
__device__ float g_ns[N_];
__device__ float g_nf1[N_];
__device__ float g_nf2[N_];
__device__ int   g_match[B_];

__device__ float g_esum_part[NSLAB][B_];
__device__ float g_acc1_part[NSLAB][B_][D_];
__device__ float g_acc2_part[NSLAB][B_][D_];

__device__ float g_xt1[B_][D_];
__device__ float g_xt2[B_][D_];
__device__ float g_nxt1[B_];
__device__ float g_nxt2[B_];
__device__ int   g_yidx1[B_];
__device__ int   g_yidx2[B_];

__device__ float g_num1_part[NSLAB2][B_][DY_];
__device__ float g_num2_part[NSLAB2][B_][DY_];
__device__ float g_den1_part[NSLAB2][B_];
__device__ float g_den2_part[NSLAB2][B_];

// ---------------- K0: squared norms + match init -----------------------------
__global__ void k_prep(const float* __restrict__ x, const float* __restrict__ star,
                       const float* __restrict__ f1, const float* __restrict__ f2) {
    int gid = blockIdx.x * blockDim.x + threadIdx.x;
    const float* src;
    float* dst;
    if (gid < B_) {
        g_match[gid] = 0x7fffffff;
        src = x + gid * D_;        dst = &g_nx[gid];
    } else if (gid < B_ + N_) {
        int r = gid - B_;          src = star + r * D_; dst = &g_ns[r];
    } else if (gid < B_ + 2 * N_) {
        int r = gid - B_ - N_;     src = f1 + r * D_;   dst = &g_nf1[r];
    } else if (gid < B_ + 3 * N_) {
        int r = gid - B_ - 2 * N_; src = f2 + r * D_;   dst = &g_nf2[r];
    } else {
        return;
    }
    float s = 0.f;
    const float4* p = reinterpret_cast<const float4*>(src);
#pragma unroll
    for (int i = 0; i < 16; i++) {
        float4 v = p[i];
        s += v.x * v.x + v.y * v.y + v.z * v.z + v.w * v.w;
    }
    *dst = s;
}

// ---------------- K1: phase A — e_star, esum, feats^T @ e_star ---------------
struct __align__(16) SmemA {
    float xA[D_][XAP];    // x tile cols with j&4==0, k-major, phys col (j>>3)*4+(j&3)
    float xB[D_][XAP];    // cols with j&4==4
    float nxs[TJ];
    float ss[TI][SSP];    // star chunk, row-major
    float nss[TI];
    float f1s[TI][D_];
    float f2s[TI][D_];
    float esA[TI][XAP];   // e cols j&4==0
    float esB[TI][XAP];
    float esred[16][SSP]; // esum partials [dg][j]
};

__global__ __launch_bounds__(256, 2)
void k_phaseA(const float* __restrict__ x, const float* __restrict__ star,
              const float* __restrict__ f1, const float* __restrict__ f2) {
    extern __shared__ char raw_[];
    SmemA& sm = *reinterpret_cast<SmemA*>(raw_);
    const int tid   = threadIdx.x;
    const int j0    = blockIdx.x * TJ;
    const int slab  = blockIdx.y;
    const int ibase = slab * SLABROWS;
    const int iend  = ibase + SLABROWS;

    // x tile: transpose into split k-major arrays (once per block)
    for (int idx = tid; idx < TJ * 16; idx += 256) {
        int j = idx >> 4, k4 = (idx & 15) * 4;
        float4 v = *reinterpret_cast<const float4*>(x + (j0 + j) * D_ + k4);
        float* arr = (j & 4) ? &sm.xB[0][0] : &sm.xA[0][0];
        int jp = (j >> 3) * 4 + (j & 3);
        arr[(k4 + 0) * XAP + jp] = v.x; arr[(k4 + 1) * XAP + jp] = v.y;
        arr[(k4 + 2) * XAP + jp] = v.z; arr[(k4 + 3) * XAP + jp] = v.w;
    }
    if (tid < TJ) sm.nxs[tid] = g_nx[j0 + tid];

    const int cg   = tid & 7;           // distance: cols cg*8..+7
    const int row2 = (tid >> 3) * 2;    // distance: rows row2, row2+1
    const int sid  = tid >> 7;          // accumulate: feature set
    const int jg   = tid & 7;           // accumulate: j block of 8
    const int dg   = (tid >> 3) & 15;   // accumulate: d block of 4
    const int dg4  = dg * 4;

    ull acc_[8][2];
#pragma unroll
    for (int a = 0; a < 8; a++) { acc_[a][0] = 0ull; acc_[a][1] = 0ull; }
    float esum8[8];
#pragma unroll
    for (int a = 0; a < 8; a++) esum8[a] = 0.f;

    const unsigned ss_b = su32(&sm.ss[0][0]);
    const unsigned f1_b = su32(&sm.f1s[0][0]);
    const unsigned f2_b = su32(&sm.f2s[0][0]);

    for (int c = 0; c < NCHUNK; c++) {
        const int i0 = ibase + c * TI;
        __syncthreads();   // previous consumers done / x-tile visible
        // tile loads via cp.async (12 x 16B per thread)
        for (int idx = tid; idx < TI * 16; idx += 256) {
            int r = idx >> 4, kb = (idx & 15) * 16;
            long gb = (long)min(i0 + r, N_ - 1) * 256;
            CPA16(ss_b + r * (SSP * 4) + kb, (const char*)star + gb + kb);
            CPA16(f1_b + r * 256 + kb, (const char*)f1 + gb + kb);
            CPA16(f2_b + r * 256 + kb, (const char*)f2 + gb + kb);
        }
        if (tid < TI) sm.nss[tid] = g_ns[min(i0 + tid, N_ - 1)];
        CP_COMMIT(); CP_WAIT0();
        __syncthreads();

        // --- distance: 2 rows x 8 cols, packed f32x2 ---
        ull a_[2][4];
#pragma unroll
        for (int r = 0; r < 2; r++)
#pragma unroll
            for (int cc = 0; cc < 4; cc++) a_[r][cc] = 0ull;
#pragma unroll 8
        for (int k = 0; k < D_; k++) {
            ulonglong2 xq0 = *reinterpret_cast<const ulonglong2*>(&sm.xA[k][cg * 4]);
            ulonglong2 xq1 = *reinterpret_cast<const ulonglong2*>(&sm.xB[k][cg * 4]);
            float s0 = sm.ss[row2][k];
            float s1 = sm.ss[row2 + 1][k];
            ull sp0 = pack2(s0, s0), sp1 = pack2(s1, s1);
            ffma2(a_[0][0], sp0, xq0.x); ffma2(a_[0][1], sp0, xq0.y);
            ffma2(a_[0][2], sp0, xq1.x); ffma2(a_[0][3], sp0, xq1.y);
            ffma2(a_[1][0], sp1, xq0.x); ffma2(a_[1][1], sp1, xq0.y);
            ffma2(a_[1][2], sp1, xq1.x); ffma2(a_[1][3], sp1, xq1.y);
        }
        {
            float4 nxa = *reinterpret_cast<const float4*>(&sm.nxs[cg * 8]);
            float4 nxb = *reinterpret_cast<const float4*>(&sm.nxs[cg * 8 + 4]);
            float nx[8] = {nxa.x, nxa.y, nxa.z, nxa.w, nxb.x, nxb.y, nxb.z, nxb.w};
#pragma unroll
            for (int r = 0; r < 2; r++) {
                int gi = i0 + row2 + r;
                bool valid = gi < iend;
                float ns = sm.nss[row2 + r];
                float ev[8];
#pragma unroll
                for (int c2 = 0; c2 < 4; c2++) {
                    float d0, d1;
                    // a_[r]: [0],[1] -> cols cg*8+0..3 ; [2],[3] -> cols cg*8+4..7
                    unpack2(a_[r][c2 < 2 ? c2 : c2], d0, d1);
                    int cbase = (c2 < 2) ? 2 * c2 : 4 + 2 * (c2 - 2);
                    float r0 = ns + nx[cbase]     - 2.f * d0;
                    float r1 = ns + nx[cbase + 1] - 2.f * d1;
                    if (valid && r0 <= 0.f) atomicMin(&g_match[j0 + cg * 8 + cbase], gi);
                    if (valid && r1 <= 0.f) atomicMin(&g_match[j0 + cg * 8 + cbase + 1], gi);
                    ev[cbase]     = valid ? __expf(-fmaxf(r0, 0.f)) : 0.f;
                    ev[cbase + 1] = valid ? __expf(-fmaxf(r1, 0.f)) : 0.f;
                }
                *reinterpret_cast<float4*>(&sm.esA[row2 + r][cg * 4]) =
                    make_float4(ev[0], ev[1], ev[2], ev[3]);
                *reinterpret_cast<float4*>(&sm.esB[row2 + r][cg * 4]) =
                    make_float4(ev[4], ev[5], ev[6], ev[7]);
            }
        }
        __syncthreads();   // es ready

        // --- accumulate: acc[j][d] += f[i][d]*e[i][j], 8j x 4d, set-split ---
        const float* fbase = sid ? &sm.f2s[0][0] : &sm.f1s[0][0];
#pragma unroll 4
        for (int i = 0; i < TI; i++) {
            float4 ea = *reinterpret_cast<const float4*>(&sm.esA[i][jg * 4]);
            float4 eb = *reinterpret_cast<const float4*>(&sm.esB[i][jg * 4]);
            ulonglong2 fq = *reinterpret_cast<const ulonglong2*>(fbase + i * D_ + dg4);
            ull e0 = pack2(ea.x, ea.x), e1 = pack2(ea.y, ea.y);
            ull e2 = pack2(ea.z, ea.z), e3 = pack2(ea.w, ea.w);
            ull e4 = pack2(eb.x, eb.x), e5 = pack2(eb.y, eb.y);
            ull e6 = pack2(eb.z, eb.z), e7 = pack2(eb.w, eb.w);
            ffma2(acc_[0][0], e0, fq.x); ffma2(acc_[0][1], e0, fq.y);
            ffma2(acc_[1][0], e1, fq.x); ffma2(acc_[1][1], e1, fq.y);
            ffma2(acc_[2][0], e2, fq.x); ffma2(acc_[2][1], e2, fq.y);
            ffma2(acc_[3][0], e3, fq.x); ffma2(acc_[3][1], e3, fq.y);
            ffma2(acc_[4][0], e4, fq.x); ffma2(acc_[4][1], e4, fq.y);
            ffma2(acc_[5][0], e5, fq.x); ffma2(acc_[5][1], e5, fq.y);
            ffma2(acc_[6][0], e6, fq.x); ffma2(acc_[6][1], e6, fq.y);
            ffma2(acc_[7][0], e7, fq.x); ffma2(acc_[7][1], e7, fq.y);
            if (sid == 0 && dg == (i & 15)) {
                esum8[0] += ea.x; esum8[1] += ea.y; esum8[2] += ea.z; esum8[3] += ea.w;
                esum8[4] += eb.x; esum8[5] += eb.y; esum8[6] += eb.z; esum8[7] += eb.w;
            }
        }
    }

    // write acc partials: logical j = j0 + jg*8 + jj
    {
        float (*accp)[B_][D_] = sid ? g_acc2_part : g_acc1_part;
#pragma unroll
        for (int jj = 0; jj < 8; jj++) {
            float o0, o1, o2, o3;
            unpack2(acc_[jj][0], o0, o1);
            unpack2(acc_[jj][1], o2, o3);
            *reinterpret_cast<float4*>(&accp[slab][j0 + jg * 8 + jj][dg4]) =
                make_float4(o0, o1, o2, o3);
        }
    }
    if (sid == 0) {
#pragma unroll
        for (int jj = 0; jj < 8; jj++) sm.esred[dg][jg * 8 + jj] = esum8[jj];
    }
    __syncthreads();
    if (tid < TJ) {
        float s = 0.f;
#pragma unroll
        for (int g = 0; g < 16; g++) s += sm.esred[g][tid];
        g_esum_part[slab][j0 + tid] = s;
    }
}

// ---------------- K2: middle — xt, y = xt@W+b, argmin label ------------------
__global__ __launch_bounds__(128)
void k_mid(const float* __restrict__ f1, const float* __restrict__ f2,
           const float* __restrict__ W1, const float* __restrict__ b1,
           const float* __restrict__ W2, const float* __restrict__ b2,
           const float* __restrict__ u1, const float* __restrict__ u2) {
    int j = blockIdx.x;
    int t = threadIdx.x;   // 128 threads

    __shared__ float xts[D_];
    __shared__ float ys[DY_];
    __shared__ float esum_s;
    __shared__ float ny_s;
    __shared__ float redv[128];
    __shared__ int   redi[128];

    int  mi = g_match[j];
    bool hm = (mi != 0x7fffffff);
    if (t == 0) {
        float s = 0.f;
        for (int k = 0; k < NSLAB; k++) s += g_esum_part[k][j];
        esum_s = s;
    }
    __syncthreads();

    for (int br = 0; br < 2; br++) {
        const float* f  = br ? f2 : f1;
        const float* W  = br ? W2 : W1;
        const float* bb = br ? b2 : b1;
        const float* u  = br ? u2 : u1;

        if (t < D_) {
            float a = 0.f;
            if (br) { for (int k = 0; k < NSLAB; k++) a += g_acc2_part[k][j][t]; }
            else    { for (int k = 0; k < NSLAB; k++) a += g_acc1_part[k][j][t]; }
            float v = hm ? f[mi * D_ + t] : a / esum_s;
            xts[t] = v;
            if (br) g_xt2[j][t] = v; else g_xt1[j][t] = v;
        }
        __syncthreads();
        if (t == 0) {
            float s = 0.f;
            for (int d = 0; d < D_; d++) s += xts[d] * xts[d];
            if (br) g_nxt2[j] = s; else g_nxt1[j] = s;
        }
        if (t < DY_) {
            float a = bb[t];
            for (int d = 0; d < D_; d++) a += xts[d] * W[d * DY_ + t];
            ys[t] = a;
        }
        __syncthreads();
        if (t == 0) {
            float s = 0.f;
            for (int dy = 0; dy < DY_; dy++) s += ys[dy] * ys[dy];
            ny_s = s;
        }
        __syncthreads();

        float v = FLT_MAX;
        int   vi = 0x7fffffff;
        if (t < L_) {
            float nu = 0.f, dot = 0.f;
            for (int dy = 0; dy < DY_; dy++) {
                float uu = u[t * DY_ + dy];
                nu += uu * uu;
                dot += uu * ys[dy];
            }
            v = fmaxf(ny_s + nu - 2.f * dot, 0.f);
            vi = t;
        }
        redv[t] = v; redi[t] = vi;
        __syncthreads();
        for (int off = 64; off > 0; off >>= 1) {
            if (t < off) {
                float v2 = redv[t + off]; int i2 = redi[t + off];
                if (v2 < redv[t] || (v2 == redv[t] && i2 < redi[t])) {
                    redv[t] = v2; redi[t] = i2;
                }
            }
            __syncthreads();
        }
        if (t == 0) { if (br) g_yidx2[j] = redi[0]; else g_yidx1[j] = redi[0]; }
        __syncthreads();
    }
}

// ---------------- K3: phase C — e2, labels^T @ e2 ---------------------------
struct __align__(16) SmemC {
    float multT[L_][MSP]; // exp(-eta*ld[l][yidx[j]])
    float xA[D_][XAP];    // xt tile split k-major
    float xB[D_][XAP];
    float nxts[TJ];
    int   yidxs[TJ];
    float fs[TI][SSP];
    float nfs[TI];
    int   lidxs[TI];
    float sls[TI][DY_];
    float esA[TI][XAP];
    float esB[TI][XAP];
    float denred[16][SSP]; // [par*8+dyg][j]
};

__global__ __launch_bounds__(256, 2)
void k_phaseC(const float* __restrict__ f1, const float* __restrict__ f2,
              const float* __restrict__ slb,
              const float* __restrict__ ld1, const float* __restrict__ ld2,
              const int* __restrict__ li1, const int* __restrict__ li2) {
    extern __shared__ char raw_[];
    SmemC& sm = *reinterpret_cast<SmemC*>(raw_);
    const int tid   = threadIdx.x;
    const int j0    = blockIdx.x * TJ;
    const int slab  = blockIdx.y;
    const int br    = blockIdx.z;
    const int ibase = slab * SLABROWS;
    const int iend  = ibase + SLABROWS;

    const float* f   = br ? f2 : f1;
    const float* ld  = br ? ld2 : ld1;
    const int*   li  = br ? li2 : li1;
    const float* nf  = br ? g_nf2 : g_nf1;
    const float (*xt)[D_] = br ? g_xt2 : g_xt1;
    const float* nxt = br ? g_nxt2 : g_nxt1;
    const int*   yix = br ? g_yidx2 : g_yidx1;
    float (*nump)[B_][DY_] = br ? g_num2_part : g_num1_part;
    float (*denp)[B_]      = br ? g_den2_part : g_den1_part;

    // xt tile split k-major
    for (int idx = tid; idx < TJ * 16; idx += 256) {
        int j = idx >> 4, k4 = (idx & 15) * 4;
        float4 v = *reinterpret_cast<const float4*>(&xt[j0 + j][k4]);
        float* arr = (j & 4) ? &sm.xB[0][0] : &sm.xA[0][0];
        int jp = (j >> 3) * 4 + (j & 3);
        arr[(k4 + 0) * XAP + jp] = v.x; arr[(k4 + 1) * XAP + jp] = v.y;
        arr[(k4 + 2) * XAP + jp] = v.z; arr[(k4 + 3) * XAP + jp] = v.w;
    }
    if (tid < TJ) { sm.nxts[tid] = nxt[j0 + tid]; sm.yidxs[tid] = yix[j0 + tid]; }
    __syncthreads();
    // multT: exp(-eta * ld[l][yidx[j]]), once per block
    for (int idx = tid; idx < L_ * TJ; idx += 256) {
        int l = idx >> 6, j = idx & 63;
        sm.multT[l][j] = __expf(-ETA_ * ld[l * L_ + sm.yidxs[j]]);
    }

    const int cg   = tid & 7;
    const int row2 = (tid >> 3) * 2;
    const int par  = tid >> 7;          // i-parity group
    const int t7   = tid & 127;
    const int jgc  = t7 & 15;           // 16 groups x 4 j
    const int dyg  = t7 >> 4;           // 8 groups x 4 dy
    const int dy4  = dyg * 4;

    ull accn[4][2];
#pragma unroll
    for (int a = 0; a < 4; a++) { accn[a][0] = 0ull; accn[a][1] = 0ull; }
    float4 den4 = make_float4(0.f, 0.f, 0.f, 0.f);

    const unsigned fs_b = su32(&sm.fs[0][0]);
    const unsigned sl_b = su32(&sm.sls[0][0]);

    for (int c = 0; c < NCHUNK; c++) {
        const int i0 = ibase + c * TI;
        __syncthreads();
        for (int idx = tid; idx < TI * 16; idx += 256) {
            int r = idx >> 4, kb = (idx & 15) * 16;
            long gb = (long)min(i0 + r, N_ - 1) * 256;
            CPA16(fs_b + r * (SSP * 4) + kb, (const char*)f + gb + kb);
        }
        for (int idx = tid; idx < TI * 8; idx += 256) {
            int r = idx >> 3, kb = (idx & 7) * 16;
            long gb = (long)min(i0 + r, N_ - 1) * 128;
            CPA16(sl_b + r * 128 + kb, (const char*)slb + gb + kb);
        }
        if (tid < TI) {
            int gi = min(i0 + tid, N_ - 1);
            sm.nfs[tid] = nf[gi];
            sm.lidxs[tid] = li[gi];
        }
        CP_COMMIT(); CP_WAIT0();
        __syncthreads();

        // --- distance ---
        ull a_[2][4];
#pragma unroll
        for (int r = 0; r < 2; r++)
#pragma unroll
            for (int cc = 0; cc < 4; cc++) a_[r][cc] = 0ull;
#pragma unroll 8
        for (int k = 0; k < D_; k++) {
            ulonglong2 xq0 = *reinterpret_cast<const ulonglong2*>(&sm.xA[k][cg * 4]);
            ulonglong2 xq1 = *reinterpret_cast<const ulonglong2*>(&sm.xB[k][cg * 4]);
            float s0 = sm.fs[row2][k];
            float s1 = sm.fs[row2 + 1][k];
            ull sp0 = pack2(s0, s0), sp1 = pack2(s1, s1);
            ffma2(a_[0][0], sp0, xq0.x); ffma2(a_[0][1], sp0, xq0.y);
            ffma2(a_[0][2], sp0, xq1.x); ffma2(a_[0][3], sp0, xq1.y);
            ffma2(a_[1][0], sp1, xq0.x); ffma2(a_[1][1], sp1, xq0.y);
            ffma2(a_[1][2], sp1, xq1.x); ffma2(a_[1][3], sp1, xq1.y);
        }
        {
            float4 nxa = *reinterpret_cast<const float4*>(&sm.nxts[cg * 8]);
            float4 nxb = *reinterpret_cast<const float4*>(&sm.nxts[cg * 8 + 4]);
            float nx[8] = {nxa.x, nxa.y, nxa.z, nxa.w, nxb.x, nxb.y, nxb.z, nxb.w};
#pragma unroll
            for (int r = 0; r < 2; r++) {
                int gi = i0 + row2 + r;
                bool valid = gi < iend;
                float nfv = sm.nfs[row2 + r];
                int lrow = sm.lidxs[row2 + r];
                float4 m0 = *reinterpret_cast<const float4*>(&sm.multT[lrow][cg * 8]);
                float4 m1 = *reinterpret_cast<const float4*>(&sm.multT[lrow][cg * 8 + 4]);
                float mv[8] = {m0.x, m0.y, m0.z, m0.w, m1.x, m1.y, m1.z, m1.w};
                float ev[8];
#pragma unroll
                for (int c2 = 0; c2 < 4; c2++) {
                    float d0, d1;
                    unpack2(a_[r][c2], d0, d1);
                    int cbase = (c2 < 2) ? 2 * c2 : 4 + 2 * (c2 - 2);
                    float r0 = fmaxf(nfv + nx[cbase]     - 2.f * d0, 0.f);
                    float r1 = fmaxf(nfv + nx[cbase + 1] - 2.f * d1, 0.f);
                    ev[cbase]     = valid ? __expf(-r0) * mv[cbase]     : 0.f;
                    ev[cbase + 1] = valid ? __expf(-r1) * mv[cbase + 1] : 0.f;
                }
                *reinterpret_cast<float4*>(&sm.esA[row2 + r][cg * 4]) =
                    make_float4(ev[0], ev[1], ev[2], ev[3]);
                *reinterpret_cast<float4*>(&sm.esB[row2 + r][cg * 4]) =
                    make_float4(ev[4], ev[5], ev[6], ev[7]);
            }
        }
        __syncthreads();

        // --- accumulate: num[j][dy] += sl[i][dy]*e[i][j], 4j x 4dy, i-parity split ---
        const float* ebase = (jgc & 1) ? &sm.esB[0][0] : &sm.esA[0][0];
        const int ecol = (jgc >> 1) * 4;
#pragma unroll 4
        for (int i = par; i < TI; i += 2) {
            float4 e4 = *reinterpret_cast<const float4*>(ebase + i * XAP + ecol);
            ulonglong2 slq = *reinterpret_cast<const ulonglong2*>(&sm.sls[i][dy4]);
            ull e0 = pack2(e4.x, e4.x), e1 = pack2(e4.y, e4.y);
            ull e2 = pack2(e4.z, e4.z), e3 = pack2(e4.w, e4.w);
            ffma2(accn[0][0], e0, slq.x); ffma2(accn[0][1], e0, slq.y);
            ffma2(accn[1][0], e1, slq.x); ffma2(accn[1][1], e1, slq.y);
            ffma2(accn[2][0], e2, slq.x); ffma2(accn[2][1], e2, slq.y);
            ffma2(accn[3][0], e3, slq.x); ffma2(accn[3][1], e3, slq.y);
            if (dyg == ((i >> 1) & 7)) {
                den4.x += e4.x; den4.y += e4.y; den4.z += e4.z; den4.w += e4.w;
            }
        }
    }

    // logical j for accumulate thread: j = jgc*4 + {0..3}?  No: split mapping.
    // ebase/ecol covers logical cols: jgc even -> esA phys (jgc>>1)*4 -> j = (jgc>>1)*8 + {0..3}
    //                                 jgc odd  -> esB phys (jgc>>1)*4 -> j = (jgc>>1)*8 + {4..7}
    const int jlog = (jgc >> 1) * 8 + (jgc & 1) * 4;
    const int slab2 = slab * 2 + par;
#pragma unroll
    for (int jj = 0; jj < 4; jj++) {
        float o0, o1, o2, o3;
        unpack2(accn[jj][0], o0, o1);
        unpack2(accn[jj][1], o2, o3);
        *reinterpret_cast<float4*>(&nump[slab2][j0 + jlog + jj][dy4]) =
            make_float4(o0, o1, o2, o3);
    }
    *reinterpret_cast<float4*>(&sm.denred[par * 8 + dyg][jlog]) = den4;
    __syncthreads();
    if (tid < TJ * 2) {
        int p = tid >> 6, j = tid & 63;
        float s = 0.f;
#pragma unroll
        for (int g = 0; g < 8; g++) s += sm.denred[p * 8 + g][j];
        denp[slab * 2 + p][j0 + j] = s;
    }
}

// ---------------- K4: reduce partials, combine branches ----------------------
__global__ void k_out(float* __restrict__ out) {
    int gid = blockIdx.x * blockDim.x + threadIdx.x;
    if (gid >= B_ * DY_) return;
    int j = gid >> 5, dy = gid & 31;
    float n1 = 0.f, d1 = 0.f, n2 = 0.f, d2 = 0.f;
    for (int s = 0; s < NSLAB2; s++) {
        n1 += g_num1_part[s][j][dy];
        d1 += g_den1_part[s][j];
        n2 += g_num2_part[s][j][dy];
        d2 += g_den2_part[s][j];
    }
    out[gid] = 0.5f * (n1 / d1 + n2 / d2);
}

// ---------------- launch -----------------------------------------------------
extern "C" void kernel_launch(void* const* d_in, const int* in_sizes, int n_in,
                              void* d_out, int out_size) {
    const float* x    = (const float*)d_in[0];
    const float* star = (const float*)d_in[1];
    const float* slb  = (const float*)d_in[2];
    const float* f1   = (const float*)d_in[3];
    const float* f2   = (const float*)d_in[4];
    const float* u1   = (const float*)d_in[5];
    const float* u2   = (const float*)d_in[6];
    const float* ld1  = (const float*)d_in[7];
    const float* ld2  = (const float*)d_in[8];
    const float* W1   = (const float*)d_in[9];
    const float* b1   = (const float*)d_in[10];
    const float* W2   = (const float*)d_in[11];
    const float* b2   = (const float*)d_in[12];
    const int*   li1  = (const int*)d_in[13];
    const int*   li2  = (const int*)d_in[14];
    float* out = (float*)d_out;

    cudaFuncSetAttribute(k_phaseA, cudaFuncAttributeMaxDynamicSharedMemorySize,
                         (int)sizeof(SmemA));
    cudaFuncSetAttribute(k_phaseC, cudaFuncAttributeMaxDynamicSharedMemorySize,
                         (int)sizeof(SmemC));

    k_prep<<<(B_ + 3 * N_ + 255) / 256, 256>>>(x, star, f1, f2);
    k_phaseA<<<dim3(B_ / TJ, NSLAB), 256, sizeof(SmemA)>>>(x, star, f1, f2);
    k_mid<<<B_, 128>>>(f1, f2, W1, b1, W2, b2, u1, u2);
    k_phaseC<<<dim3(B_ / TJ, NSLAB, 2), 256, sizeof(SmemC)>>>(f1, f2, slb, ld1, ld2, li1, li2);
    k_out<<<(B_ * DY_ + 255) / 256, 256>>>(out);
}

// round 7
// speedup vs baseline: 1.9102x; 1.9102x over previous
#include <cuda_runtime.h>
#include <cstdint>
#include <cfloat>

// Problem constants (fixed shapes for MergeNN_38903813767173)
#define B_ 2048
#define N_ 20000
#define D_ 64
#define DY_ 32
#define L_ 100
#define ETA_ 0.01f

#define NP 20224            // 158*128 padded i-extent
#define NCH_TOT 158
#define NSLAB_A 10
#define CPS_A 16
#define NSLAB_C 5
#define CPS_C 32

#define XS_STR 68           // X/star/f/xt smem row stride (words): frag banks 4r+c
#define E_STR 132           // E smem row stride: frag banks 4r+c
#define FC_COLS 136         // fcomb cols (64+64+1+7 pad): B-frag banks 8r+c
#define SL_COLS 40          // slbcomb cols (32+1+7 pad)

// ---------------- helpers ----------------------------------------------------
__device__ __forceinline__ uint32_t su32(const void* p) {
    return (uint32_t)__cvta_generic_to_shared(p);
}
#define CPA16(dst, src) \
    asm volatile("cp.async.ca.shared.global [%0], [%1], 16;" :: "r"(dst), "l"(src))
#define CP_COMMIT() asm volatile("cp.async.commit_group;")
#define CP_WAIT0()  asm volatile("cp.async.wait_group 0;" ::: "memory")

__device__ __forceinline__ uint32_t tf(float x) {
    uint32_t r; asm("cvt.rna.tf32.f32 %0, %1;" : "=r"(r) : "f"(x)); return r;
}
__device__ __forceinline__ void mma8(float c[4], const uint32_t a[4], const uint32_t b[2]) {
    asm volatile("mma.sync.aligned.m16n8k8.row.col.f32.tf32.tf32.f32 "
                 "{%0,%1,%2,%3}, {%4,%5,%6,%7}, {%8,%9}, {%0,%1,%2,%3};"
                 : "+f"(c[0]), "+f"(c[1]), "+f"(c[2]), "+f"(c[3])
                 : "r"(a[0]), "r"(a[1]), "r"(a[2]), "r"(a[3]), "r"(b[0]), "r"(b[1]));
}

// ---------------- scratch ----------------------------------------------------
__device__ float g_nx[B_];
__device__ float g_ns[N_];
__device__ float g_nf1[N_];
__device__ float g_nf2[N_];
__device__ int   g_match[B_];

__device__ float g_fcomb[NP][FC_COLS];    // tf32-rounded: e^{-ns}[f1|f2|1|0pad]
__device__ float g_slbc[2][NP][SL_COLS];  // tf32-rounded: e^{-nf}[slb|1|0pad]

__device__ float g_esum_part[NSLAB_A][B_];
__device__ float g_acc1_part[NSLAB_A][B_][D_];
__device__ float g_acc2_part[NSLAB_A][B_][D_];

__device__ float g_xt1[B_][D_];
__device__ float g_xt2[B_][D_];
__device__ float g_nxt1[B_];
__device__ float g_nxt2[B_];
__device__ int   g_yidx1[B_];
__device__ int   g_yidx2[B_];

__device__ float g_num1_part[NSLAB_C][B_][DY_];
__device__ float g_num2_part[NSLAB_C][B_][DY_];
__device__ float g_den1_part[NSLAB_C][B_];
__device__ float g_den2_part[NSLAB_C][B_];

// ---------------- K0: norms + match init -------------------------------------
__global__ void k_prep(const float* __restrict__ x, const float* __restrict__ star,
                       const float* __restrict__ f1, const float* __restrict__ f2) {
    int gid = blockIdx.x * blockDim.x + threadIdx.x;
    const float* src;
    float* dst;
    if (gid < B_) {
        g_match[gid] = 0x7fffffff;
        src = x + gid * D_;        dst = &g_nx[gid];
    } else if (gid < B_ + N_) {
        int r = gid - B_;          src = star + r * D_; dst = &g_ns[r];
    } else if (gid < B_ + 2 * N_) {
        int r = gid - B_ - N_;     src = f1 + r * D_;   dst = &g_nf1[r];
    } else if (gid < B_ + 3 * N_) {
        int r = gid - B_ - 2 * N_; src = f2 + r * D_;   dst = &g_nf2[r];
    } else return;
    float s = 0.f;
    const float4* p = reinterpret_cast<const float4*>(src);
#pragma unroll
    for (int i = 0; i < 16; i++) {
        float4 v = p[i];
        s += v.x * v.x + v.y * v.y + v.z * v.z + v.w * v.w;
    }
    *dst = s;
}

// ---------------- K0b: fcomb -------------------------------------------------
__global__ void k_fc(const float* __restrict__ f1, const float* __restrict__ f2) {
    int gid = blockIdx.x * blockDim.x + threadIdx.x;
    if (gid >= NP * FC_COLS) return;
    int i = gid / FC_COLS, c = gid % FC_COLS;
    float v = 0.f;
    if (i < N_) {
        float sc = __expf(-g_ns[i]);
        if (c < 64)       v = f1[i * 64 + c] * sc;
        else if (c < 128) v = f2[i * 64 + c - 64] * sc;
        else if (c == 128) v = sc;
    }
    g_fcomb[i][c] = __uint_as_float(tf(v));
}

// ---------------- K0c: slbcomb -----------------------------------------------
__global__ void k_slbc(const float* __restrict__ slb) {
    int gid = blockIdx.x * blockDim.x + threadIdx.x;
    if (gid >= 2 * NP * SL_COLS) return;
    int br = gid / (NP * SL_COLS);
    int rem = gid - br * NP * SL_COLS;
    int i = rem / SL_COLS, c = rem % SL_COLS;
    float v = 0.f;
    if (i < N_) {
        float sc = __expf(-(br ? g_nf2[i] : g_nf1[i]));
        if (c < 32)       v = slb[i * 32 + c] * sc;
        else if (c == 32) v = sc;
    }
    g_slbc[br][i][c] = __uint_as_float(tf(v));
}

// ---------------- phase A ----------------------------------------------------
// smem map (bytes)
#define SA_X   0
#define SA_ST  34816
#define SA_FC  69632
#define SA_E   139264
#define SA_NSS 206848
#define SA_SIZE 207360

__global__ __launch_bounds__(256, 1)
void k_phaseA(const float* __restrict__ x, const float* __restrict__ star) {
    extern __shared__ char smem[];
    float* Xs  = (float*)(smem + SA_X);
    float* STs = (float*)(smem + SA_ST);
    float* FCs = (float*)(smem + SA_FC);
    float* Es  = (float*)(smem + SA_E);
    float* nss = (float*)(smem + SA_NSS);
    const uint32_t Xb  = su32(Xs), STb = su32(STs), FCb = su32(FCs);

    const int tid = threadIdx.x;
    const int w = tid >> 5, lane = tid & 31;
    const int r0 = lane >> 2, c0l = lane & 3;
    const int jw = w * 16;
    const int j0 = blockIdx.x * 128;
    const int slab = blockIdx.y;
    const int ch0 = slab * CPS_A;
    const int ch1 = min(ch0 + CPS_A, NCH_TOT);

    // X tile (once)
    for (int idx = tid; idx < 128 * 16; idx += 256) {
        int r = idx >> 4, g = idx & 15;
        CPA16(Xb + (r * XS_STR * 4) + g * 16, (const char*)x + (long)(j0 + r) * 256 + g * 16);
    }
    CP_COMMIT();
    const float nx0 = g_nx[j0 + jw + r0];
    const float nx1 = g_nx[j0 + jw + r0 + 8];

    float acc[17][4];
#pragma unroll
    for (int n = 0; n < 17; n++)
#pragma unroll
        for (int q = 0; q < 4; q++) acc[n][q] = 0.f;

    for (int ch = ch0; ch < ch1; ch++) {
        const int i0 = ch * 128;
        __syncthreads();   // previous consumers done
        for (int idx = tid; idx < 128 * 16; idx += 256) {
            int r = idx >> 4, g = idx & 15;
            long gi = min(i0 + r, N_ - 1);
            CPA16(STb + (r * XS_STR * 4) + g * 16, (const char*)star + gi * 256 + g * 16);
        }
        for (int idx = tid; idx < 128 * 34; idx += 256) {
            int r = idx / 34, g = idx % 34;
            CPA16(FCb + (r * FC_COLS * 4) + g * 16,
                  (const char*)g_fcomb + (long)(i0 + r) * (FC_COLS * 4) + g * 16);
        }
        if (tid < 128) { int gi = i0 + tid; nss[tid] = (gi < N_) ? g_ns[gi] : 1e30f; }
        CP_COMMIT(); CP_WAIT0();
        __syncthreads();

        // A frags for all 8 k-steps
        uint32_t aF[8][4];
#pragma unroll
        for (int ks = 0; ks < 8; ks++) {
            aF[ks][0] = tf(Xs[(jw + r0) * XS_STR + ks * 8 + c0l]);
            aF[ks][1] = tf(Xs[(jw + r0 + 8) * XS_STR + ks * 8 + c0l]);
            aF[ks][2] = tf(Xs[(jw + r0) * XS_STR + ks * 8 + c0l + 4]);
            aF[ks][3] = tf(Xs[(jw + r0 + 8) * XS_STR + ks * 8 + c0l + 4]);
        }

#pragma unroll
        for (int half = 0; half < 2; half++) {
            float cf[8][4];
#pragma unroll
            for (int n = 0; n < 8; n++)
#pragma unroll
                for (int q = 0; q < 4; q++) cf[n][q] = 0.f;
#pragma unroll
            for (int n8 = 0; n8 < 8; n8++) {
                int nt = half * 8 + n8;
#pragma unroll
                for (int ks = 0; ks < 8; ks++) {
                    uint32_t b[2];
                    b[0] = tf(STs[(nt * 8 + r0) * XS_STR + ks * 8 + c0l]);
                    b[1] = tf(STs[(nt * 8 + r0) * XS_STR + ks * 8 + c0l + 4]);
                    mma8(cf[n8], aF[ks], b);
                }
            }
            // exp + match + store E
#pragma unroll
            for (int n8 = 0; n8 < 8; n8++) {
                int nt = half * 8 + n8;
                int ic0 = nt * 8 + 2 * c0l, ic1 = ic0 + 1;
                float ns0 = nss[ic0], ns1 = nss[ic1];
                float t00 = 2.f * cf[n8][0] - nx0, t01 = 2.f * cf[n8][1] - nx0;
                float t10 = 2.f * cf[n8][2] - nx1, t11 = 2.f * cf[n8][3] - nx1;
                if (t00 >= ns0) atomicMin(&g_match[j0 + jw + r0], i0 + ic0);
                if (t01 >= ns1) atomicMin(&g_match[j0 + jw + r0], i0 + ic1);
                if (t10 >= ns0) atomicMin(&g_match[j0 + jw + r0 + 8], i0 + ic0);
                if (t11 >= ns1) atomicMin(&g_match[j0 + jw + r0 + 8], i0 + ic1);
                uint2 v0 = make_uint2(tf(__expf(t00)), tf(__expf(t01)));
                uint2 v1 = make_uint2(tf(__expf(t10)), tf(__expf(t11)));
                *(uint2*)&Es[(jw + r0) * E_STR + ic0] = v0;
                *(uint2*)&Es[(jw + r0 + 8) * E_STR + ic0] = v1;
            }
        }
        __syncwarp();

        // MMA2: acc[j][0:136] += E[j][i] . fcomb[i][0:136]
        const uint32_t* Eu  = (const uint32_t*)Es;
        const uint32_t* FCu = (const uint32_t*)FCs;
#pragma unroll
        for (int kc = 0; kc < 16; kc++) {
            uint32_t a2[4];
            a2[0] = Eu[(jw + r0) * E_STR + kc * 8 + c0l];
            a2[1] = Eu[(jw + r0 + 8) * E_STR + kc * 8 + c0l];
            a2[2] = Eu[(jw + r0) * E_STR + kc * 8 + c0l + 4];
            a2[3] = Eu[(jw + r0 + 8) * E_STR + kc * 8 + c0l + 4];
#pragma unroll
            for (int nt = 0; nt < 17; nt++) {
                uint32_t b[2];
                b[0] = FCu[(kc * 8 + c0l) * FC_COLS + nt * 8 + r0];
                b[1] = FCu[(kc * 8 + c0l + 4) * FC_COLS + nt * 8 + r0];
                mma8(acc[nt], a2, b);
            }
        }
    }

    // writeback
    const int jr0 = j0 + jw + r0, jr1 = jr0 + 8;
#pragma unroll
    for (int nt = 0; nt < 17; nt++) {
        int n = nt * 8 + 2 * c0l;
        if (n < 64) {
            *(float2*)&g_acc1_part[slab][jr0][n] = make_float2(acc[nt][0], acc[nt][1]);
            *(float2*)&g_acc1_part[slab][jr1][n] = make_float2(acc[nt][2], acc[nt][3]);
        } else if (n < 128) {
            *(float2*)&g_acc2_part[slab][jr0][n - 64] = make_float2(acc[nt][0], acc[nt][1]);
            *(float2*)&g_acc2_part[slab][jr1][n - 64] = make_float2(acc[nt][2], acc[nt][3]);
        } else if (n == 128) {
            g_esum_part[slab][jr0] = acc[nt][0];
            g_esum_part[slab][jr1] = acc[nt][2];
        }
    }
}

// ---------------- K2: middle — xt, y = xt@W+b, argmin label ------------------
__global__ __launch_bounds__(128)
void k_mid(const float* __restrict__ f1, const float* __restrict__ f2,
           const float* __restrict__ W1, const float* __restrict__ b1,
           const float* __restrict__ W2, const float* __restrict__ b2,
           const float* __restrict__ u1, const float* __restrict__ u2) {
    int j = blockIdx.x;
    int t = threadIdx.x;

    __shared__ float xts[D_];
    __shared__ float ys[DY_];
    __shared__ float esum_s;
    __shared__ float ny_s;
    __shared__ float redv[128];
    __shared__ int   redi[128];

    int  mi = g_match[j];
    bool hm = (mi != 0x7fffffff);
    if (t == 0) {
        float s = 0.f;
        for (int k = 0; k < NSLAB_A; k++) s += g_esum_part[k][j];
        esum_s = s;
    }
    __syncthreads();

    for (int br = 0; br < 2; br++) {
        const float* f  = br ? f2 : f1;
        const float* W  = br ? W2 : W1;
        const float* bb = br ? b2 : b1;
        const float* u  = br ? u2 : u1;

        if (t < D_) {
            float a = 0.f;
            if (br) { for (int k = 0; k < NSLAB_A; k++) a += g_acc2_part[k][j][t]; }
            else    { for (int k = 0; k < NSLAB_A; k++) a += g_acc1_part[k][j][t]; }
            float v = hm ? f[mi * D_ + t] : a / esum_s;
            xts[t] = v;
            if (br) g_xt2[j][t] = v; else g_xt1[j][t] = v;
        }
        __syncthreads();
        if (t == 0) {
            float s = 0.f;
            for (int d = 0; d < D_; d++) s += xts[d] * xts[d];
            if (br) g_nxt2[j] = s; else g_nxt1[j] = s;
        }
        if (t < DY_) {
            float a = bb[t];
            for (int d = 0; d < D_; d++) a += xts[d] * W[d * DY_ + t];
            ys[t] = a;
        }
        __syncthreads();
        if (t == 0) {
            float s = 0.f;
            for (int dy = 0; dy < DY_; dy++) s += ys[dy] * ys[dy];
            ny_s = s;
        }
        __syncthreads();

        float v = FLT_MAX;
        int   vi = 0x7fffffff;
        if (t < L_) {
            float nu = 0.f, dot = 0.f;
            for (int dy = 0; dy < DY_; dy++) {
                float uu = u[t * DY_ + dy];
                nu += uu * uu;
                dot += uu * ys[dy];
            }
            v = fmaxf(ny_s + nu - 2.f * dot, 0.f);
            vi = t;
        }
        redv[t] = v; redi[t] = vi;
        __syncthreads();
        for (int off = 64; off > 0; off >>= 1) {
            if (t < off) {
                float v2 = redv[t + off]; int i2 = redi[t + off];
                if (v2 < redv[t] || (v2 == redv[t] && i2 < redi[t])) {
                    redv[t] = v2; redi[t] = i2;
                }
            }
            __syncthreads();
        }
        if (t == 0) { if (br) g_yidx2[j] = redi[0]; else g_yidx1[j] = redi[0]; }
        __syncthreads();
    }
}

// ---------------- phase C ----------------------------------------------------
#define SC_XT   0
#define SC_F    34816
#define SC_SL   69632
#define SC_E    90112
#define SC_MT   157696
#define SC_LIDX 209408
#define SC_YJS  209920
#define SC_SIZE 210432

__global__ __launch_bounds__(256, 1)
void k_phaseC(const float* __restrict__ f1, const float* __restrict__ f2,
              const float* __restrict__ ld1, const float* __restrict__ ld2,
              const int* __restrict__ li1, const int* __restrict__ li2) {
    extern __shared__ char smem[];
    float* XTs = (float*)(smem + SC_XT);
    float* Fs  = (float*)(smem + SC_F);
    float* SLs = (float*)(smem + SC_SL);
    float* Es  = (float*)(smem + SC_E);
    float* mt  = (float*)(smem + SC_MT);      // [128][101]
    int*   lidx = (int*)(smem + SC_LIDX);
    int*   yjs  = (int*)(smem + SC_YJS);
    const uint32_t XTb = su32(XTs), Fb = su32(Fs), SLb = su32(SLs);

    const int tid = threadIdx.x;
    const int w = tid >> 5, lane = tid & 31;
    const int r0 = lane >> 2, c0l = lane & 3;
    const int jw = w * 16;
    const int j0 = blockIdx.x * 128;
    const int slab = blockIdx.y;
    const int br = blockIdx.z;
    const int ch0 = slab * CPS_C;
    const int ch1 = min(ch0 + CPS_C, NCH_TOT);

    const float* f  = br ? f2 : f1;
    const float* ld = br ? ld2 : ld1;
    const int*   li = br ? li2 : li1;
    const float (*xt)[D_] = br ? g_xt2 : g_xt1;
    const float* nxt = br ? g_nxt2 : g_nxt1;
    const int*   yix = br ? g_yidx2 : g_yidx1;
    float (*nump)[B_][DY_] = br ? g_num2_part : g_num1_part;
    float (*denp)[B_]      = br ? g_den2_part : g_den1_part;

    // XT tile (once)
    for (int idx = tid; idx < 128 * 16; idx += 256) {
        int r = idx >> 4, g = idx & 15;
        CPA16(XTb + (r * XS_STR * 4) + g * 16, (const char*)&xt[j0 + r][0] + g * 16);
    }
    CP_COMMIT();
    if (tid < 128) yjs[tid] = yix[j0 + tid];
    __syncthreads();
    // mt[j][l] = exp(-eta * ld[l][yj])
    for (int idx = tid; idx < 128 * L_; idx += 256) {
        int j = idx / L_, l = idx - j * L_;
        mt[j * 101 + l] = __expf(-ETA_ * ld[l * L_ + yjs[j]]);
    }
    const float nxt0 = nxt[j0 + jw + r0];
    const float nxt1 = nxt[j0 + jw + r0 + 8];

    float acc[5][4];
#pragma unroll
    for (int n = 0; n < 5; n++)
#pragma unroll
        for (int q = 0; q < 4; q++) acc[n][q] = 0.f;

    for (int ch = ch0; ch < ch1; ch++) {
        const int i0 = ch * 128;
        __syncthreads();
        for (int idx = tid; idx < 128 * 16; idx += 256) {
            int r = idx >> 4, g = idx & 15;
            long gi = min(i0 + r, N_ - 1);
            CPA16(Fb + (r * XS_STR * 4) + g * 16, (const char*)f + gi * 256 + g * 16);
        }
        for (int idx = tid; idx < 128 * 10; idx += 256) {
            int r = idx / 10, g = idx % 10;
            CPA16(SLb + (r * SL_COLS * 4) + g * 16,
                  (const char*)&g_slbc[br][0][0] + (long)(i0 + r) * (SL_COLS * 4) + g * 16);
        }
        if (tid < 128) lidx[tid] = li[min(i0 + tid, N_ - 1)];
        CP_COMMIT(); CP_WAIT0();
        __syncthreads();

        uint32_t aF[8][4];
#pragma unroll
        for (int ks = 0; ks < 8; ks++) {
            aF[ks][0] = tf(XTs[(jw + r0) * XS_STR + ks * 8 + c0l]);
            aF[ks][1] = tf(XTs[(jw + r0 + 8) * XS_STR + ks * 8 + c0l]);
            aF[ks][2] = tf(XTs[(jw + r0) * XS_STR + ks * 8 + c0l + 4]);
            aF[ks][3] = tf(XTs[(jw + r0 + 8) * XS_STR + ks * 8 + c0l + 4]);
        }

#pragma unroll
        for (int half = 0; half < 2; half++) {
            float cf[8][4];
#pragma unroll
            for (int n = 0; n < 8; n++)
#pragma unroll
                for (int q = 0; q < 4; q++) cf[n][q] = 0.f;
#pragma unroll
            for (int n8 = 0; n8 < 8; n8++) {
                int nt = half * 8 + n8;
#pragma unroll
                for (int ks = 0; ks < 8; ks++) {
                    uint32_t b[2];
                    b[0] = tf(Fs[(nt * 8 + r0) * XS_STR + ks * 8 + c0l]);
                    b[1] = tf(Fs[(nt * 8 + r0) * XS_STR + ks * 8 + c0l + 4]);
                    mma8(cf[n8], aF[ks], b);
                }
            }
#pragma unroll
            for (int n8 = 0; n8 < 8; n8++) {
                int nt = half * 8 + n8;
                int ic0 = nt * 8 + 2 * c0l, ic1 = ic0 + 1;
                int l0 = lidx[ic0], l1 = lidx[ic1];
                float m00 = mt[(jw + r0) * 101 + l0], m01 = mt[(jw + r0) * 101 + l1];
                float m10 = mt[(jw + r0 + 8) * 101 + l0], m11 = mt[(jw + r0 + 8) * 101 + l1];
                float e00 = __expf(2.f * cf[n8][0] - nxt0) * m00;
                float e01 = __expf(2.f * cf[n8][1] - nxt0) * m01;
                float e10 = __expf(2.f * cf[n8][2] - nxt1) * m10;
                float e11 = __expf(2.f * cf[n8][3] - nxt1) * m11;
                uint2 v0 = make_uint2(tf(e00), tf(e01));
                uint2 v1 = make_uint2(tf(e10), tf(e11));
                *(uint2*)&Es[(jw + r0) * E_STR + ic0] = v0;
                *(uint2*)&Es[(jw + r0 + 8) * E_STR + ic0] = v1;
            }
        }
        __syncwarp();

        const uint32_t* Eu  = (const uint32_t*)Es;
        const uint32_t* SLu = (const uint32_t*)SLs;
#pragma unroll
        for (int kc = 0; kc < 16; kc++) {
            uint32_t a2[4];
            a2[0] = Eu[(jw + r0) * E_STR + kc * 8 + c0l];
            a2[1] = Eu[(jw + r0 + 8) * E_STR + kc * 8 + c0l];
            a2[2] = Eu[(jw + r0) * E_STR + kc * 8 + c0l + 4];
            a2[3] = Eu[(jw + r0 + 8) * E_STR + kc * 8 + c0l + 4];
#pragma unroll
            for (int nt = 0; nt < 5; nt++) {
                uint32_t b[2];
                b[0] = SLu[(kc * 8 + c0l) * SL_COLS + nt * 8 + r0];
                b[1] = SLu[(kc * 8 + c0l + 4) * SL_COLS + nt * 8 + r0];
                mma8(acc[nt], a2, b);
            }
        }
    }

    const int jr0 = j0 + jw + r0, jr1 = jr0 + 8;
#pragma unroll
    for (int nt = 0; nt < 5; nt++) {
        int n = nt * 8 + 2 * c0l;
        if (n < 32) {
            *(float2*)&nump[slab][jr0][n] = make_float2(acc[nt][0], acc[nt][1]);
            *(float2*)&nump[slab][jr1][n] = make_float2(acc[nt][2], acc[nt][3]);
        } else if (n == 32) {
            denp[slab][jr0] = acc[nt][0];
            denp[slab][jr1] = acc[nt][2];
        }
    }
}

// ---------------- K4: reduce partials ----------------------------------------
__global__ void k_out(float* __restrict__ out) {
    int gid = blockIdx.x * blockDim.x + threadIdx.x;
    if (gid >= B_ * DY_) return;
    int j = gid >> 5, dy = gid & 31;
    float n1 = 0.f, d1 = 0.f, n2 = 0.f, d2 = 0.f;
    for (int s = 0; s < NSLAB_C; s++) {
        n1 += g_num1_part[s][j][dy];
        d1 += g_den1_part[s][j];
        n2 += g_num2_part[s][j][dy];
        d2 += g_den2_part[s][j];
    }
    out[gid] = 0.5f * (n1 / d1 + n2 / d2);
}

// ---------------- launch -----------------------------------------------------
extern "C" void kernel_launch(void* const* d_in, const int* in_sizes, int n_in,
                              void* d_out, int out_size) {
    const float* x    = (const float*)d_in[0];
    const float* star = (const float*)d_in[1];
    const float* slb  = (const float*)d_in[2];
    const float* f1   = (const float*)d_in[3];
    const float* f2   = (const float*)d_in[4];
    const float* u1   = (const float*)d_in[5];
    const float* u2   = (const float*)d_in[6];
    const float* ld1  = (const float*)d_in[7];
    const float* ld2  = (const float*)d_in[8];
    const float* W1   = (const float*)d_in[9];
    const float* b1   = (const float*)d_in[10];
    const float* W2   = (const float*)d_in[11];
    const float* b2   = (const float*)d_in[12];
    const int*   li1  = (const int*)d_in[13];
    const int*   li2  = (const int*)d_in[14];
    float* out = (float*)d_out;

    cudaFuncSetAttribute(k_phaseA, cudaFuncAttributeMaxDynamicSharedMemorySize, SA_SIZE);
    cudaFuncSetAttribute(k_phaseC, cudaFuncAttributeMaxDynamicSharedMemorySize, SC_SIZE);

    k_prep<<<(B_ + 3 * N_ + 255) / 256, 256>>>(x, star, f1, f2);
    k_fc<<<(NP * FC_COLS + 255) / 256, 256>>>(f1, f2);
    k_slbc<<<(2 * NP * SL_COLS + 255) / 256, 256>>>(slb);
    k_phaseA<<<dim3(16, NSLAB_A), 256, SA_SIZE>>>(x, star);
    k_mid<<<B_, 128>>>(f1, f2, W1, b1, W2, b2, u1, u2);
    k_phaseC<<<dim3(16, NSLAB_C, 2), 256, SC_SIZE>>>(f1, f2, ld1, ld2, li1, li2);
    k_out<<<(B_ * DY_ + 255) / 256, 256>>>(out);
}

// round 8
// speedup vs baseline: 2.7945x; 1.4630x over previous
#include <cuda_runtime.h>
#include <cstdint>
#include <cfloat>

// Problem constants (fixed shapes for MergeNN_38903813767173)
#define B_ 2048
#define N_ 20000
#define D_ 64
#define DY_ 32
#define L_ 100
#define ETA_ 0.01f

#define NP 20224            // 158*128 padded i-extent
#define NCH_TOT 158
#define NSLAB_A 9
#define CPS_A 18            // 9*18 = 162 >= 158 ; grid 16*9 = 144 <= 148 (one wave)
#define NSLAB_C 4
#define CPS_C 40            // 4*40 = 160 >= 158 ; grid 16*4*2 = 128 <= 148

#define XS_STR 68           // X/star/f/xt smem row stride (words): 68%32=4 -> frag lds conflict-free
#define E_STR 132           // E smem row stride: 132%32=4 -> conflict-free
#define FCS 132             // fcombT smem row stride (words)
#define FC_ROWS 136         // 64+64+1+7 pad
#define SLS 132
#define SL_ROWS 40          // 32+1+7 pad

// ---------------- helpers ----------------------------------------------------
__device__ __forceinline__ uint32_t su32(const void* p) {
    return (uint32_t)__cvta_generic_to_shared(p);
}
#define CPA16(dst, src) \
    asm volatile("cp.async.ca.shared.global [%0], [%1], 16;" :: "r"(dst), "l"(src))
#define CP_COMMIT() asm volatile("cp.async.commit_group;")
#define CP_WAIT0()  asm volatile("cp.async.wait_group 0;" ::: "memory")
#define CP_WAIT1()  asm volatile("cp.async.wait_group 1;" ::: "memory")
#define CP_WAIT2()  asm volatile("cp.async.wait_group 2;" ::: "memory")

__device__ __forceinline__ uint32_t tf(float x) {
    uint32_t r; asm("cvt.rna.tf32.f32 %0, %1;" : "=r"(r) : "f"(x)); return r;
}
__device__ __forceinline__ void mma8(float c[4], const uint32_t a[4], const uint32_t b[2]) {
    asm volatile("mma.sync.aligned.m16n8k8.row.col.f32.tf32.tf32.f32 "
                 "{%0,%1,%2,%3}, {%4,%5,%6,%7}, {%8,%9}, {%0,%1,%2,%3};"
                 : "+f"(c[0]), "+f"(c[1]), "+f"(c[2]), "+f"(c[3])
                 : "r"(a[0]), "r"(a[1]), "r"(a[2]), "r"(a[3]), "r"(b[0]), "r"(b[1]));
}

// ---------------- scratch ----------------------------------------------------
__device__ float g_nx[B_];
__device__ float g_ns[N_];
__device__ float g_nf1[N_];
__device__ float g_nf2[N_];
__device__ int   g_match[B_];

__device__ float g_fcombT[FC_ROWS][NP];   // tf32: rows 0-63 e^{-ns}f1^T, 64-127 e^{-ns}f2^T, 128 e^{-ns}, 129-135 zero
__device__ float g_slbcT[2][SL_ROWS][NP]; // tf32: rows 0-31 e^{-nf}slb^T, 32 e^{-nf}, 33-39 zero

__device__ float g_esum_part[NSLAB_A][B_];
__device__ float g_acc1_part[NSLAB_A][B_][D_];
__device__ float g_acc2_part[NSLAB_A][B_][D_];

__device__ float g_xt1[B_][D_];
__device__ float g_xt2[B_][D_];
__device__ float g_nxt1[B_];
__device__ float g_nxt2[B_];
__device__ int   g_yidx1[B_];
__device__ int   g_yidx2[B_];

__device__ float g_num1_part[NSLAB_C][B_][DY_];
__device__ float g_num2_part[NSLAB_C][B_][DY_];
__device__ float g_den1_part[NSLAB_C][B_];
__device__ float g_den2_part[NSLAB_C][B_];

// ---------------- K0: norms + match init -------------------------------------
__global__ void k_prep(const float* __restrict__ x, const float* __restrict__ star,
                       const float* __restrict__ f1, const float* __restrict__ f2) {
    int gid = blockIdx.x * blockDim.x + threadIdx.x;
    const float* src;
    float* dst;
    if (gid < B_) {
        g_match[gid] = 0x7fffffff;
        src = x + gid * D_;        dst = &g_nx[gid];
    } else if (gid < B_ + N_) {
        int r = gid - B_;          src = star + r * D_; dst = &g_ns[r];
    } else if (gid < B_ + 2 * N_) {
        int r = gid - B_ - N_;     src = f1 + r * D_;   dst = &g_nf1[r];
    } else if (gid < B_ + 3 * N_) {
        int r = gid - B_ - 2 * N_; src = f2 + r * D_;   dst = &g_nf2[r];
    } else return;
    float s = 0.f;
    const float4* p = reinterpret_cast<const float4*>(src);
#pragma unroll
    for (int i = 0; i < 16; i++) {
        float4 v = p[i];
        s += v.x * v.x + v.y * v.y + v.z * v.z + v.w * v.w;
    }
    *dst = s;
}

// ---------------- K0b: g_fcombT (transposed, tf32) ---------------------------
__global__ void k_tfT(const float* __restrict__ f1, const float* __restrict__ f2) {
    __shared__ float ts[32][33];
    int tx = threadIdx.x, ty = threadIdx.y;
    int i0 = blockIdx.x * 32;
    int by = blockIdx.y;
    int i = i0 + tx;
    float sc = (i < N_) ? __expf(-g_ns[i]) : 0.f;
    if (by == 4) {
        for (int r = 128 + ty; r < FC_ROWS; r += 8)
            g_fcombT[r][i] = (r == 128) ? __uint_as_float(tf(sc)) : 0.f;
        return;
    }
    const float* src = (by < 2) ? f1 : f2;
    int d0 = (by & 1) * 32;
    int rowbase = by * 32;
#pragma unroll
    for (int q = 0; q < 4; q++) {
        int r = ty + q * 8;
        ts[r][tx] = src[(long)min(i0 + r, N_ - 1) * 64 + d0 + tx];
    }
    __syncthreads();
#pragma unroll
    for (int q = 0; q < 4; q++) {
        int d = ty + q * 8;
        g_fcombT[rowbase + d][i] = __uint_as_float(tf(ts[tx][d] * sc));
    }
}

// ---------------- K0c: g_slbcT (transposed, tf32) ----------------------------
__global__ void k_tsT(const float* __restrict__ slb) {
    __shared__ float ts[32][33];
    int tx = threadIdx.x, ty = threadIdx.y;
    int i0 = blockIdx.x * 32;
    int br = blockIdx.z;
    int i = i0 + tx;
    float sc = (i < N_) ? __expf(-(br ? g_nf2[i] : g_nf1[i])) : 0.f;
#pragma unroll
    for (int q = 0; q < 4; q++) {
        int r = ty + q * 8;
        ts[r][tx] = slb[(long)min(i0 + r, N_ - 1) * 32 + tx];
    }
    __syncthreads();
#pragma unroll
    for (int q = 0; q < 4; q++) {
        int d = ty + q * 8;
        g_slbcT[br][d][i] = __uint_as_float(tf(ts[tx][d] * sc));
    }
    if (ty == 0) g_slbcT[br][32][i] = __uint_as_float(tf(sc));
    if (33 + ty < SL_ROWS) g_slbcT[br][33 + ty][i] = 0.f;
}

// ---------------- phase A ----------------------------------------------------
// smem (bytes): B0 34816 | B1 34816 | FC 71808 | E 67584 | NS 1024
#define SA_B0 0
#define SA_B1 34816
#define SA_FC 69632
#define SA_E  141440
#define SA_NS 209024
#define SA_SIZE 210048

__global__ __launch_bounds__(256, 1)
void k_phaseA(const float* __restrict__ x, const float* __restrict__ star) {
    extern __shared__ char smem[];
    float* buf0 = (float*)(smem + SA_B0);
    float* buf1 = (float*)(smem + SA_B1);
    float* FCs  = (float*)(smem + SA_FC);
    float* Es   = (float*)(smem + SA_E);
    float* nsb  = (float*)(smem + SA_NS);   // [2][128]
    const uint32_t bb0 = su32(buf0), bb1 = su32(buf1), FCb = su32(FCs);

    const int tid = threadIdx.x;
    const int w = tid >> 5, lane = tid & 31;
    const int r0 = lane >> 2, c0l = lane & 3;
    const int jw = w * 16;
    const int j0 = blockIdx.x * 128;
    const int slab = blockIdx.y;
    const int ch0 = slab * CPS_A;
    const int ch1 = min(ch0 + CPS_A, NCH_TOT);
    const int nc = ch1 - ch0;

    // prologue group P: X->buf0, ST(0)->buf1, FC(0), ns(0)
    const int i0p = ch0 * 128;
    for (int idx = tid; idx < 128 * 16; idx += 256) {
        int r = idx >> 4, g = idx & 15;
        CPA16(bb0 + r * (XS_STR * 4) + g * 16, (const char*)x + (long)(j0 + r) * 256 + g * 16);
    }
    for (int idx = tid; idx < 128 * 16; idx += 256) {
        int r = idx >> 4, g = idx & 15;
        long gi = min(i0p + r, N_ - 1);
        CPA16(bb1 + r * (XS_STR * 4) + g * 16, (const char*)star + gi * 256 + g * 16);
    }
    for (int idx = tid; idx < FC_ROWS * 32; idx += 256) {
        int r = idx >> 5, g = idx & 31;
        CPA16(FCb + r * (FCS * 4) + g * 16,
              (const char*)g_fcombT + ((long)r * NP + i0p) * 4 + g * 16);
    }
    if (tid < 128) { int gi = i0p + tid; nsb[tid] = (gi < N_) ? g_ns[gi] : 1e30f; }
    CP_COMMIT(); CP_WAIT0();
    __syncthreads();

    // persistent A-fragments from X tile (buf0 becomes ST ping buffer afterwards)
    uint32_t aF[8][4];
#pragma unroll
    for (int ks = 0; ks < 8; ks++) {
        aF[ks][0] = tf(buf0[(jw + r0) * XS_STR + ks * 8 + c0l]);
        aF[ks][1] = tf(buf0[(jw + r0 + 8) * XS_STR + ks * 8 + c0l]);
        aF[ks][2] = tf(buf0[(jw + r0) * XS_STR + ks * 8 + c0l + 4]);
        aF[ks][3] = tf(buf0[(jw + r0 + 8) * XS_STR + ks * 8 + c0l + 4]);
    }
    const float nx0 = g_nx[j0 + jw + r0];
    const float nx1 = g_nx[j0 + jw + r0 + 8];
    __syncthreads();   // all warps done reading X from buf0

    float acc[17][4];
#pragma unroll
    for (int n = 0; n < 17; n++)
#pragma unroll
        for (int q = 0; q < 4; q++) acc[n][q] = 0.f;

    for (int c = 0; c < nc; c++) {
        const int i0 = (ch0 + c) * 128;
        // a: prefetch ST(c+1) into buf[c&1] (ST(c) lives in buf[(c+1)&1])
        if (c + 1 < nc) {
            const uint32_t dstb = (c & 1) ? bb1 : bb0;
            const int i0n = i0 + 128;
            for (int idx = tid; idx < 128 * 16; idx += 256) {
                int r = idx >> 4, g = idx & 15;
                long gi = min(i0n + r, N_ - 1);
                CPA16(dstb + r * (XS_STR * 4) + g * 16, (const char*)star + gi * 256 + g * 16);
            }
            if (tid < 128) {
                int gi = i0n + tid;
                nsb[((c + 1) & 1) * 128 + tid] = (gi < N_) ? g_ns[gi] : 1e30f;
            }
            CP_COMMIT();
        }
        // b: ensure ST(c) ready
        if (c > 0) { if (c + 1 < nc) CP_WAIT2(); else CP_WAIT1(); }
        __syncthreads();

        const float* STs = (c & 1) ? buf0 : buf1;
        const float* nsc = nsb + (c & 1) * 128;

        // MMA1: S = X . star^T ; then E = exp(2S - nx) + match detect
#pragma unroll
        for (int half = 0; half < 2; half++) {
            float cf[8][4];
#pragma unroll
            for (int n = 0; n < 8; n++)
#pragma unroll
                for (int q = 0; q < 4; q++) cf[n][q] = 0.f;
#pragma unroll
            for (int n8 = 0; n8 < 8; n8++) {
                int nt = half * 8 + n8;
#pragma unroll
                for (int ks = 0; ks < 8; ks++) {
                    uint32_t b[2];
                    b[0] = tf(STs[(nt * 8 + r0) * XS_STR + ks * 8 + c0l]);
                    b[1] = tf(STs[(nt * 8 + r0) * XS_STR + ks * 8 + c0l + 4]);
                    mma8(cf[n8], aF[ks], b);
                }
            }
#pragma unroll
            for (int n8 = 0; n8 < 8; n8++) {
                int nt = half * 8 + n8;
                int ic0 = nt * 8 + 2 * c0l, ic1 = ic0 + 1;
                float ns0 = nsc[ic0], ns1 = nsc[ic1];
                float t00 = 2.f * cf[n8][0] - nx0, t01 = 2.f * cf[n8][1] - nx0;
                float t10 = 2.f * cf[n8][2] - nx1, t11 = 2.f * cf[n8][3] - nx1;
                if (t00 >= ns0) atomicMin(&g_match[j0 + jw + r0], i0 + ic0);
                if (t01 >= ns1) atomicMin(&g_match[j0 + jw + r0], i0 + ic1);
                if (t10 >= ns0) atomicMin(&g_match[j0 + jw + r0 + 8], i0 + ic0);
                if (t11 >= ns1) atomicMin(&g_match[j0 + jw + r0 + 8], i0 + ic1);
                uint2 v0 = make_uint2(tf(__expf(t00)), tf(__expf(t01)));
                uint2 v1 = make_uint2(tf(__expf(t10)), tf(__expf(t11)));
                *(uint2*)&Es[(jw + r0) * E_STR + ic0] = v0;
                *(uint2*)&Es[(jw + r0 + 8) * E_STR + ic0] = v1;
            }
        }
        __syncwarp();

        // d: ensure FC(c) ready
        if (c + 1 < nc) CP_WAIT1(); else CP_WAIT0();
        __syncthreads();

        // e: MMA2: acc += E . fcombT  (B conflict-free, stride 132)
        const uint32_t* Eu  = (const uint32_t*)Es;
        const uint32_t* FCu = (const uint32_t*)FCs;
#pragma unroll
        for (int kc = 0; kc < 16; kc++) {
            uint32_t a2[4];
            a2[0] = Eu[(jw + r0) * E_STR + kc * 8 + c0l];
            a2[1] = Eu[(jw + r0 + 8) * E_STR + kc * 8 + c0l];
            a2[2] = Eu[(jw + r0) * E_STR + kc * 8 + c0l + 4];
            a2[3] = Eu[(jw + r0 + 8) * E_STR + kc * 8 + c0l + 4];
#pragma unroll
            for (int nt = 0; nt < 17; nt++) {
                uint32_t b[2];
                b[0] = FCu[(nt * 8 + r0) * FCS + kc * 8 + c0l];
                b[1] = FCu[(nt * 8 + r0) * FCS + kc * 8 + c0l + 4];
                mma8(acc[nt], a2, b);
            }
        }
        // f: prefetch FC(c+1)
        if (c + 1 < nc) {
            __syncthreads();
            const int i0n = i0 + 128;
            for (int idx = tid; idx < FC_ROWS * 32; idx += 256) {
                int r = idx >> 5, g = idx & 31;
                CPA16(FCb + r * (FCS * 4) + g * 16,
                      (const char*)g_fcombT + ((long)r * NP + i0n) * 4 + g * 16);
            }
            CP_COMMIT();
        }
    }

    // writeback
    const int jr0 = j0 + jw + r0, jr1 = jr0 + 8;
#pragma unroll
    for (int nt = 0; nt < 17; nt++) {
        int n = nt * 8 + 2 * c0l;
        if (n < 64) {
            *(float2*)&g_acc1_part[slab][jr0][n] = make_float2(acc[nt][0], acc[nt][1]);
            *(float2*)&g_acc1_part[slab][jr1][n] = make_float2(acc[nt][2], acc[nt][3]);
        } else if (n < 128) {
            *(float2*)&g_acc2_part[slab][jr0][n - 64] = make_float2(acc[nt][0], acc[nt][1]);
            *(float2*)&g_acc2_part[slab][jr1][n - 64] = make_float2(acc[nt][2], acc[nt][3]);
        } else if (n == 128) {
            g_esum_part[slab][jr0] = acc[nt][0];
            g_esum_part[slab][jr1] = acc[nt][2];
        }
    }
}

// ---------------- K2: middle — xt, y = xt@W+b, argmin label ------------------
__global__ __launch_bounds__(128)
void k_mid(const float* __restrict__ f1, const float* __restrict__ f2,
           const float* __restrict__ W1, const float* __restrict__ b1,
           const float* __restrict__ W2, const float* __restrict__ b2,
           const float* __restrict__ u1, const float* __restrict__ u2) {
    int j = blockIdx.x;
    int t = threadIdx.x;

    __shared__ float xts[D_];
    __shared__ float ys[DY_];
    __shared__ float esum_s;
    __shared__ float ny_s;
    __shared__ float redv[128];
    __shared__ int   redi[128];

    int  mi = g_match[j];
    bool hm = (mi != 0x7fffffff);
    if (t == 0) {
        float s = 0.f;
        for (int k = 0; k < NSLAB_A; k++) s += g_esum_part[k][j];
        esum_s = s;
    }
    __syncthreads();

    for (int br = 0; br < 2; br++) {
        const float* f  = br ? f2 : f1;
        const float* W  = br ? W2 : W1;
        const float* bb = br ? b2 : b1;
        const float* u  = br ? u2 : u1;

        if (t < D_) {
            float a = 0.f;
            if (br) { for (int k = 0; k < NSLAB_A; k++) a += g_acc2_part[k][j][t]; }
            else    { for (int k = 0; k < NSLAB_A; k++) a += g_acc1_part[k][j][t]; }
            float v = hm ? f[mi * D_ + t] : a / esum_s;
            xts[t] = v;
            if (br) g_xt2[j][t] = v; else g_xt1[j][t] = v;
        }
        __syncthreads();
        if (t == 0) {
            float s = 0.f;
            for (int d = 0; d < D_; d++) s += xts[d] * xts[d];
            if (br) g_nxt2[j] = s; else g_nxt1[j] = s;
        }
        if (t < DY_) {
            float a = bb[t];
            for (int d = 0; d < D_; d++) a += xts[d] * W[d * DY_ + t];
            ys[t] = a;
        }
        __syncthreads();
        if (t == 0) {
            float s = 0.f;
            for (int dy = 0; dy < DY_; dy++) s += ys[dy] * ys[dy];
            ny_s = s;
        }
        __syncthreads();

        float v = FLT_MAX;
        int   vi = 0x7fffffff;
        if (t < L_) {
            float nu = 0.f, dot = 0.f;
            for (int dy = 0; dy < DY_; dy++) {
                float uu = u[t * DY_ + dy];
                nu += uu * uu;
                dot += uu * ys[dy];
            }
            v = fmaxf(ny_s + nu - 2.f * dot, 0.f);
            vi = t;
        }
        redv[t] = v; redi[t] = vi;
        __syncthreads();
        for (int off = 64; off > 0; off >>= 1) {
            if (t < off) {
                float v2 = redv[t + off]; int i2 = redi[t + off];
                if (v2 < redv[t] || (v2 == redv[t] && i2 < redi[t])) {
                    redv[t] = v2; redi[t] = i2;
                }
            }
            __syncthreads();
        }
        if (t == 0) { if (br) g_yidx2[j] = redi[0]; else g_yidx1[j] = redi[0]; }
        __syncthreads();
    }
}

// ---------------- phase C ----------------------------------------------------
// smem (bytes): B0 34816 | B1 34816 | SL 21120 | E 67584 | MT 51712 | LI 1024 | YJ 512
#define SC_B0 0
#define SC_B1 34816
#define SC_SL 69632
#define SC_E  90752
#define SC_MT 158336
#define SC_LI 210048
#define SC_YJ 211072
#define SC_SIZE 211584

__global__ __launch_bounds__(256, 1)
void k_phaseC(const float* __restrict__ f1, const float* __restrict__ f2,
              const float* __restrict__ ld1, const float* __restrict__ ld2,
              const int* __restrict__ li1, const int* __restrict__ li2) {
    extern __shared__ char smem[];
    float* buf0 = (float*)(smem + SC_B0);
    float* buf1 = (float*)(smem + SC_B1);
    float* SLs  = (float*)(smem + SC_SL);
    float* Es   = (float*)(smem + SC_E);
    float* mt   = (float*)(smem + SC_MT);   // [128][101]
    int*   lib  = (int*)(smem + SC_LI);     // [2][128]
    int*   yjs  = (int*)(smem + SC_YJ);
    const uint32_t bb0 = su32(buf0), bb1 = su32(buf1), SLb = su32(SLs);

    const int tid = threadIdx.x;
    const int w = tid >> 5, lane = tid & 31;
    const int r0 = lane >> 2, c0l = lane & 3;
    const int jw = w * 16;
    const int j0 = blockIdx.x * 128;
    const int slab = blockIdx.y;
    const int br = blockIdx.z;
    const int ch0 = slab * CPS_C;
    const int ch1 = min(ch0 + CPS_C, NCH_TOT);
    const int nc = ch1 - ch0;

    const float* f  = br ? f2 : f1;
    const float* ld = br ? ld2 : ld1;
    const int*   li = br ? li2 : li1;
    const float (*xt)[D_] = br ? g_xt2 : g_xt1;
    const float* nxt = br ? g_nxt2 : g_nxt1;
    const int*   yix = br ? g_yidx2 : g_yidx1;
    float (*nump)[B_][DY_] = br ? g_num2_part : g_num1_part;
    float (*denp)[B_]      = br ? g_den2_part : g_den1_part;

    // prologue: XT->buf0, F(0)->buf1, SL(0), lidx(0), yjs
    const int i0p = ch0 * 128;
    for (int idx = tid; idx < 128 * 16; idx += 256) {
        int r = idx >> 4, g = idx & 15;
        CPA16(bb0 + r * (XS_STR * 4) + g * 16, (const char*)&xt[j0 + r][0] + g * 16);
    }
    for (int idx = tid; idx < 128 * 16; idx += 256) {
        int r = idx >> 4, g = idx & 15;
        long gi = min(i0p + r, N_ - 1);
        CPA16(bb1 + r * (XS_STR * 4) + g * 16, (const char*)f + gi * 256 + g * 16);
    }
    for (int idx = tid; idx < SL_ROWS * 32; idx += 256) {
        int r = idx >> 5, g = idx & 31;
        CPA16(SLb + r * (SLS * 4) + g * 16,
              (const char*)&g_slbcT[br][0][0] + ((long)r * NP + i0p) * 4 + g * 16);
    }
    if (tid < 128) {
        lib[tid] = li[min(i0p + tid, N_ - 1)];
        yjs[tid] = yix[j0 + tid];
    }
    CP_COMMIT(); CP_WAIT0();
    __syncthreads();

    uint32_t aF[8][4];
#pragma unroll
    for (int ks = 0; ks < 8; ks++) {
        aF[ks][0] = tf(buf0[(jw + r0) * XS_STR + ks * 8 + c0l]);
        aF[ks][1] = tf(buf0[(jw + r0 + 8) * XS_STR + ks * 8 + c0l]);
        aF[ks][2] = tf(buf0[(jw + r0) * XS_STR + ks * 8 + c0l + 4]);
        aF[ks][3] = tf(buf0[(jw + r0 + 8) * XS_STR + ks * 8 + c0l + 4]);
    }
    const float nxt0 = nxt[j0 + jw + r0];
    const float nxt1 = nxt[j0 + jw + r0 + 8];
    // mt[j][l] = exp(-eta * ld[l][yidx_j])
    for (int idx = tid; idx < 128 * L_; idx += 256) {
        int j = idx / L_, l = idx - j * L_;
        mt[j * 101 + l] = __expf(-ETA_ * ld[l * L_ + yjs[j]]);
    }
    __syncthreads();   // buf0(XT) consumed, mt ready

    float acc[5][4];
#pragma unroll
    for (int n = 0; n < 5; n++)
#pragma unroll
        for (int q = 0; q < 4; q++) acc[n][q] = 0.f;

    for (int c = 0; c < nc; c++) {
        const int i0 = (ch0 + c) * 128;
        if (c + 1 < nc) {
            const uint32_t dstb = (c & 1) ? bb1 : bb0;
            const int i0n = i0 + 128;
            for (int idx = tid; idx < 128 * 16; idx += 256) {
                int r = idx >> 4, g = idx & 15;
                long gi = min(i0n + r, N_ - 1);
                CPA16(dstb + r * (XS_STR * 4) + g * 16, (const char*)f + gi * 256 + g * 16);
            }
            if (tid < 128)
                lib[((c + 1) & 1) * 128 + tid] = li[min(i0n + tid, N_ - 1)];
            CP_COMMIT();
        }
        if (c > 0) { if (c + 1 < nc) CP_WAIT2(); else CP_WAIT1(); }
        __syncthreads();

        const float* Fs = (c & 1) ? buf0 : buf1;
        const int* lic = lib + (c & 1) * 128;

#pragma unroll
        for (int half = 0; half < 2; half++) {
            float cf[8][4];
#pragma unroll
            for (int n = 0; n < 8; n++)
#pragma unroll
                for (int q = 0; q < 4; q++) cf[n][q] = 0.f;
#pragma unroll
            for (int n8 = 0; n8 < 8; n8++) {
                int nt = half * 8 + n8;
#pragma unroll
                for (int ks = 0; ks < 8; ks++) {
                    uint32_t b[2];
                    b[0] = tf(Fs[(nt * 8 + r0) * XS_STR + ks * 8 + c0l]);
                    b[1] = tf(Fs[(nt * 8 + r0) * XS_STR + ks * 8 + c0l + 4]);
                    mma8(cf[n8], aF[ks], b);
                }
            }
#pragma unroll
            for (int n8 = 0; n8 < 8; n8++) {
                int nt = half * 8 + n8;
                int ic0 = nt * 8 + 2 * c0l, ic1 = ic0 + 1;
                int l0 = lic[ic0], l1 = lic[ic1];
                float m00 = mt[(jw + r0) * 101 + l0], m01 = mt[(jw + r0) * 101 + l1];
                float m10 = mt[(jw + r0 + 8) * 101 + l0], m11 = mt[(jw + r0 + 8) * 101 + l1];
                float e00 = __expf(2.f * cf[n8][0] - nxt0) * m00;
                float e01 = __expf(2.f * cf[n8][1] - nxt0) * m01;
                float e10 = __expf(2.f * cf[n8][2] - nxt1) * m10;
                float e11 = __expf(2.f * cf[n8][3] - nxt1) * m11;
                uint2 v0 = make_uint2(tf(e00), tf(e01));
                uint2 v1 = make_uint2(tf(e10), tf(e11));
                *(uint2*)&Es[(jw + r0) * E_STR + ic0] = v0;
                *(uint2*)&Es[(jw + r0 + 8) * E_STR + ic0] = v1;
            }
        }
        __syncwarp();

        if (c + 1 < nc) CP_WAIT1(); else CP_WAIT0();
        __syncthreads();

        const uint32_t* Eu  = (const uint32_t*)Es;
        const uint32_t* SLu = (const uint32_t*)SLs;
#pragma unroll
        for (int kc = 0; kc < 16; kc++) {
            uint32_t a2[4];
            a2[0] = Eu[(jw + r0) * E_STR + kc * 8 + c0l];
            a2[1] = Eu[(jw + r0 + 8) * E_STR + kc * 8 + c0l];
            a2[2] = Eu[(jw + r0) * E_STR + kc * 8 + c0l + 4];
            a2[3] = Eu[(jw + r0 + 8) * E_STR + kc * 8 + c0l + 4];
#pragma unroll
            for (int nt = 0; nt < 5; nt++) {
                uint32_t b[2];
                b[0] = SLu[(nt * 8 + r0) * SLS + kc * 8 + c0l];
                b[1] = SLu[(nt * 8 + r0) * SLS + kc * 8 + c0l + 4];
                mma8(acc[nt], a2, b);
            }
        }
        if (c + 1 < nc) {
            __syncthreads();
            const int i0n = i0 + 128;
            for (int idx = tid; idx < SL_ROWS * 32; idx += 256) {
                int r = idx >> 5, g = idx & 31;
                CPA16(SLb + r * (SLS * 4) + g * 16,
                      (const char*)&g_slbcT[br][0][0] + ((long)r * NP + i0n) * 4 + g * 16);
            }
            CP_COMMIT();
        }
    }

    const int jr0 = j0 + jw + r0, jr1 = jr0 + 8;
#pragma unroll
    for (int nt = 0; nt < 5; nt++) {
        int n = nt * 8 + 2 * c0l;
        if (n < 32) {
            *(float2*)&nump[slab][jr0][n] = make_float2(acc[nt][0], acc[nt][1]);
            *(float2*)&nump[slab][jr1][n] = make_float2(acc[nt][2], acc[nt][3]);
        } else if (n == 32) {
            denp[slab][jr0] = acc[nt][0];
            denp[slab][jr1] = acc[nt][2];
        }
    }
}

// ---------------- K4: reduce partials ----------------------------------------
__global__ void k_out(float* __restrict__ out) {
    int gid = blockIdx.x * blockDim.x + threadIdx.x;
    if (gid >= B_ * DY_) return;
    int j = gid >> 5, dy = gid & 31;
    float n1 = 0.f, d1 = 0.f, n2 = 0.f, d2 = 0.f;
    for (int s = 0; s < NSLAB_C; s++) {
        n1 += g_num1_part[s][j][dy];
        d1 += g_den1_part[s][j];
        n2 += g_num2_part[s][j][dy];
        d2 += g_den2_part[s][j];
    }
    out[gid] = 0.5f * (n1 / d1 + n2 / d2);
}

// ---------------- launch -----------------------------------------------------
extern "C" void kernel_launch(void* const* d_in, const int* in_sizes, int n_in,
                              void* d_out, int out_size) {
    const float* x    = (const float*)d_in[0];
    const float* star = (const float*)d_in[1];
    const float* slb  = (const float*)d_in[2];
    const float* f1   = (const float*)d_in[3];
    const float* f2   = (const float*)d_in[4];
    const float* u1   = (const float*)d_in[5];
    const float* u2   = (const float*)d_in[6];
    const float* ld1  = (const float*)d_in[7];
    const float* ld2  = (const float*)d_in[8];
    const float* W1   = (const float*)d_in[9];
    const float* b1   = (const float*)d_in[10];
    const float* W2   = (const float*)d_in[11];
    const float* b2   = (const float*)d_in[12];
    const int*   li1  = (const int*)d_in[13];
    const int*   li2  = (const int*)d_in[14];
    float* out = (float*)d_out;

    cudaFuncSetAttribute(k_phaseA, cudaFuncAttributeMaxDynamicSharedMemorySize, SA_SIZE);
    cudaFuncSetAttribute(k_phaseC, cudaFuncAttributeMaxDynamicSharedMemorySize, SC_SIZE);

    k_prep<<<(B_ + 3 * N_ + 255) / 256, 256>>>(x, star, f1, f2);
    k_tfT<<<dim3(NP / 32, 5), dim3(32, 8)>>>(f1, f2);
    k_tsT<<<dim3(NP / 32, 1, 2), dim3(32, 8)>>>(slb);
    k_phaseA<<<dim3(16, NSLAB_A), 256, SA_SIZE>>>(x, star);
    k_mid<<<B_, 128>>>(f1, f2, W1, b1, W2, b2, u1, u2);
    k_phaseC<<<dim3(16, NSLAB_C, 2), 256, SC_SIZE>>>(f1, f2, ld1, ld2, li1, li2);
    k_out<<<(B_ * DY_ + 255) / 256, 256>>>(out);
}

// round 9
// speedup vs baseline: 2.9245x; 1.0465x over previous
#include <cuda_runtime.h>
#include <cstdint>
#include <cfloat>

// Problem constants (fixed shapes for MergeNN_38903813767173)
#define B_ 2048
#define N_ 20000
#define D_ 64
#define DY_ 32
#define L_ 100
#define ETA_ 0.01f

#define NP 20224            // 158*128 padded i-extent
#define NCH_TOT 158
#define NSLAB_A 9
#define CPS_A 18            // 9*18 = 162 >= 158 ; grid 16*9 = 144 <= 148 (one wave)
#define NSLAB_C 4
#define CPS_C 40            // 4*40 = 160 >= 158 ; grid 16*4*2 = 128 <= 148

#define XS_STR 68           // X/star/f/xt smem row stride (words): 68%32=4 -> frag lds conflict-free
#define E_STR 132           // E smem row stride: 132%32=4 -> conflict-free
#define FCS 132             // fcombT smem row stride (words)
#define FC_ROWS 136         // 64+64+1+7 pad
#define SLS 132
#define SL_ROWS 40          // 32+1+7 pad

// ---------------- helpers ----------------------------------------------------
__device__ __forceinline__ uint32_t su32(const void* p) {
    return (uint32_t)__cvta_generic_to_shared(p);
}
#define CPA16(dst, src) \
    asm volatile("cp.async.ca.shared.global [%0], [%1], 16;" :: "r"(dst), "l"(src))
#define CP_COMMIT() asm volatile("cp.async.commit_group;")
#define CP_WAIT0()  asm volatile("cp.async.wait_group 0;" ::: "memory")
#define CP_WAIT1()  asm volatile("cp.async.wait_group 1;" ::: "memory")
#define CP_WAIT2()  asm volatile("cp.async.wait_group 2;" ::: "memory")

__device__ __forceinline__ uint32_t tf(float x) {
    uint32_t r; asm("cvt.rna.tf32.f32 %0, %1;" : "=r"(r) : "f"(x)); return r;
}
__device__ __forceinline__ void mma8(float c[4], const uint32_t a[4], const uint32_t b[2]) {
    asm volatile("mma.sync.aligned.m16n8k8.row.col.f32.tf32.tf32.f32 "
                 "{%0,%1,%2,%3}, {%4,%5,%6,%7}, {%8,%9}, {%0,%1,%2,%3};"
                 : "+f"(c[0]), "+f"(c[1]), "+f"(c[2]), "+f"(c[3])
                 : "r"(a[0]), "r"(a[1]), "r"(a[2]), "r"(a[3]), "r"(b[0]), "r"(b[1]));
}

// ---------------- scratch ----------------------------------------------------
__device__ float g_nx[B_];
__device__ float g_ns[N_];
__device__ float g_nf1[N_];
__device__ float g_nf2[N_];
__device__ int   g_match[B_];

__device__ float g_fcombT[FC_ROWS][NP];   // tf32: rows 0-63 e^{-ns}f1^T, 64-127 e^{-ns}f2^T, 128 e^{-ns}, 129-135 zero
__device__ float g_slbcT[2][SL_ROWS][NP]; // tf32: rows 0-31 e^{-nf}slb^T, 32 e^{-nf}, 33-39 zero

__device__ float g_esum_part[NSLAB_A][B_];
__device__ float g_acc1_part[NSLAB_A][B_][D_];
__device__ float g_acc2_part[NSLAB_A][B_][D_];

__device__ float g_xt1[B_][D_];
__device__ float g_xt2[B_][D_];
__device__ float g_nxt1[B_];
__device__ float g_nxt2[B_];
__device__ int   g_yidx1[B_];
__device__ int   g_yidx2[B_];

__device__ float g_num1_part[NSLAB_C][B_][DY_];
__device__ float g_num2_part[NSLAB_C][B_][DY_];
__device__ float g_den1_part[NSLAB_C][B_];
__device__ float g_den2_part[NSLAB_C][B_];

// ---------------- K0: norms + match init -------------------------------------
__global__ void k_prep(const float* __restrict__ x, const float* __restrict__ star,
                       const float* __restrict__ f1, const float* __restrict__ f2) {
    int gid = blockIdx.x * blockDim.x + threadIdx.x;
    const float* src;
    float* dst;
    if (gid < B_) {
        g_match[gid] = 0x7fffffff;
        src = x + gid * D_;        dst = &g_nx[gid];
    } else if (gid < B_ + N_) {
        int r = gid - B_;          src = star + r * D_; dst = &g_ns[r];
    } else if (gid < B_ + 2 * N_) {
        int r = gid - B_ - N_;     src = f1 + r * D_;   dst = &g_nf1[r];
    } else if (gid < B_ + 3 * N_) {
        int r = gid - B_ - 2 * N_; src = f2 + r * D_;   dst = &g_nf2[r];
    } else return;
    float s = 0.f;
    const float4* p = reinterpret_cast<const float4*>(src);
#pragma unroll
    for (int i = 0; i < 16; i++) {
        float4 v = p[i];
        s += v.x * v.x + v.y * v.y + v.z * v.z + v.w * v.w;
    }
    *dst = s;
}

// ---------------- K0b: g_fcombT (transposed, tf32) ---------------------------
__global__ void k_tfT(const float* __restrict__ f1, const float* __restrict__ f2) {
    __shared__ float ts[32][33];
    int tx = threadIdx.x, ty = threadIdx.y;
    int i0 = blockIdx.x * 32;
    int by = blockIdx.y;
    int i = i0 + tx;
    float sc = (i < N_) ? __expf(-g_ns[i]) : 0.f;
    if (by == 4) {
        for (int r = 128 + ty; r < FC_ROWS; r += 8)
            g_fcombT[r][i] = (r == 128) ? __uint_as_float(tf(sc)) : 0.f;
        return;
    }
    const float* src = (by < 2) ? f1 : f2;
    int d0 = (by & 1) * 32;
    int rowbase = by * 32;
#pragma unroll
    for (int q = 0; q < 4; q++) {
        int r = ty + q * 8;
        ts[r][tx] = src[(long)min(i0 + r, N_ - 1) * 64 + d0 + tx];
    }
    __syncthreads();
#pragma unroll
    for (int q = 0; q < 4; q++) {
        int d = ty + q * 8;
        g_fcombT[rowbase + d][i] = __uint_as_float(tf(ts[tx][d] * sc));
    }
}

// ---------------- K0c: g_slbcT (transposed, tf32) ----------------------------
__global__ void k_tsT(const float* __restrict__ slb) {
    __shared__ float ts[32][33];
    int tx = threadIdx.x, ty = threadIdx.y;
    int i0 = blockIdx.x * 32;
    int br = blockIdx.z;
    int i = i0 + tx;
    float sc = (i < N_) ? __expf(-(br ? g_nf2[i] : g_nf1[i])) : 0.f;
#pragma unroll
    for (int q = 0; q < 4; q++) {
        int r = ty + q * 8;
        ts[r][tx] = slb[(long)min(i0 + r, N_ - 1) * 32 + tx];
    }
    __syncthreads();
#pragma unroll
    for (int q = 0; q < 4; q++) {
        int d = ty + q * 8;
        g_slbcT[br][d][i] = __uint_as_float(tf(ts[tx][d] * sc));
    }
    if (ty == 0) g_slbcT[br][32][i] = __uint_as_float(tf(sc));
    if (33 + ty < SL_ROWS) g_slbcT[br][33 + ty][i] = 0.f;
}

// ---------------- phase A ----------------------------------------------------
// smem (bytes): B0 34816 | B1 34816 | FC 71808 | E 67584 | NS 1024
#define SA_B0 0
#define SA_B1 34816
#define SA_FC 69632
#define SA_E  141440
#define SA_NS 209024
#define SA_SIZE 210048

__global__ __launch_bounds__(256, 1)
void k_phaseA(const float* __restrict__ x, const float* __restrict__ star) {
    extern __shared__ char smem[];
    float* buf0 = (float*)(smem + SA_B0);
    float* buf1 = (float*)(smem + SA_B1);
    float* FCs  = (float*)(smem + SA_FC);
    float* Es   = (float*)(smem + SA_E);
    float* nsb  = (float*)(smem + SA_NS);   // [2][128]
    const uint32_t bb0 = su32(buf0), bb1 = su32(buf1), FCb = su32(FCs);

    const int tid = threadIdx.x;
    const int w = tid >> 5, lane = tid & 31;
    const int r0 = lane >> 2, c0l = lane & 3;
    const int jw = w * 16;
    const int j0 = blockIdx.x * 128;
    const int slab = blockIdx.y;
    const int ch0 = slab * CPS_A;
    const int ch1 = min(ch0 + CPS_A, NCH_TOT);
    const int nc = ch1 - ch0;

    // prologue: X->buf0, ST(0)->buf1, FC(0), ns(0)
    const int i0p = ch0 * 128;
    for (int idx = tid; idx < 128 * 16; idx += 256) {
        int r = idx >> 4, g = idx & 15;
        CPA16(bb0 + r * (XS_STR * 4) + g * 16, (const char*)x + (long)(j0 + r) * 256 + g * 16);
    }
    for (int idx = tid; idx < 128 * 16; idx += 256) {
        int r = idx >> 4, g = idx & 15;
        long gi = min(i0p + r, N_ - 1);
        CPA16(bb1 + r * (XS_STR * 4) + g * 16, (const char*)star + gi * 256 + g * 16);
    }
    for (int idx = tid; idx < FC_ROWS * 32; idx += 256) {
        int r = idx >> 5, g = idx & 31;
        CPA16(FCb + r * (FCS * 4) + g * 16,
              (const char*)g_fcombT + ((long)r * NP + i0p) * 4 + g * 16);
    }
    if (tid < 128) { int gi = i0p + tid; nsb[tid] = (gi < N_) ? g_ns[gi] : 1e30f; }
    CP_COMMIT(); CP_WAIT0();
    __syncthreads();

    // persistent A-fragments from X tile (buf0 becomes ST ping buffer afterwards)
    uint32_t aF[8][4];
#pragma unroll
    for (int ks = 0; ks < 8; ks++) {
        aF[ks][0] = tf(buf0[(jw + r0) * XS_STR + ks * 8 + c0l]);
        aF[ks][1] = tf(buf0[(jw + r0 + 8) * XS_STR + ks * 8 + c0l]);
        aF[ks][2] = tf(buf0[(jw + r0) * XS_STR + ks * 8 + c0l + 4]);
        aF[ks][3] = tf(buf0[(jw + r0 + 8) * XS_STR + ks * 8 + c0l + 4]);
    }
    const float nx0 = g_nx[j0 + jw + r0];
    const float nx1 = g_nx[j0 + jw + r0 + 8];
    __syncthreads();   // all warps done reading X from buf0

    float acc[17][4];
#pragma unroll
    for (int n = 0; n < 17; n++)
#pragma unroll
        for (int q = 0; q < 4; q++) acc[n][q] = 0.f;

    for (int c = 0; c < nc; c++) {
        const int i0 = (ch0 + c) * 128;
        // a: prefetch ST(c+1) into buf[c&1]
        if (c + 1 < nc) {
            const uint32_t dstb = (c & 1) ? bb1 : bb0;
            const int i0n = i0 + 128;
            for (int idx = tid; idx < 128 * 16; idx += 256) {
                int r = idx >> 4, g = idx & 15;
                long gi = min(i0n + r, N_ - 1);
                CPA16(dstb + r * (XS_STR * 4) + g * 16, (const char*)star + gi * 256 + g * 16);
            }
            if (tid < 128) {
                int gi = i0n + tid;
                nsb[((c + 1) & 1) * 128 + tid] = (gi < N_) ? g_ns[gi] : 1e30f;
            }
            CP_COMMIT();
        }
        if (c > 0) { if (c + 1 < nc) CP_WAIT2(); else CP_WAIT1(); }
        __syncthreads();

        const float* STs = (c & 1) ? buf0 : buf1;
        const uint32_t* STu = (const uint32_t*)STs;
        const float* nsc = nsb + (c & 1) * 128;

        // MMA1: S = X . star^T ; E = exp(2S - nx) + match detect
        // (B-frags: raw fp32 bits -> HW tf32 truncation; ks-outer for 8 indep chains)
#pragma unroll
        for (int half = 0; half < 2; half++) {
            float cf[8][4];
#pragma unroll
            for (int n = 0; n < 8; n++)
#pragma unroll
                for (int q = 0; q < 4; q++) cf[n][q] = 0.f;
#pragma unroll
            for (int ks = 0; ks < 8; ks++) {
#pragma unroll
                for (int n8 = 0; n8 < 8; n8++) {
                    int nt = half * 8 + n8;
                    uint32_t b[2];
                    b[0] = STu[(nt * 8 + r0) * XS_STR + ks * 8 + c0l];
                    b[1] = STu[(nt * 8 + r0) * XS_STR + ks * 8 + c0l + 4];
                    mma8(cf[n8], aF[ks], b);
                }
            }
#pragma unroll
            for (int n8 = 0; n8 < 8; n8++) {
                int nt = half * 8 + n8;
                int ic0 = nt * 8 + 2 * c0l, ic1 = ic0 + 1;
                float ns0 = nsc[ic0], ns1 = nsc[ic1];
                float t00 = 2.f * cf[n8][0] - nx0, t01 = 2.f * cf[n8][1] - nx0;
                float t10 = 2.f * cf[n8][2] - nx1, t11 = 2.f * cf[n8][3] - nx1;
                if (t00 >= ns0) atomicMin(&g_match[j0 + jw + r0], i0 + ic0);
                if (t01 >= ns1) atomicMin(&g_match[j0 + jw + r0], i0 + ic1);
                if (t10 >= ns0) atomicMin(&g_match[j0 + jw + r0 + 8], i0 + ic0);
                if (t11 >= ns1) atomicMin(&g_match[j0 + jw + r0 + 8], i0 + ic1);
                uint2 v0 = make_uint2(tf(__expf(t00)), tf(__expf(t01)));
                uint2 v1 = make_uint2(tf(__expf(t10)), tf(__expf(t11)));
                *(uint2*)&Es[(jw + r0) * E_STR + ic0] = v0;
                *(uint2*)&Es[(jw + r0 + 8) * E_STR + ic0] = v1;
            }
        }
        __syncwarp();

        // ensure FC(c) ready
        if (c + 1 < nc) CP_WAIT1(); else CP_WAIT0();
        __syncthreads();

        // MMA2: acc += E . fcombT (17 indep chains, conflict-free B)
        const uint32_t* Eu  = (const uint32_t*)Es;
        const uint32_t* FCu = (const uint32_t*)FCs;
#pragma unroll
        for (int kc = 0; kc < 16; kc++) {
            uint32_t a2[4];
            a2[0] = Eu[(jw + r0) * E_STR + kc * 8 + c0l];
            a2[1] = Eu[(jw + r0 + 8) * E_STR + kc * 8 + c0l];
            a2[2] = Eu[(jw + r0) * E_STR + kc * 8 + c0l + 4];
            a2[3] = Eu[(jw + r0 + 8) * E_STR + kc * 8 + c0l + 4];
#pragma unroll
            for (int nt = 0; nt < 17; nt++) {
                uint32_t b[2];
                b[0] = FCu[(nt * 8 + r0) * FCS + kc * 8 + c0l];
                b[1] = FCu[(nt * 8 + r0) * FCS + kc * 8 + c0l + 4];
                mma8(acc[nt], a2, b);
            }
        }
        // prefetch FC(c+1)
        if (c + 1 < nc) {
            __syncthreads();
            const int i0n = i0 + 128;
            for (int idx = tid; idx < FC_ROWS * 32; idx += 256) {
                int r = idx >> 5, g = idx & 31;
                CPA16(FCb + r * (FCS * 4) + g * 16,
                      (const char*)g_fcombT + ((long)r * NP + i0n) * 4 + g * 16);
            }
            CP_COMMIT();
        }
    }

    // writeback
    const int jr0 = j0 + jw + r0, jr1 = jr0 + 8;
#pragma unroll
    for (int nt = 0; nt < 17; nt++) {
        int n = nt * 8 + 2 * c0l;
        if (n < 64) {
            *(float2*)&g_acc1_part[slab][jr0][n] = make_float2(acc[nt][0], acc[nt][1]);
            *(float2*)&g_acc1_part[slab][jr1][n] = make_float2(acc[nt][2], acc[nt][3]);
        } else if (n < 128) {
            *(float2*)&g_acc2_part[slab][jr0][n - 64] = make_float2(acc[nt][0], acc[nt][1]);
            *(float2*)&g_acc2_part[slab][jr1][n - 64] = make_float2(acc[nt][2], acc[nt][3]);
        } else if (n == 128) {
            g_esum_part[slab][jr0] = acc[nt][0];
            g_esum_part[slab][jr1] = acc[nt][2];
        }
    }
}

// ---------------- K2: middle — xt, y = xt@W+b, argmin label ------------------
__global__ __launch_bounds__(128)
void k_mid(const float* __restrict__ f1, const float* __restrict__ f2,
           const float* __restrict__ W1, const float* __restrict__ b1,
           const float* __restrict__ W2, const float* __restrict__ b2,
           const float* __restrict__ u1, const float* __restrict__ u2) {
    int j = blockIdx.x;
    int t = threadIdx.x;

    __shared__ float xts[D_];
    __shared__ float ys[DY_];
    __shared__ float esum_s;
    __shared__ float ny_s;
    __shared__ float redv[128];
    __shared__ int   redi[128];

    int  mi = g_match[j];
    bool hm = (mi != 0x7fffffff);
    if (t == 0) {
        float s = 0.f;
        for (int k = 0; k < NSLAB_A; k++) s += g_esum_part[k][j];
        esum_s = s;
    }
    __syncthreads();

    for (int br = 0; br < 2; br++) {
        const float* f  = br ? f2 : f1;
        const float* W  = br ? W2 : W1;
        const float* bb = br ? b2 : b1;
        const float* u  = br ? u2 : u1;

        if (t < D_) {
            float a = 0.f;
            if (br) { for (int k = 0; k < NSLAB_A; k++) a += g_acc2_part[k][j][t]; }
            else    { for (int k = 0; k < NSLAB_A; k++) a += g_acc1_part[k][j][t]; }
            float v = hm ? f[mi * D_ + t] : a / esum_s;
            xts[t] = v;
            if (br) g_xt2[j][t] = v; else g_xt1[j][t] = v;
        }
        __syncthreads();
        if (t == 0) {
            float s = 0.f;
            for (int d = 0; d < D_; d++) s += xts[d] * xts[d];
            if (br) g_nxt2[j] = s; else g_nxt1[j] = s;
        }
        if (t < DY_) {
            float a = bb[t];
            for (int d = 0; d < D_; d++) a += xts[d] * W[d * DY_ + t];
            ys[t] = a;
        }
        __syncthreads();
        if (t == 0) {
            float s = 0.f;
            for (int dy = 0; dy < DY_; dy++) s += ys[dy] * ys[dy];
            ny_s = s;
        }
        __syncthreads();

        float v = FLT_MAX;
        int   vi = 0x7fffffff;
        if (t < L_) {
            float nu = 0.f, dot = 0.f;
            for (int dy = 0; dy < DY_; dy++) {
                float uu = u[t * DY_ + dy];
                nu += uu * uu;
                dot += uu * ys[dy];
            }
            v = fmaxf(ny_s + nu - 2.f * dot, 0.f);
            vi = t;
        }
        redv[t] = v; redi[t] = vi;
        __syncthreads();
        for (int off = 64; off > 0; off >>= 1) {
            if (t < off) {
                float v2 = redv[t + off]; int i2 = redi[t + off];
                if (v2 < redv[t] || (v2 == redv[t] && i2 < redi[t])) {
                    redv[t] = v2; redi[t] = i2;
                }
            }
            __syncthreads();
        }
        if (t == 0) { if (br) g_yidx2[j] = redi[0]; else g_yidx1[j] = redi[0]; }
        __syncthreads();
    }
}

// ---------------- phase C ----------------------------------------------------
#define SC_B0 0
#define SC_B1 34816
#define SC_SL 69632
#define SC_E  90752
#define SC_MT 158336
#define SC_LI 210048
#define SC_YJ 211072
#define SC_SIZE 211584

__global__ __launch_bounds__(256, 1)
void k_phaseC(const float* __restrict__ f1, const float* __restrict__ f2,
              const float* __restrict__ ld1, const float* __restrict__ ld2,
              const int* __restrict__ li1, const int* __restrict__ li2) {
    extern __shared__ char smem[];
    float* buf0 = (float*)(smem + SC_B0);
    float* buf1 = (float*)(smem + SC_B1);
    float* SLs  = (float*)(smem + SC_SL);
    float* Es   = (float*)(smem + SC_E);
    float* mt   = (float*)(smem + SC_MT);   // [128][101]
    int*   lib  = (int*)(smem + SC_LI);     // [2][128]
    int*   yjs  = (int*)(smem + SC_YJ);
    const uint32_t bb0 = su32(buf0), bb1 = su32(buf1), SLb = su32(SLs);

    const int tid = threadIdx.x;
    const int w = tid >> 5, lane = tid & 31;
    const int r0 = lane >> 2, c0l = lane & 3;
    const int jw = w * 16;
    const int j0 = blockIdx.x * 128;
    const int slab = blockIdx.y;
    const int br = blockIdx.z;
    const int ch0 = slab * CPS_C;
    const int ch1 = min(ch0 + CPS_C, NCH_TOT);
    const int nc = ch1 - ch0;

    const float* f  = br ? f2 : f1;
    const float* ld = br ? ld2 : ld1;
    const int*   li = br ? li2 : li1;
    const float (*xt)[D_] = br ? g_xt2 : g_xt1;
    const float* nxt = br ? g_nxt2 : g_nxt1;
    const int*   yix = br ? g_yidx2 : g_yidx1;
    float (*nump)[B_][DY_] = br ? g_num2_part : g_num1_part;
    float (*denp)[B_]      = br ? g_den2_part : g_den1_part;

    // prologue: XT->buf0, F(0)->buf1, SL(0), lidx(0), yjs
    const int i0p = ch0 * 128;
    for (int idx = tid; idx < 128 * 16; idx += 256) {
        int r = idx >> 4, g = idx & 15;
        CPA16(bb0 + r * (XS_STR * 4) + g * 16, (const char*)&xt[j0 + r][0] + g * 16);
    }
    for (int idx = tid; idx < 128 * 16; idx += 256) {
        int r = idx >> 4, g = idx & 15;
        long gi = min(i0p + r, N_ - 1);
        CPA16(bb1 + r * (XS_STR * 4) + g * 16, (const char*)f + gi * 256 + g * 16);
    }
    for (int idx = tid; idx < SL_ROWS * 32; idx += 256) {
        int r = idx >> 5, g = idx & 31;
        CPA16(SLb + r * (SLS * 4) + g * 16,
              (const char*)&g_slbcT[br][0][0] + ((long)r * NP + i0p) * 4 + g * 16);
    }
    if (tid < 128) {
        lib[tid] = li[min(i0p + tid, N_ - 1)];
        yjs[tid] = yix[j0 + tid];
    }
    CP_COMMIT(); CP_WAIT0();
    __syncthreads();

    uint32_t aF[8][4];
#pragma unroll
    for (int ks = 0; ks < 8; ks++) {
        aF[ks][0] = tf(buf0[(jw + r0) * XS_STR + ks * 8 + c0l]);
        aF[ks][1] = tf(buf0[(jw + r0 + 8) * XS_STR + ks * 8 + c0l]);
        aF[ks][2] = tf(buf0[(jw + r0) * XS_STR + ks * 8 + c0l + 4]);
        aF[ks][3] = tf(buf0[(jw + r0 + 8) * XS_STR + ks * 8 + c0l + 4]);
    }
    const float nxt0 = nxt[j0 + jw + r0];
    const float nxt1 = nxt[j0 + jw + r0 + 8];
    for (int idx = tid; idx < 128 * L_; idx += 256) {
        int j = idx / L_, l = idx - j * L_;
        mt[j * 101 + l] = __expf(-ETA_ * ld[l * L_ + yjs[j]]);
    }
    __syncthreads();   // buf0(XT) consumed, mt ready

    float acc[5][4];
#pragma unroll
    for (int n = 0; n < 5; n++)
#pragma unroll
        for (int q = 0; q < 4; q++) acc[n][q] = 0.f;

    for (int c = 0; c < nc; c++) {
        const int i0 = (ch0 + c) * 128;
        if (c + 1 < nc) {
            const uint32_t dstb = (c & 1) ? bb1 : bb0;
            const int i0n = i0 + 128;
            for (int idx = tid; idx < 128 * 16; idx += 256) {
                int r = idx >> 4, g = idx & 15;
                long gi = min(i0n + r, N_ - 1);
                CPA16(dstb + r * (XS_STR * 4) + g * 16, (const char*)f + gi * 256 + g * 16);
            }
            if (tid < 128)
                lib[((c + 1) & 1) * 128 + tid] = li[min(i0n + tid, N_ - 1)];
            CP_COMMIT();
        }
        if (c > 0) { if (c + 1 < nc) CP_WAIT2(); else CP_WAIT1(); }
        __syncthreads();

        const float* Fs = (c & 1) ? buf0 : buf1;
        const uint32_t* Fu = (const uint32_t*)Fs;
        const int* lic = lib + (c & 1) * 128;

#pragma unroll
        for (int half = 0; half < 2; half++) {
            float cf[8][4];
#pragma unroll
            for (int n = 0; n < 8; n++)
#pragma unroll
                for (int q = 0; q < 4; q++) cf[n][q] = 0.f;
#pragma unroll
            for (int ks = 0; ks < 8; ks++) {
#pragma unroll
                for (int n8 = 0; n8 < 8; n8++) {
                    int nt = half * 8 + n8;
                    uint32_t b[2];
                    b[0] = Fu[(nt * 8 + r0) * XS_STR + ks * 8 + c0l];
                    b[1] = Fu[(nt * 8 + r0) * XS_STR + ks * 8 + c0l + 4];
                    mma8(cf[n8], aF[ks], b);
                }
            }
#pragma unroll
            for (int n8 = 0; n8 < 8; n8++) {
                int nt = half * 8 + n8;
                int ic0 = nt * 8 + 2 * c0l, ic1 = ic0 + 1;
                int l0 = lic[ic0], l1 = lic[ic1];
                float m00 = mt[(jw + r0) * 101 + l0], m01 = mt[(jw + r0) * 101 + l1];
                float m10 = mt[(jw + r0 + 8) * 101 + l0], m11 = mt[(jw + r0 + 8) * 101 + l1];
                float e00 = __expf(2.f * cf[n8][0] - nxt0) * m00;
                float e01 = __expf(2.f * cf[n8][1] - nxt0) * m01;
                float e10 = __expf(2.f * cf[n8][2] - nxt1) * m10;
                float e11 = __expf(2.f * cf[n8][3] - nxt1) * m11;
                uint2 v0 = make_uint2(tf(e00), tf(e01));
                uint2 v1 = make_uint2(tf(e10), tf(e11));
                *(uint2*)&Es[(jw + r0) * E_STR + ic0] = v0;
                *(uint2*)&Es[(jw + r0 + 8) * E_STR + ic0] = v1;
            }
        }
        __syncwarp();

        if (c + 1 < nc) CP_WAIT1(); else CP_WAIT0();
        __syncthreads();

        const uint32_t* Eu  = (const uint32_t*)Es;
        const uint32_t* SLu = (const uint32_t*)SLs;
#pragma unroll
        for (int kc = 0; kc < 16; kc++) {
            uint32_t a2[4];
            a2[0] = Eu[(jw + r0) * E_STR + kc * 8 + c0l];
            a2[1] = Eu[(jw + r0 + 8) * E_STR + kc * 8 + c0l];
            a2[2] = Eu[(jw + r0) * E_STR + kc * 8 + c0l + 4];
            a2[3] = Eu[(jw + r0 + 8) * E_STR + kc * 8 + c0l + 4];
#pragma unroll
            for (int nt = 0; nt < 5; nt++) {
                uint32_t b[2];
                b[0] = SLu[(nt * 8 + r0) * SLS + kc * 8 + c0l];
                b[1] = SLu[(nt * 8 + r0) * SLS + kc * 8 + c0l + 4];
                mma8(acc[nt], a2, b);
            }
        }
        if (c + 1 < nc) {
            __syncthreads();
            const int i0n = i0 + 128;
            for (int idx = tid; idx < SL_ROWS * 32; idx += 256) {
                int r = idx >> 5, g = idx & 31;
                CPA16(SLb + r * (SLS * 4) + g * 16,
                      (const char*)&g_slbcT[br][0][0] + ((long)r * NP + i0n) * 4 + g * 16);
            }
            CP_COMMIT();
        }
    }

    const int jr0 = j0 + jw + r0, jr1 = jr0 + 8;
#pragma unroll
    for (int nt = 0; nt < 5; nt++) {
        int n = nt * 8 + 2 * c0l;
        if (n < 32) {
            *(float2*)&nump[slab][jr0][n] = make_float2(acc[nt][0], acc[nt][1]);
            *(float2*)&nump[slab][jr1][n] = make_float2(acc[nt][2], acc[nt][3]);
        } else if (n == 32) {
            denp[slab][jr0] = acc[nt][0];
            denp[slab][jr1] = acc[nt][2];
        }
    }
}

// ---------------- K4: reduce partials ----------------------------------------
__global__ void k_out(float* __restrict__ out) {
    int gid = blockIdx.x * blockDim.x + threadIdx.x;
    if (gid >= B_ * DY_) return;
    int j = gid >> 5, dy = gid & 31;
    float n1 = 0.f, d1 = 0.f, n2 = 0.f, d2 = 0.f;
    for (int s = 0; s < NSLAB_C; s++) {
        n1 += g_num1_part[s][j][dy];
        d1 += g_den1_part[s][j];
        n2 += g_num2_part[s][j][dy];
        d2 += g_den2_part[s][j];
    }
    out[gid] = 0.5f * (n1 / d1 + n2 / d2);
}

// ---------------- launch -----------------------------------------------------
extern "C" void kernel_launch(void* const* d_in, const int* in_sizes, int n_in,
                              void* d_out, int out_size) {
    const float* x    = (const float*)d_in[0];
    const float* star = (const float*)d_in[1];
    const float* slb  = (const float*)d_in[2];
    const float* f1   = (const float*)d_in[3];
    const float* f2   = (const float*)d_in[4];
    const float* u1   = (const float*)d_in[5];
    const float* u2   = (const float*)d_in[6];
    const float* ld1  = (const float*)d_in[7];
    const float* ld2  = (const float*)d_in[8];
    const float* W1   = (const float*)d_in[9];
    const float* b1   = (const float*)d_in[10];
    const float* W2   = (const float*)d_in[11];
    const float* b2   = (const float*)d_in[12];
    const int*   li1  = (const int*)d_in[13];
    const int*   li2  = (const int*)d_in[14];
    float* out = (float*)d_out;

    cudaFuncSetAttribute(k_phaseA, cudaFuncAttributeMaxDynamicSharedMemorySize, SA_SIZE);
    cudaFuncSetAttribute(k_phaseC, cudaFuncAttributeMaxDynamicSharedMemorySize, SC_SIZE);

    k_prep<<<(B_ + 3 * N_ + 255) / 256, 256>>>(x, star, f1, f2);
    k_tfT<<<dim3(NP / 32, 5), dim3(32, 8)>>>(f1, f2);
    k_tsT<<<dim3(NP / 32, 1, 2), dim3(32, 8)>>>(slb);
    k_phaseA<<<dim3(16, NSLAB_A), 256, SA_SIZE>>>(x, star);
    k_mid<<<B_, 128>>>(f1, f2, W1, b1, W2, b2, u1, u2);
    k_phaseC<<<dim3(16, NSLAB_C, 2), 256, SC_SIZE>>>(f1, f2, ld1, ld2, li1, li2);
    k_out<<<(B_ * DY_ + 255) / 256, 256>>>(out);
}

// round 10
// speedup vs baseline: 3.0866x; 1.0554x over previous
#include <cuda_runtime.h>
#include <cstdint>
#include <cfloat>

// Problem constants (fixed shapes for MergeNN_38903813767173)
#define B_ 2048
#define N_ 20000
#define D_ 64
#define DY_ 32
#define L_ 100
#define ETA_ 0.01f

#define NP 20224            // 158*128 padded i-extent
#define NCH_TOT 158
#define NSLAB_A 9
#define CPS_A 18            // grid 16*9 = 144 <= 148 (one wave)
#define NSLAB_C 4
#define CPS_C 40            // grid 16*4*2 = 128 <= 148

// Strides chosen ≡ 8 (mod 32) words so the (r0, 2*c0l) lds.64 pattern is conflict-free
#define XS_STR 72           // X/star/f/xt smem row stride (words)
#define E_STR 136           // E smem row stride (words)
#define FCS 136             // fcombT smem row stride (words)
#define FC_ROWS 136         // 64+64+1+7 pad
#define SLS 136
#define SL_ROWS 40          // 32+1+7 pad

// ---------------- helpers ----------------------------------------------------
__device__ __forceinline__ uint32_t su32(const void* p) {
    return (uint32_t)__cvta_generic_to_shared(p);
}
#define CPA16(dst, src) \
    asm volatile("cp.async.ca.shared.global [%0], [%1], 16;" :: "r"(dst), "l"(src))
#define CP_COMMIT() asm volatile("cp.async.commit_group;")
#define CP_WAIT0()  asm volatile("cp.async.wait_group 0;" ::: "memory")
#define CP_WAIT1()  asm volatile("cp.async.wait_group 1;" ::: "memory")
#define CP_WAIT2()  asm volatile("cp.async.wait_group 2;" ::: "memory")

__device__ __forceinline__ uint32_t tf(float x) {
    uint32_t r; asm("cvt.rna.tf32.f32 %0, %1;" : "=r"(r) : "f"(x)); return r;
}
__device__ __forceinline__ void mma8(float c[4], const uint32_t a[4], const uint32_t b[2]) {
    asm volatile("mma.sync.aligned.m16n8k8.row.col.f32.tf32.tf32.f32 "
                 "{%0,%1,%2,%3}, {%4,%5,%6,%7}, {%8,%9}, {%0,%1,%2,%3};"
                 : "+f"(c[0]), "+f"(c[1]), "+f"(c[2]), "+f"(c[3])
                 : "r"(a[0]), "r"(a[1]), "r"(a[2]), "r"(a[3]), "r"(b[0]), "r"(b[1]));
}

// ---------------- scratch ----------------------------------------------------
__device__ float g_nx[B_];
__device__ float g_ns[N_];
__device__ float g_nf1[N_];
__device__ float g_nf2[N_];
__device__ int   g_match[B_];

__device__ float g_fcombT[FC_ROWS][NP];   // tf32: rows 0-63 e^{-ns}f1^T, 64-127 e^{-ns}f2^T, 128 e^{-ns}, 129-135 zero
__device__ float g_slbcT[2][SL_ROWS][NP]; // tf32: rows 0-31 e^{-nf}slb^T, 32 e^{-nf}, 33-39 zero

__device__ float g_esum_part[NSLAB_A][B_];
__device__ float g_acc1_part[NSLAB_A][B_][D_];
__device__ float g_acc2_part[NSLAB_A][B_][D_];

__device__ float g_xt1[B_][D_];
__device__ float g_xt2[B_][D_];
__device__ float g_nxt1[B_];
__device__ float g_nxt2[B_];
__device__ int   g_yidx1[B_];
__device__ int   g_yidx2[B_];

__device__ float g_num1_part[NSLAB_C][B_][DY_];
__device__ float g_num2_part[NSLAB_C][B_][DY_];
__device__ float g_den1_part[NSLAB_C][B_];
__device__ float g_den2_part[NSLAB_C][B_];

// ---------------- K0: norms + match init -------------------------------------
__global__ void k_prep(const float* __restrict__ x, const float* __restrict__ star,
                       const float* __restrict__ f1, const float* __restrict__ f2) {
    int gid = blockIdx.x * blockDim.x + threadIdx.x;
    const float* src;
    float* dst;
    if (gid < B_) {
        g_match[gid] = 0x7fffffff;
        src = x + gid * D_;        dst = &g_nx[gid];
    } else if (gid < B_ + N_) {
        int r = gid - B_;          src = star + r * D_; dst = &g_ns[r];
    } else if (gid < B_ + 2 * N_) {
        int r = gid - B_ - N_;     src = f1 + r * D_;   dst = &g_nf1[r];
    } else if (gid < B_ + 3 * N_) {
        int r = gid - B_ - 2 * N_; src = f2 + r * D_;   dst = &g_nf2[r];
    } else return;
    float s = 0.f;
    const float4* p = reinterpret_cast<const float4*>(src);
#pragma unroll
    for (int i = 0; i < 16; i++) {
        float4 v = p[i];
        s += v.x * v.x + v.y * v.y + v.z * v.z + v.w * v.w;
    }
    *dst = s;
}

// ---------------- K0b: g_fcombT (transposed, tf32) ---------------------------
__global__ void k_tfT(const float* __restrict__ f1, const float* __restrict__ f2) {
    __shared__ float ts[32][33];
    int tx = threadIdx.x, ty = threadIdx.y;
    int i0 = blockIdx.x * 32;
    int by = blockIdx.y;
    int i = i0 + tx;
    float sc = (i < N_) ? __expf(-g_ns[i]) : 0.f;
    if (by == 4) {
        for (int r = 128 + ty; r < FC_ROWS; r += 8)
            g_fcombT[r][i] = (r == 128) ? __uint_as_float(tf(sc)) : 0.f;
        return;
    }
    const float* src = (by < 2) ? f1 : f2;
    int d0 = (by & 1) * 32;
    int rowbase = by * 32;
#pragma unroll
    for (int q = 0; q < 4; q++) {
        int r = ty + q * 8;
        ts[r][tx] = src[(long)min(i0 + r, N_ - 1) * 64 + d0 + tx];
    }
    __syncthreads();
#pragma unroll
    for (int q = 0; q < 4; q++) {
        int d = ty + q * 8;
        g_fcombT[rowbase + d][i] = __uint_as_float(tf(ts[tx][d] * sc));
    }
}

// ---------------- K0c: g_slbcT (transposed, tf32) ----------------------------
__global__ void k_tsT(const float* __restrict__ slb) {
    __shared__ float ts[32][33];
    int tx = threadIdx.x, ty = threadIdx.y;
    int i0 = blockIdx.x * 32;
    int br = blockIdx.z;
    int i = i0 + tx;
    float sc = (i < N_) ? __expf(-(br ? g_nf2[i] : g_nf1[i])) : 0.f;
#pragma unroll
    for (int q = 0; q < 4; q++) {
        int r = ty + q * 8;
        ts[r][tx] = slb[(long)min(i0 + r, N_ - 1) * 32 + tx];
    }
    __syncthreads();
#pragma unroll
    for (int q = 0; q < 4; q++) {
        int d = ty + q * 8;
        g_slbcT[br][d][i] = __uint_as_float(tf(ts[tx][d] * sc));
    }
    if (ty == 0) g_slbcT[br][32][i] = __uint_as_float(tf(sc));
    if (33 + ty < SL_ROWS) g_slbcT[br][33 + ty][i] = 0.f;
}

// ---------------- phase A ----------------------------------------------------
// smem (bytes): B0 36864 | B1 36864 | FC 73984 | E 69632 | NS 1024
#define SA_B0 0
#define SA_B1 36864
#define SA_FC 73728
#define SA_E  147712
#define SA_NS 217344
#define SA_SIZE 218368

__global__ __launch_bounds__(256, 1)
void k_phaseA(const float* __restrict__ x, const float* __restrict__ star) {
    extern __shared__ char smem[];
    float* buf0 = (float*)(smem + SA_B0);
    float* buf1 = (float*)(smem + SA_B1);
    float* FCs  = (float*)(smem + SA_FC);
    float* Es   = (float*)(smem + SA_E);
    float* nsb  = (float*)(smem + SA_NS);   // [2][128]
    const uint32_t bb0 = su32(buf0), bb1 = su32(buf1), FCb = su32(FCs);

    const int tid = threadIdx.x;
    const int w = tid >> 5, lane = tid & 31;
    const int r0 = lane >> 2, c0l = lane & 3;
    const int jw = w * 16;
    const int j0 = blockIdx.x * 128;
    const int slab = blockIdx.y;
    const int ch0 = slab * CPS_A;
    const int ch1 = min(ch0 + CPS_A, NCH_TOT);
    const int nc = ch1 - ch0;

    // prologue: X->buf0, ST(0)->buf1, FC(0), ns(0)
    const int i0p = ch0 * 128;
    for (int idx = tid; idx < 128 * 16; idx += 256) {
        int r = idx >> 4, g = idx & 15;
        CPA16(bb0 + r * (XS_STR * 4) + g * 16, (const char*)x + (long)(j0 + r) * 256 + g * 16);
    }
    for (int idx = tid; idx < 128 * 16; idx += 256) {
        int r = idx >> 4, g = idx & 15;
        long gi = min(i0p + r, N_ - 1);
        CPA16(bb1 + r * (XS_STR * 4) + g * 16, (const char*)star + gi * 256 + g * 16);
    }
    for (int idx = tid; idx < FC_ROWS * 32; idx += 256) {
        int r = idx >> 5, g = idx & 31;
        CPA16(FCb + r * (FCS * 4) + g * 16,
              (const char*)g_fcombT + ((long)r * NP + i0p) * 4 + g * 16);
    }
    if (tid < 128) { int gi = i0p + tid; nsb[tid] = (gi < N_) ? g_ns[gi] : 1e30f; }
    CP_COMMIT(); CP_WAIT0();
    __syncthreads();

    // persistent A-fragments (virtual-k perm: pair (2c0l, 2c0l+1) per k-group)
    uint32_t aF[8][4];
#pragma unroll
    for (int ks = 0; ks < 8; ks++) {
        uint2 p0 = *(const uint2*)&buf0[(jw + r0) * XS_STR + ks * 8 + 2 * c0l];
        uint2 p1 = *(const uint2*)&buf0[(jw + r0 + 8) * XS_STR + ks * 8 + 2 * c0l];
        aF[ks][0] = p0.x; aF[ks][1] = p1.x; aF[ks][2] = p0.y; aF[ks][3] = p1.y;
    }
    const float nx0 = g_nx[j0 + jw + r0];
    const float nx1 = g_nx[j0 + jw + r0 + 8];
    __syncthreads();   // all warps done reading X from buf0

    float acc[17][4];
#pragma unroll
    for (int n = 0; n < 17; n++)
#pragma unroll
        for (int q = 0; q < 4; q++) acc[n][q] = 0.f;

    for (int c = 0; c < nc; c++) {
        const int i0 = (ch0 + c) * 128;
        // prefetch ST(c+1) into buf[c&1]
        if (c + 1 < nc) {
            const uint32_t dstb = (c & 1) ? bb1 : bb0;
            const int i0n = i0 + 128;
            for (int idx = tid; idx < 128 * 16; idx += 256) {
                int r = idx >> 4, g = idx & 15;
                long gi = min(i0n + r, N_ - 1);
                CPA16(dstb + r * (XS_STR * 4) + g * 16, (const char*)star + gi * 256 + g * 16);
            }
            if (tid < 128) {
                int gi = i0n + tid;
                nsb[((c + 1) & 1) * 128 + tid] = (gi < N_) ? g_ns[gi] : 1e30f;
            }
            CP_COMMIT();
        }
        if (c > 0) { if (c + 1 < nc) CP_WAIT2(); else CP_WAIT1(); }
        __syncthreads();

        const float* STs = (c & 1) ? buf0 : buf1;
        const float* nsc = nsb + (c & 1) * 128;

        // MMA1: S = X . star^T ; E = exp(2S - nx) + match detect
#pragma unroll
        for (int half = 0; half < 2; half++) {
            float cf[8][4];
#pragma unroll
            for (int n = 0; n < 8; n++)
#pragma unroll
                for (int q = 0; q < 4; q++) cf[n][q] = 0.f;
#pragma unroll
            for (int ks = 0; ks < 8; ks++) {
#pragma unroll
                for (int n8 = 0; n8 < 8; n8++) {
                    int nt = half * 8 + n8;
                    uint2 q = *(const uint2*)&STs[(nt * 8 + r0) * XS_STR + ks * 8 + 2 * c0l];
                    uint32_t b[2] = {q.x, q.y};
                    mma8(cf[n8], aF[ks], b);
                }
            }
#pragma unroll
            for (int n8 = 0; n8 < 8; n8++) {
                int nt = half * 8 + n8;
                int ic0 = nt * 8 + 2 * c0l, ic1 = ic0 + 1;
                float ns0 = nsc[ic0], ns1 = nsc[ic1];
                float t00 = 2.f * cf[n8][0] - nx0, t01 = 2.f * cf[n8][1] - nx0;
                float t10 = 2.f * cf[n8][2] - nx1, t11 = 2.f * cf[n8][3] - nx1;
                if (t00 >= ns0) atomicMin(&g_match[j0 + jw + r0], i0 + ic0);
                if (t01 >= ns1) atomicMin(&g_match[j0 + jw + r0], i0 + ic1);
                if (t10 >= ns0) atomicMin(&g_match[j0 + jw + r0 + 8], i0 + ic0);
                if (t11 >= ns1) atomicMin(&g_match[j0 + jw + r0 + 8], i0 + ic1);
                float2 v0 = make_float2(__expf(t00), __expf(t01));
                float2 v1 = make_float2(__expf(t10), __expf(t11));
                *(float2*)&Es[(jw + r0) * E_STR + ic0] = v0;
                *(float2*)&Es[(jw + r0 + 8) * E_STR + ic0] = v1;
            }
        }
        __syncwarp();

        if (c + 1 < nc) CP_WAIT1(); else CP_WAIT0();
        __syncthreads();

        // MMA2: acc += E . fcombT (virtual-k perm on i-axis, all lds.64)
#pragma unroll
        for (int kc = 0; kc < 16; kc++) {
            uint2 p0 = *(const uint2*)&Es[(jw + r0) * E_STR + kc * 8 + 2 * c0l];
            uint2 p1 = *(const uint2*)&Es[(jw + r0 + 8) * E_STR + kc * 8 + 2 * c0l];
            uint32_t a2[4] = {p0.x, p1.x, p0.y, p1.y};
#pragma unroll
            for (int nt = 0; nt < 17; nt++) {
                uint2 q = *(const uint2*)&FCs[(nt * 8 + r0) * FCS + kc * 8 + 2 * c0l];
                uint32_t b[2] = {q.x, q.y};
                mma8(acc[nt], a2, b);
            }
        }
        if (c + 1 < nc) {
            __syncthreads();
            const int i0n = i0 + 128;
            for (int idx = tid; idx < FC_ROWS * 32; idx += 256) {
                int r = idx >> 5, g = idx & 31;
                CPA16(FCb + r * (FCS * 4) + g * 16,
                      (const char*)g_fcombT + ((long)r * NP + i0n) * 4 + g * 16);
            }
            CP_COMMIT();
        }
    }

    // writeback
    const int jr0 = j0 + jw + r0, jr1 = jr0 + 8;
#pragma unroll
    for (int nt = 0; nt < 17; nt++) {
        int n = nt * 8 + 2 * c0l;
        if (n < 64) {
            *(float2*)&g_acc1_part[slab][jr0][n] = make_float2(acc[nt][0], acc[nt][1]);
            *(float2*)&g_acc1_part[slab][jr1][n] = make_float2(acc[nt][2], acc[nt][3]);
        } else if (n < 128) {
            *(float2*)&g_acc2_part[slab][jr0][n - 64] = make_float2(acc[nt][0], acc[nt][1]);
            *(float2*)&g_acc2_part[slab][jr1][n - 64] = make_float2(acc[nt][2], acc[nt][3]);
        } else if (n == 128) {
            g_esum_part[slab][jr0] = acc[nt][0];
            g_esum_part[slab][jr1] = acc[nt][2];
        }
    }
}

// ---------------- K2: middle — xt, y = xt@W+b, argmin label ------------------
__global__ __launch_bounds__(128)
void k_mid(const float* __restrict__ f1, const float* __restrict__ f2,
           const float* __restrict__ W1, const float* __restrict__ b1,
           const float* __restrict__ W2, const float* __restrict__ b2,
           const float* __restrict__ u1, const float* __restrict__ u2) {
    int j = blockIdx.x;
    int t = threadIdx.x;

    __shared__ float xts[D_];
    __shared__ float ys[DY_];
    __shared__ float esum_s;
    __shared__ float ny_s;
    __shared__ float redv[128];
    __shared__ int   redi[128];

    int  mi = g_match[j];
    bool hm = (mi != 0x7fffffff);
    if (t == 0) {
        float s = 0.f;
        for (int k = 0; k < NSLAB_A; k++) s += g_esum_part[k][j];
        esum_s = s;
    }
    __syncthreads();

    for (int br = 0; br < 2; br++) {
        const float* f  = br ? f2 : f1;
        const float* W  = br ? W2 : W1;
        const float* bb = br ? b2 : b1;
        const float* u  = br ? u2 : u1;

        if (t < D_) {
            float a = 0.f;
            if (br) { for (int k = 0; k < NSLAB_A; k++) a += g_acc2_part[k][j][t]; }
            else    { for (int k = 0; k < NSLAB_A; k++) a += g_acc1_part[k][j][t]; }
            float v = hm ? f[mi * D_ + t] : a / esum_s;
            xts[t] = v;
            if (br) g_xt2[j][t] = v; else g_xt1[j][t] = v;
        }
        __syncthreads();
        if (t == 0) {
            float s = 0.f;
            for (int d = 0; d < D_; d++) s += xts[d] * xts[d];
            if (br) g_nxt2[j] = s; else g_nxt1[j] = s;
        }
        if (t < DY_) {
            float a = bb[t];
            for (int d = 0; d < D_; d++) a += xts[d] * W[d * DY_ + t];
            ys[t] = a;
        }
        __syncthreads();
        if (t == 0) {
            float s = 0.f;
            for (int dy = 0; dy < DY_; dy++) s += ys[dy] * ys[dy];
            ny_s = s;
        }
        __syncthreads();

        float v = FLT_MAX;
        int   vi = 0x7fffffff;
        if (t < L_) {
            float nu = 0.f, dot = 0.f;
            for (int dy = 0; dy < DY_; dy++) {
                float uu = u[t * DY_ + dy];
                nu += uu * uu;
                dot += uu * ys[dy];
            }
            v = fmaxf(ny_s + nu - 2.f * dot, 0.f);
            vi = t;
        }
        redv[t] = v; redi[t] = vi;
        __syncthreads();
        for (int off = 64; off > 0; off >>= 1) {
            if (t < off) {
                float v2 = redv[t + off]; int i2 = redi[t + off];
                if (v2 < redv[t] || (v2 == redv[t] && i2 < redi[t])) {
                    redv[t] = v2; redi[t] = i2;
                }
            }
            __syncthreads();
        }
        if (t == 0) { if (br) g_yidx2[j] = redi[0]; else g_yidx1[j] = redi[0]; }
        __syncthreads();
    }
}

// ---------------- phase C ----------------------------------------------------
// smem (bytes): B0 36864 | B1 36864 | SL 21760 | E 69632 | MT 51712 | LI 1024 | YJ 512
#define SC_B0 0
#define SC_B1 36864
#define SC_SL 73728
#define SC_E  95488
#define SC_MT 165120
#define SC_LI 216832
#define SC_YJ 217856
#define SC_SIZE 218368

__global__ __launch_bounds__(256, 1)
void k_phaseC(const float* __restrict__ f1, const float* __restrict__ f2,
              const float* __restrict__ ld1, const float* __restrict__ ld2,
              const int* __restrict__ li1, const int* __restrict__ li2) {
    extern __shared__ char smem[];
    float* buf0 = (float*)(smem + SC_B0);
    float* buf1 = (float*)(smem + SC_B1);
    float* SLs  = (float*)(smem + SC_SL);
    float* Es   = (float*)(smem + SC_E);
    float* mt   = (float*)(smem + SC_MT);   // [128][101]
    int*   lib  = (int*)(smem + SC_LI);     // [2][128]
    int*   yjs  = (int*)(smem + SC_YJ);
    const uint32_t bb0 = su32(buf0), bb1 = su32(buf1), SLb = su32(SLs);

    const int tid = threadIdx.x;
    const int w = tid >> 5, lane = tid & 31;
    const int r0 = lane >> 2, c0l = lane & 3;
    const int jw = w * 16;
    const int j0 = blockIdx.x * 128;
    const int slab = blockIdx.y;
    const int br = blockIdx.z;
    const int ch0 = slab * CPS_C;
    const int ch1 = min(ch0 + CPS_C, NCH_TOT);
    const int nc = ch1 - ch0;

    const float* f  = br ? f2 : f1;
    const float* ld = br ? ld2 : ld1;
    const int*   li = br ? li2 : li1;
    const float (*xt)[D_] = br ? g_xt2 : g_xt1;
    const float* nxt = br ? g_nxt2 : g_nxt1;
    const int*   yix = br ? g_yidx2 : g_yidx1;
    float (*nump)[B_][DY_] = br ? g_num2_part : g_num1_part;
    float (*denp)[B_]      = br ? g_den2_part : g_den1_part;

    // prologue: XT->buf0, F(0)->buf1, SL(0), lidx(0), yjs
    const int i0p = ch0 * 128;
    for (int idx = tid; idx < 128 * 16; idx += 256) {
        int r = idx >> 4, g = idx & 15;
        CPA16(bb0 + r * (XS_STR * 4) + g * 16, (const char*)&xt[j0 + r][0] + g * 16);
    }
    for (int idx = tid; idx < 128 * 16; idx += 256) {
        int r = idx >> 4, g = idx & 15;
        long gi = min(i0p + r, N_ - 1);
        CPA16(bb1 + r * (XS_STR * 4) + g * 16, (const char*)f + gi * 256 + g * 16);
    }
    for (int idx = tid; idx < SL_ROWS * 32; idx += 256) {
        int r = idx >> 5, g = idx & 31;
        CPA16(SLb + r * (SLS * 4) + g * 16,
              (const char*)&g_slbcT[br][0][0] + ((long)r * NP + i0p) * 4 + g * 16);
    }
    if (tid < 128) {
        lib[tid] = li[min(i0p + tid, N_ - 1)];
        yjs[tid] = yix[j0 + tid];
    }
    CP_COMMIT(); CP_WAIT0();
    __syncthreads();

    uint32_t aF[8][4];
#pragma unroll
    for (int ks = 0; ks < 8; ks++) {
        uint2 p0 = *(const uint2*)&buf0[(jw + r0) * XS_STR + ks * 8 + 2 * c0l];
        uint2 p1 = *(const uint2*)&buf0[(jw + r0 + 8) * XS_STR + ks * 8 + 2 * c0l];
        aF[ks][0] = p0.x; aF[ks][1] = p1.x; aF[ks][2] = p0.y; aF[ks][3] = p1.y;
    }
    const float nxt0 = nxt[j0 + jw + r0];
    const float nxt1 = nxt[j0 + jw + r0 + 8];
    for (int idx = tid; idx < 128 * L_; idx += 256) {
        int j = idx / L_, l = idx - j * L_;
        mt[j * 101 + l] = __expf(-ETA_ * ld[l * L_ + yjs[j]]);
    }
    __syncthreads();   // buf0(XT) consumed, mt ready

    float acc[5][4];
#pragma unroll
    for (int n = 0; n < 5; n++)
#pragma unroll
        for (int q = 0; q < 4; q++) acc[n][q] = 0.f;

    for (int c = 0; c < nc; c++) {
        const int i0 = (ch0 + c) * 128;
        if (c + 1 < nc) {
            const uint32_t dstb = (c & 1) ? bb1 : bb0;
            const int i0n = i0 + 128;
            for (int idx = tid; idx < 128 * 16; idx += 256) {
                int r = idx >> 4, g = idx & 15;
                long gi = min(i0n + r, N_ - 1);
                CPA16(dstb + r * (XS_STR * 4) + g * 16, (const char*)f + gi * 256 + g * 16);
            }
            if (tid < 128)
                lib[((c + 1) & 1) * 128 + tid] = li[min(i0n + tid, N_ - 1)];
            CP_COMMIT();
        }
        if (c > 0) { if (c + 1 < nc) CP_WAIT2(); else CP_WAIT1(); }
        __syncthreads();

        const float* Fs = (c & 1) ? buf0 : buf1;
        const int* lic = lib + (c & 1) * 128;

#pragma unroll
        for (int half = 0; half < 2; half++) {
            float cf[8][4];
#pragma unroll
            for (int n = 0; n < 8; n++)
#pragma unroll
                for (int q = 0; q < 4; q++) cf[n][q] = 0.f;
#pragma unroll
            for (int ks = 0; ks < 8; ks++) {
#pragma unroll
                for (int n8 = 0; n8 < 8; n8++) {
                    int nt = half * 8 + n8;
                    uint2 q = *(const uint2*)&Fs[(nt * 8 + r0) * XS_STR + ks * 8 + 2 * c0l];
                    uint32_t b[2] = {q.x, q.y};
                    mma8(cf[n8], aF[ks], b);
                }
            }
#pragma unroll
            for (int n8 = 0; n8 < 8; n8++) {
                int nt = half * 8 + n8;
                int ic0 = nt * 8 + 2 * c0l, ic1 = ic0 + 1;
                int l0 = lic[ic0], l1 = lic[ic1];
                float m00 = mt[(jw + r0) * 101 + l0], m01 = mt[(jw + r0) * 101 + l1];
                float m10 = mt[(jw + r0 + 8) * 101 + l0], m11 = mt[(jw + r0 + 8) * 101 + l1];
                float2 v0 = make_float2(__expf(2.f * cf[n8][0] - nxt0) * m00,
                                        __expf(2.f * cf[n8][1] - nxt0) * m01);
                float2 v1 = make_float2(__expf(2.f * cf[n8][2] - nxt1) * m10,
                                        __expf(2.f * cf[n8][3] - nxt1) * m11);
                *(float2*)&Es[(jw + r0) * E_STR + ic0] = v0;
                *(float2*)&Es[(jw + r0 + 8) * E_STR + ic0] = v1;
            }
        }
        __syncwarp();

        if (c + 1 < nc) CP_WAIT1(); else CP_WAIT0();
        __syncthreads();

#pragma unroll
        for (int kc = 0; kc < 16; kc++) {
            uint2 p0 = *(const uint2*)&Es[(jw + r0) * E_STR + kc * 8 + 2 * c0l];
            uint2 p1 = *(const uint2*)&Es[(jw + r0 + 8) * E_STR + kc * 8 + 2 * c0l];
            uint32_t a2[4] = {p0.x, p1.x, p0.y, p1.y};
#pragma unroll
            for (int nt = 0; nt < 5; nt++) {
                uint2 q = *(const uint2*)&SLs[(nt * 8 + r0) * SLS + kc * 8 + 2 * c0l];
                uint32_t b[2] = {q.x, q.y};
                mma8(acc[nt], a2, b);
            }
        }
        if (c + 1 < nc) {
            __syncthreads();
            const int i0n = i0 + 128;
            for (int idx = tid; idx < SL_ROWS * 32; idx += 256) {
                int r = idx >> 5, g = idx & 31;
                CPA16(SLb + r * (SLS * 4) + g * 16,
                      (const char*)&g_slbcT[br][0][0] + ((long)r * NP + i0n) * 4 + g * 16);
            }
            CP_COMMIT();
        }
    }

    const int jr0 = j0 + jw + r0, jr1 = jr0 + 8;
#pragma unroll
    for (int nt = 0; nt < 5; nt++) {
        int n = nt * 8 + 2 * c0l;
        if (n < 32) {
            *(float2*)&nump[slab][jr0][n] = make_float2(acc[nt][0], acc[nt][1]);
            *(float2*)&nump[slab][jr1][n] = make_float2(acc[nt][2], acc[nt][3]);
        } else if (n == 32) {
            denp[slab][jr0] = acc[nt][0];
            denp[slab][jr1] = acc[nt][2];
        }
    }
}

// ---------------- K4: reduce partials ----------------------------------------
__global__ void k_out(float* __restrict__ out) {
    int gid = blockIdx.x * blockDim.x + threadIdx.x;
    if (gid >= B_ * DY_) return;
    int j = gid >> 5, dy = gid & 31;
    float n1 = 0.f, d1 = 0.f, n2 = 0.f, d2 = 0.f;
    for (int s = 0; s < NSLAB_C; s++) {
        n1 += g_num1_part[s][j][dy];
        d1 += g_den1_part[s][j];
        n2 += g_num2_part[s][j][dy];
        d2 += g_den2_part[s][j];
    }
    out[gid] = 0.5f * (n1 / d1 + n2 / d2);
}

// ---------------- launch -----------------------------------------------------
extern "C" void kernel_launch(void* const* d_in, const int* in_sizes, int n_in,
                              void* d_out, int out_size) {
    const float* x    = (const float*)d_in[0];
    const float* star = (const float*)d_in[1];
    const float* slb  = (const float*)d_in[2];
    const float* f1   = (const float*)d_in[3];
    const float* f2   = (const float*)d_in[4];
    const float* u1   = (const float*)d_in[5];
    const float* u2   = (const float*)d_in[6];
    const float* ld1  = (const float*)d_in[7];
    const float* ld2  = (const float*)d_in[8];
    const float* W1   = (const float*)d_in[9];
    const float* b1   = (const float*)d_in[10];
    const float* W2   = (const float*)d_in[11];
    const float* b2   = (const float*)d_in[12];
    const int*   li1  = (const int*)d_in[13];
    const int*   li2  = (const int*)d_in[14];
    float* out = (float*)d_out;

    cudaFuncSetAttribute(k_phaseA, cudaFuncAttributeMaxDynamicSharedMemorySize, SA_SIZE);
    cudaFuncSetAttribute(k_phaseC, cudaFuncAttributeMaxDynamicSharedMemorySize, SC_SIZE);

    k_prep<<<(B_ + 3 * N_ + 255) / 256, 256>>>(x, star, f1, f2);
    k_tfT<<<dim3(NP / 32, 5), dim3(32, 8)>>>(f1, f2);
    k_tsT<<<dim3(NP / 32, 1, 2), dim3(32, 8)>>>(slb);
    k_phaseA<<<dim3(16, NSLAB_A), 256, SA_SIZE>>>(x, star);
    k_mid<<<B_, 128>>>(f1, f2, W1, b1, W2, b2, u1, u2);
    k_phaseC<<<dim3(16, NSLAB_C, 2), 256, SC_SIZE>>>(f1, f2, ld1, ld2, li1, li2);
    k_out<<<(B_ * DY_ + 255) / 256, 256>>>(out);
}

// round 11
// speedup vs baseline: 3.3518x; 1.0859x over previous
#include <cuda_runtime.h>
#include <cstdint>
#include <cfloat>

// Problem constants (fixed shapes for MergeNN_38903813767173)
#define B_ 2048
#define N_ 20000
#define D_ 64
#define DY_ 32
#define L_ 100
#define ETA_ 0.01f

#define NP 20224            // 158*128 padded i-extent
#define NCH_TOT 158
#define NSLAB_A 9
#define CPS_A 18            // grid 16*9 = 144 <= 148 (one wave)
#define NSLAB_C 4
#define CPS_C 40            // grid 16*4*2 = 128 <= 148

// Strides ≡ 8 (mod 32) words: the (r0, 2*c0l) lds.64 pattern is conflict-free
#define XS_STR 72           // X/star/f/xt smem row stride (words)
#define FCS 136             // fcombT smem row stride (words)
#define FC_ROWS 136         // 64+64+1+7 pad
#define SLS 136
#define SL_ROWS 40          // 32+1+7 pad

// ---------------- helpers ----------------------------------------------------
__device__ __forceinline__ uint32_t su32(const void* p) {
    return (uint32_t)__cvta_generic_to_shared(p);
}
#define CPA16(dst, src) \
    asm volatile("cp.async.ca.shared.global [%0], [%1], 16;" :: "r"(dst), "l"(src))
#define CP_COMMIT() asm volatile("cp.async.commit_group;")
#define CP_WAIT0()  asm volatile("cp.async.wait_group 0;" ::: "memory")

__device__ __forceinline__ uint32_t tf(float x) {
    uint32_t r; asm("cvt.rna.tf32.f32 %0, %1;" : "=r"(r) : "f"(x)); return r;
}
__device__ __forceinline__ void mma8(float c[4], const uint32_t a[4], const uint32_t b[2]) {
    asm volatile("mma.sync.aligned.m16n8k8.row.col.f32.tf32.tf32.f32 "
                 "{%0,%1,%2,%3}, {%4,%5,%6,%7}, {%8,%9}, {%0,%1,%2,%3};"
                 : "+f"(c[0]), "+f"(c[1]), "+f"(c[2]), "+f"(c[3])
                 : "r"(a[0]), "r"(a[1]), "r"(a[2]), "r"(a[3]), "r"(b[0]), "r"(b[1]));
}

// ---------------- scratch ----------------------------------------------------
__device__ float g_nx[B_];
__device__ float g_ns[N_];
__device__ float g_nf1[N_];
__device__ float g_nf2[N_];
__device__ int   g_match[B_];

__device__ float g_fcombT[FC_ROWS][NP];   // tf32: rows 0-63 e^{-ns}f1^T, 64-127 e^{-ns}f2^T, 128 e^{-ns}, 129-135 zero
__device__ float g_slbcT[2][SL_ROWS][NP]; // tf32: rows 0-31 e^{-nf}slb^T, 32 e^{-nf}, 33-39 zero

__device__ float g_esum_part[NSLAB_A][B_];
__device__ float g_acc1_part[NSLAB_A][B_][D_];
__device__ float g_acc2_part[NSLAB_A][B_][D_];

__device__ float g_xt1[B_][D_];
__device__ float g_xt2[B_][D_];
__device__ float g_nxt1[B_];
__device__ float g_nxt2[B_];
__device__ int   g_yidx1[B_];
__device__ int   g_yidx2[B_];

__device__ float g_num1_part[NSLAB_C][B_][DY_];
__device__ float g_num2_part[NSLAB_C][B_][DY_];
__device__ float g_den1_part[NSLAB_C][B_];
__device__ float g_den2_part[NSLAB_C][B_];

// ---------------- K0: norms + match init -------------------------------------
__global__ void k_prep(const float* __restrict__ x, const float* __restrict__ star,
                       const float* __restrict__ f1, const float* __restrict__ f2) {
    int gid = blockIdx.x * blockDim.x + threadIdx.x;
    const float* src;
    float* dst;
    if (gid < B_) {
        g_match[gid] = 0x7fffffff;
        src = x + gid * D_;        dst = &g_nx[gid];
    } else if (gid < B_ + N_) {
        int r = gid - B_;          src = star + r * D_; dst = &g_ns[r];
    } else if (gid < B_ + 2 * N_) {
        int r = gid - B_ - N_;     src = f1 + r * D_;   dst = &g_nf1[r];
    } else if (gid < B_ + 3 * N_) {
        int r = gid - B_ - 2 * N_; src = f2 + r * D_;   dst = &g_nf2[r];
    } else return;
    float s = 0.f;
    const float4* p = reinterpret_cast<const float4*>(src);
#pragma unroll
    for (int i = 0; i < 16; i++) {
        float4 v = p[i];
        s += v.x * v.x + v.y * v.y + v.z * v.z + v.w * v.w;
    }
    *dst = s;
}

// ---------------- K0b: g_fcombT (transposed, tf32) ---------------------------
__global__ void k_tfT(const float* __restrict__ f1, const float* __restrict__ f2) {
    __shared__ float ts[32][33];
    int tx = threadIdx.x, ty = threadIdx.y;
    int i0 = blockIdx.x * 32;
    int by = blockIdx.y;
    int i = i0 + tx;
    float sc = (i < N_) ? __expf(-g_ns[i]) : 0.f;
    if (by == 4) {
        for (int r = 128 + ty; r < FC_ROWS; r += 8)
            g_fcombT[r][i] = (r == 128) ? __uint_as_float(tf(sc)) : 0.f;
        return;
    }
    const float* src = (by < 2) ? f1 : f2;
    int d0 = (by & 1) * 32;
    int rowbase = by * 32;
#pragma unroll
    for (int q = 0; q < 4; q++) {
        int r = ty + q * 8;
        ts[r][tx] = src[(long)min(i0 + r, N_ - 1) * 64 + d0 + tx];
    }
    __syncthreads();
#pragma unroll
    for (int q = 0; q < 4; q++) {
        int d = ty + q * 8;
        g_fcombT[rowbase + d][i] = __uint_as_float(tf(ts[tx][d] * sc));
    }
}

// ---------------- K0c: g_slbcT (transposed, tf32) ----------------------------
__global__ void k_tsT(const float* __restrict__ slb) {
    __shared__ float ts[32][33];
    int tx = threadIdx.x, ty = threadIdx.y;
    int i0 = blockIdx.x * 32;
    int br = blockIdx.z;
    int i = i0 + tx;
    float sc = (i < N_) ? __expf(-(br ? g_nf2[i] : g_nf1[i])) : 0.f;
#pragma unroll
    for (int q = 0; q < 4; q++) {
        int r = ty + q * 8;
        ts[r][tx] = slb[(long)min(i0 + r, N_ - 1) * 32 + tx];
    }
    __syncthreads();
#pragma unroll
    for (int q = 0; q < 4; q++) {
        int d = ty + q * 8;
        g_slbcT[br][d][i] = __uint_as_float(tf(ts[tx][d] * sc));
    }
    if (ty == 0) g_slbcT[br][32][i] = __uint_as_float(tf(sc));
    if (33 + ty < SL_ROWS) g_slbcT[br][33 + ty][i] = 0.f;
}

// ---------------- phase A ----------------------------------------------------
// smem (bytes): B0 36864 | B1 36864 | FC0 73984 | FC1 73984 | NS 1024
#define SA_B0 0
#define SA_B1 36864
#define SA_F0 73728
#define SA_F1 147712
#define SA_NS 221696
#define SA_SIZE 222720

__global__ __launch_bounds__(256, 1)
void k_phaseA(const float* __restrict__ x, const float* __restrict__ star) {
    extern __shared__ char smem[];
    float* bufs[2] = {(float*)(smem + SA_B0), (float*)(smem + SA_B1)};
    float* fcs[2]  = {(float*)(smem + SA_F0), (float*)(smem + SA_F1)};
    float* nsb = (float*)(smem + SA_NS);   // [2][128]
    const uint32_t bbs[2] = {su32(bufs[0]), su32(bufs[1])};
    const uint32_t fbs[2] = {su32(fcs[0]), su32(fcs[1])};

    const int tid = threadIdx.x;
    const int w = tid >> 5, lane = tid & 31;
    const int r0 = lane >> 2, c0l = lane & 3;
    const int jw = w * 16;
    const int j0 = blockIdx.x * 128;
    const int slab = blockIdx.y;
    const int ch0 = slab * CPS_A;
    const int ch1 = min(ch0 + CPS_A, NCH_TOT);
    const int nc = ch1 - ch0;

    // prologue group(0): X->FC1(temp), ST(0)->buf0, FC(0)->FC0, ns(0)
    const int i0p = ch0 * 128;
    for (int idx = tid; idx < 128 * 16; idx += 256) {
        int r = idx >> 4, g = idx & 15;
        CPA16(fbs[1] + r * (XS_STR * 4) + g * 16, (const char*)x + (long)(j0 + r) * 256 + g * 16);
        long gi = min(i0p + r, N_ - 1);
        CPA16(bbs[0] + r * (XS_STR * 4) + g * 16, (const char*)star + gi * 256 + g * 16);
    }
    for (int idx = tid; idx < FC_ROWS * 32; idx += 256) {
        int r = idx >> 5, g = idx & 31;
        CPA16(fbs[0] + r * (FCS * 4) + g * 16,
              (const char*)g_fcombT + ((long)r * NP + i0p) * 4 + g * 16);
    }
    if (tid < 128) { int gi = i0p + tid; nsb[tid] = (gi < N_) ? g_ns[gi] : 1e30f; }
    CP_COMMIT(); CP_WAIT0();
    __syncthreads();

    // persistent A-fragments from X (in FC1 temp), virtual-k perm (pairs 2c0l,2c0l+1)
    uint32_t aF[8][4];
#pragma unroll
    for (int ks = 0; ks < 8; ks++) {
        uint2 p0 = *(const uint2*)&fcs[1][(jw + r0) * XS_STR + ks * 8 + 2 * c0l];
        uint2 p1 = *(const uint2*)&fcs[1][(jw + r0 + 8) * XS_STR + ks * 8 + 2 * c0l];
        aF[ks][0] = p0.x; aF[ks][1] = p1.x; aF[ks][2] = p0.y; aF[ks][3] = p1.y;
    }
    const float nx0 = g_nx[j0 + jw + r0];
    const float nx1 = g_nx[j0 + jw + r0 + 8];
    __syncthreads();   // all warps done reading X from FC1

    float acc[17][4];
#pragma unroll
    for (int n = 0; n < 17; n++)
#pragma unroll
        for (int q = 0; q < 4; q++) acc[n][q] = 0.f;

    for (int c = 0; c < nc; c++) {
        const int i0 = (ch0 + c) * 128;
        if (c > 0) { CP_WAIT0(); __syncthreads(); }   // group(c) ready; prior buffers free
        // prefetch group(c+1)
        if (c + 1 < nc) {
            const int pb = (c + 1) & 1;
            const int i0n = i0 + 128;
            for (int idx = tid; idx < 128 * 16; idx += 256) {
                int r = idx >> 4, g = idx & 15;
                long gi = min(i0n + r, N_ - 1);
                CPA16(bbs[pb] + r * (XS_STR * 4) + g * 16, (const char*)star + gi * 256 + g * 16);
            }
            for (int idx = tid; idx < FC_ROWS * 32; idx += 256) {
                int r = idx >> 5, g = idx & 31;
                CPA16(fbs[pb] + r * (FCS * 4) + g * 16,
                      (const char*)g_fcombT + ((long)r * NP + i0n) * 4 + g * 16);
            }
            if (tid < 128) {
                int gi = i0n + tid;
                nsb[pb * 128 + tid] = (gi < N_) ? g_ns[gi] : 1e30f;
            }
            CP_COMMIT();
        }

        const float* STs = bufs[c & 1];
        const float* FCc = fcs[c & 1];
        const float* nsc = nsb + (c & 1) * 128;

        // MMA1 half -> exp in regs -> fused MMA2 (no smem round-trip for E)
#pragma unroll
        for (int half = 0; half < 2; half++) {
            float cf[8][4];
#pragma unroll
            for (int n = 0; n < 8; n++)
#pragma unroll
                for (int q = 0; q < 4; q++) cf[n][q] = 0.f;
#pragma unroll
            for (int ks = 0; ks < 8; ks++) {
#pragma unroll
                for (int n8 = 0; n8 < 8; n8++) {
                    int nt = half * 8 + n8;
                    uint2 q = *(const uint2*)&STs[(nt * 8 + r0) * XS_STR + ks * 8 + 2 * c0l];
                    uint32_t b[2] = {q.x, q.y};
                    mma8(cf[n8], aF[ks], b);
                }
            }
#pragma unroll
            for (int n8 = 0; n8 < 8; n8++) {
                int nt = half * 8 + n8;
                int ic0 = nt * 8 + 2 * c0l, ic1 = ic0 + 1;
                float ns0 = nsc[ic0], ns1 = nsc[ic1];
                float t00 = 2.f * cf[n8][0] - nx0, t01 = 2.f * cf[n8][1] - nx0;
                float t10 = 2.f * cf[n8][2] - nx1, t11 = 2.f * cf[n8][3] - nx1;
                if (t00 >= ns0) atomicMin(&g_match[j0 + jw + r0], i0 + ic0);
                if (t01 >= ns1) atomicMin(&g_match[j0 + jw + r0], i0 + ic1);
                if (t10 >= ns0) atomicMin(&g_match[j0 + jw + r0 + 8], i0 + ic0);
                if (t11 >= ns1) atomicMin(&g_match[j0 + jw + r0 + 8], i0 + ic1);
                // MMA2 A-fragment = {e00, e10, e01, e11} (layout identity, kc = nt)
                uint32_t a2[4];
                a2[0] = __float_as_uint(__expf(t00));
                a2[1] = __float_as_uint(__expf(t10));
                a2[2] = __float_as_uint(__expf(t01));
                a2[3] = __float_as_uint(__expf(t11));
#pragma unroll
                for (int nt2 = 0; nt2 < 17; nt2++) {
                    uint2 q = *(const uint2*)&FCc[(nt2 * 8 + r0) * FCS + nt * 8 + 2 * c0l];
                    uint32_t b[2] = {q.x, q.y};
                    mma8(acc[nt2], a2, b);
                }
            }
        }
    }

    // writeback
    const int jr0 = j0 + jw + r0, jr1 = jr0 + 8;
#pragma unroll
    for (int nt = 0; nt < 17; nt++) {
        int n = nt * 8 + 2 * c0l;
        if (n < 64) {
            *(float2*)&g_acc1_part[slab][jr0][n] = make_float2(acc[nt][0], acc[nt][1]);
            *(float2*)&g_acc1_part[slab][jr1][n] = make_float2(acc[nt][2], acc[nt][3]);
        } else if (n < 128) {
            *(float2*)&g_acc2_part[slab][jr0][n - 64] = make_float2(acc[nt][0], acc[nt][1]);
            *(float2*)&g_acc2_part[slab][jr1][n - 64] = make_float2(acc[nt][2], acc[nt][3]);
        } else if (n == 128) {
            g_esum_part[slab][jr0] = acc[nt][0];
            g_esum_part[slab][jr1] = acc[nt][2];
        }
    }
}

// ---------------- K2: middle — xt, y = xt@W+b, argmin label ------------------
__global__ __launch_bounds__(128)
void k_mid(const float* __restrict__ f1, const float* __restrict__ f2,
           const float* __restrict__ W1, const float* __restrict__ b1,
           const float* __restrict__ W2, const float* __restrict__ b2,
           const float* __restrict__ u1, const float* __restrict__ u2) {
    int j = blockIdx.x;
    int t = threadIdx.x;

    __shared__ float xts[D_];
    __shared__ float ys[DY_];
    __shared__ float esum_s;
    __shared__ float ny_s;
    __shared__ float redv[128];
    __shared__ int   redi[128];

    int  mi = g_match[j];
    bool hm = (mi != 0x7fffffff);
    if (t == 0) {
        float s = 0.f;
        for (int k = 0; k < NSLAB_A; k++) s += g_esum_part[k][j];
        esum_s = s;
    }
    __syncthreads();

    for (int br = 0; br < 2; br++) {
        const float* f  = br ? f2 : f1;
        const float* W  = br ? W2 : W1;
        const float* bb = br ? b2 : b1;
        const float* u  = br ? u2 : u1;

        if (t < D_) {
            float a = 0.f;
            if (br) { for (int k = 0; k < NSLAB_A; k++) a += g_acc2_part[k][j][t]; }
            else    { for (int k = 0; k < NSLAB_A; k++) a += g_acc1_part[k][j][t]; }
            float v = hm ? f[mi * D_ + t] : a / esum_s;
            xts[t] = v;
            if (br) g_xt2[j][t] = v; else g_xt1[j][t] = v;
        }
        __syncthreads();
        if (t == 0) {
            float s = 0.f;
            for (int d = 0; d < D_; d++) s += xts[d] * xts[d];
            if (br) g_nxt2[j] = s; else g_nxt1[j] = s;
        }
        if (t < DY_) {
            float a = bb[t];
            for (int d = 0; d < D_; d++) a += xts[d] * W[d * DY_ + t];
            ys[t] = a;
        }
        __syncthreads();
        if (t == 0) {
            float s = 0.f;
            for (int dy = 0; dy < DY_; dy++) s += ys[dy] * ys[dy];
            ny_s = s;
        }
        __syncthreads();

        float v = FLT_MAX;
        int   vi = 0x7fffffff;
        if (t < L_) {
            float nu = 0.f, dot = 0.f;
            for (int dy = 0; dy < DY_; dy++) {
                float uu = u[t * DY_ + dy];
                nu += uu * uu;
                dot += uu * ys[dy];
            }
            v = fmaxf(ny_s + nu - 2.f * dot, 0.f);
            vi = t;
        }
        redv[t] = v; redi[t] = vi;
        __syncthreads();
        for (int off = 64; off > 0; off >>= 1) {
            if (t < off) {
                float v2 = redv[t + off]; int i2 = redi[t + off];
                if (v2 < redv[t] || (v2 == redv[t] && i2 < redi[t])) {
                    redv[t] = v2; redi[t] = i2;
                }
            }
            __syncthreads();
        }
        if (t == 0) { if (br) g_yidx2[j] = redi[0]; else g_yidx1[j] = redi[0]; }
        __syncthreads();
    }
}

// ---------------- phase C ----------------------------------------------------
// smem (bytes): B0 36864 | B1 36864 | SL0 21760 | SL1 21760 | MT 51712 | LI 1024 | YJ 512
#define SC_B0 0
#define SC_B1 36864
#define SC_S0 73728
#define SC_S1 95488
#define SC_MT 117248
#define SC_LI 168960
#define SC_YJ 169984
#define SC_SIZE 170496

__global__ __launch_bounds__(256, 1)
void k_phaseC(const float* __restrict__ f1, const float* __restrict__ f2,
              const float* __restrict__ ld1, const float* __restrict__ ld2,
              const int* __restrict__ li1, const int* __restrict__ li2) {
    extern __shared__ char smem[];
    float* bufs[2] = {(float*)(smem + SC_B0), (float*)(smem + SC_B1)};
    float* sls[2]  = {(float*)(smem + SC_S0), (float*)(smem + SC_S1)};
    float* mt  = (float*)(smem + SC_MT);    // [128][101]
    int*   lib = (int*)(smem + SC_LI);      // [2][128]
    int*   yjs = (int*)(smem + SC_YJ);
    const uint32_t bbs[2] = {su32(bufs[0]), su32(bufs[1])};
    const uint32_t sbs[2] = {su32(sls[0]), su32(sls[1])};

    const int tid = threadIdx.x;
    const int w = tid >> 5, lane = tid & 31;
    const int r0 = lane >> 2, c0l = lane & 3;
    const int jw = w * 16;
    const int j0 = blockIdx.x * 128;
    const int slab = blockIdx.y;
    const int br = blockIdx.z;
    const int ch0 = slab * CPS_C;
    const int ch1 = min(ch0 + CPS_C, NCH_TOT);
    const int nc = ch1 - ch0;

    const float* f  = br ? f2 : f1;
    const float* ld = br ? ld2 : ld1;
    const int*   li = br ? li2 : li1;
    const float (*xt)[D_] = br ? g_xt2 : g_xt1;
    const float* nxt = br ? g_nxt2 : g_nxt1;
    const int*   yix = br ? g_yidx2 : g_yidx1;
    float (*nump)[B_][DY_] = br ? g_num2_part : g_num1_part;
    float (*denp)[B_]      = br ? g_den2_part : g_den1_part;

    // prologue group(0): XT->buf1(temp), F(0)->buf0, SL(0)->SL0, lidx(0), yjs
    const int i0p = ch0 * 128;
    for (int idx = tid; idx < 128 * 16; idx += 256) {
        int r = idx >> 4, g = idx & 15;
        CPA16(bbs[1] + r * (XS_STR * 4) + g * 16, (const char*)&xt[j0 + r][0] + g * 16);
        long gi = min(i0p + r, N_ - 1);
        CPA16(bbs[0] + r * (XS_STR * 4) + g * 16, (const char*)f + gi * 256 + g * 16);
    }
    for (int idx = tid; idx < SL_ROWS * 32; idx += 256) {
        int r = idx >> 5, g = idx & 31;
        CPA16(sbs[0] + r * (SLS * 4) + g * 16,
              (const char*)&g_slbcT[br][0][0] + ((long)r * NP + i0p) * 4 + g * 16);
    }
    if (tid < 128) {
        lib[tid] = li[min(i0p + tid, N_ - 1)];
        yjs[tid] = yix[j0 + tid];
    }
    CP_COMMIT(); CP_WAIT0();
    __syncthreads();

    uint32_t aF[8][4];
#pragma unroll
    for (int ks = 0; ks < 8; ks++) {
        uint2 p0 = *(const uint2*)&bufs[1][(jw + r0) * XS_STR + ks * 8 + 2 * c0l];
        uint2 p1 = *(const uint2*)&bufs[1][(jw + r0 + 8) * XS_STR + ks * 8 + 2 * c0l];
        aF[ks][0] = p0.x; aF[ks][1] = p1.x; aF[ks][2] = p0.y; aF[ks][3] = p1.y;
    }
    const float nxt0 = nxt[j0 + jw + r0];
    const float nxt1 = nxt[j0 + jw + r0 + 8];
    for (int idx = tid; idx < 128 * L_; idx += 256) {
        int j = idx / L_, l = idx - j * L_;
        mt[j * 101 + l] = __expf(-ETA_ * ld[l * L_ + yjs[j]]);
    }
    __syncthreads();   // buf1(XT) consumed, mt ready

    float acc[5][4];
#pragma unroll
    for (int n = 0; n < 5; n++)
#pragma unroll
        for (int q = 0; q < 4; q++) acc[n][q] = 0.f;

    for (int c = 0; c < nc; c++) {
        const int i0 = (ch0 + c) * 128;
        if (c > 0) { CP_WAIT0(); __syncthreads(); }
        if (c + 1 < nc) {
            const int pb = (c + 1) & 1;
            const int i0n = i0 + 128;
            for (int idx = tid; idx < 128 * 16; idx += 256) {
                int r = idx >> 4, g = idx & 15;
                long gi = min(i0n + r, N_ - 1);
                CPA16(bbs[pb] + r * (XS_STR * 4) + g * 16, (const char*)f + gi * 256 + g * 16);
            }
            for (int idx = tid; idx < SL_ROWS * 32; idx += 256) {
                int r = idx >> 5, g = idx & 31;
                CPA16(sbs[pb] + r * (SLS * 4) + g * 16,
                      (const char*)&g_slbcT[br][0][0] + ((long)r * NP + i0n) * 4 + g * 16);
            }
            if (tid < 128)
                lib[pb * 128 + tid] = li[min(i0n + tid, N_ - 1)];
            CP_COMMIT();
        }

        const float* Fs  = bufs[c & 1];
        const float* SLc = sls[c & 1];
        const int*   lic = lib + (c & 1) * 128;

#pragma unroll
        for (int half = 0; half < 2; half++) {
            float cf[8][4];
#pragma unroll
            for (int n = 0; n < 8; n++)
#pragma unroll
                for (int q = 0; q < 4; q++) cf[n][q] = 0.f;
#pragma unroll
            for (int ks = 0; ks < 8; ks++) {
#pragma unroll
                for (int n8 = 0; n8 < 8; n8++) {
                    int nt = half * 8 + n8;
                    uint2 q = *(const uint2*)&Fs[(nt * 8 + r0) * XS_STR + ks * 8 + 2 * c0l];
                    uint32_t b[2] = {q.x, q.y};
                    mma8(cf[n8], aF[ks], b);
                }
            }
#pragma unroll
            for (int n8 = 0; n8 < 8; n8++) {
                int nt = half * 8 + n8;
                int ic0 = nt * 8 + 2 * c0l, ic1 = ic0 + 1;
                int l0 = lic[ic0], l1 = lic[ic1];
                float m00 = mt[(jw + r0) * 101 + l0], m01 = mt[(jw + r0) * 101 + l1];
                float m10 = mt[(jw + r0 + 8) * 101 + l0], m11 = mt[(jw + r0 + 8) * 101 + l1];
                uint32_t a2[4];
                a2[0] = __float_as_uint(__expf(2.f * cf[n8][0] - nxt0) * m00);
                a2[1] = __float_as_uint(__expf(2.f * cf[n8][2] - nxt1) * m10);
                a2[2] = __float_as_uint(__expf(2.f * cf[n8][1] - nxt0) * m01);
                a2[3] = __float_as_uint(__expf(2.f * cf[n8][3] - nxt1) * m11);
#pragma unroll
                for (int nt2 = 0; nt2 < 5; nt2++) {
                    uint2 q = *(const uint2*)&SLc[(nt2 * 8 + r0) * SLS + nt * 8 + 2 * c0l];
                    uint32_t b[2] = {q.x, q.y};
                    mma8(acc[nt2], a2, b);
                }
            }
        }
    }

    const int jr0 = j0 + jw + r0, jr1 = jr0 + 8;
#pragma unroll
    for (int nt = 0; nt < 5; nt++) {
        int n = nt * 8 + 2 * c0l;
        if (n < 32) {
            *(float2*)&nump[slab][jr0][n] = make_float2(acc[nt][0], acc[nt][1]);
            *(float2*)&nump[slab][jr1][n] = make_float2(acc[nt][2], acc[nt][3]);
        } else if (n == 32) {
            denp[slab][jr0] = acc[nt][0];
            denp[slab][jr1] = acc[nt][2];
        }
    }
}

// ---------------- K4: reduce partials ----------------------------------------
__global__ void k_out(float* __restrict__ out) {
    int gid = blockIdx.x * blockDim.x + threadIdx.x;
    if (gid >= B_ * DY_) return;
    int j = gid >> 5, dy = gid & 31;
    float n1 = 0.f, d1 = 0.f, n2 = 0.f, d2 = 0.f;
    for (int s = 0; s < NSLAB_C; s++) {
        n1 += g_num1_part[s][j][dy];
        d1 += g_den1_part[s][j];
        n2 += g_num2_part[s][j][dy];
        d2 += g_den2_part[s][j];
    }
    out[gid] = 0.5f * (n1 / d1 + n2 / d2);
}

// ---------------- launch -----------------------------------------------------
extern "C" void kernel_launch(void* const* d_in, const int* in_sizes, int n_in,
                              void* d_out, int out_size) {
    const float* x    = (const float*)d_in[0];
    const float* star = (const float*)d_in[1];
    const float* slb  = (const float*)d_in[2];
    const float* f1   = (const float*)d_in[3];
    const float* f2   = (const float*)d_in[4];
    const float* u1   = (const float*)d_in[5];
    const float* u2   = (const float*)d_in[6];
    const float* ld1  = (const float*)d_in[7];
    const float* ld2  = (const float*)d_in[8];
    const float* W1   = (const float*)d_in[9];
    const float* b1   = (const float*)d_in[10];
    const float* W2   = (const float*)d_in[11];
    const float* b2   = (const float*)d_in[12];
    const int*   li1  = (const int*)d_in[13];
    const int*   li2  = (const int*)d_in[14];
    float* out = (float*)d_out;

    cudaFuncSetAttribute(k_phaseA, cudaFuncAttributeMaxDynamicSharedMemorySize, SA_SIZE);
    cudaFuncSetAttribute(k_phaseC, cudaFuncAttributeMaxDynamicSharedMemorySize, SC_SIZE);

    k_prep<<<(B_ + 3 * N_ + 255) / 256, 256>>>(x, star, f1, f2);
    k_tfT<<<dim3(NP / 32, 5), dim3(32, 8)>>>(f1, f2);
    k_tsT<<<dim3(NP / 32, 1, 2), dim3(32, 8)>>>(slb);
    k_phaseA<<<dim3(16, NSLAB_A), 256, SA_SIZE>>>(x, star);
    k_mid<<<B_, 128>>>(f1, f2, W1, b1, W2, b2, u1, u2);
    k_phaseC<<<dim3(16, NSLAB_C, 2), 256, SC_SIZE>>>(f1, f2, ld1, ld2, li1, li2);
    k_out<<<(B_ * DY_ + 255) / 256, 256>>>(out);
}

// round 12
// speedup vs baseline: 3.5866x; 1.0700x over previous
#include <cuda_runtime.h>
#include <cstdint>
#include <cfloat>

// Problem constants (fixed shapes for MergeNN_38903813767173)
#define B_ 2048
#define N_ 20000
#define D_ 64
#define DY_ 32
#define L_ 100
#define ETA_ 0.01f

#define NP 20224            // 158*128 padded i-extent
#define NCH_TOT 158
#define NSLAB_A 9
#define CPS_A 18            // grid 32*9 = 288 <= 296 (one wave @ 2 CTA/SM)
#define NSLAB_C 4
#define CPS_C 40            // grid 32*4*2 = 256 <= 296

// Strides ≡ 8 (mod 32) words: the (r0, 2*c0l) lds.64 pattern is conflict-free
#define XS_STR 72           // star/f smem row stride (words)
#define FCS 136             // fcombT smem row stride (words)
#define FC_ROWS 136         // 64+64+1+7 pad
#define SLS 136
#define SL_ROWS 40          // 32+1+7 pad

// ---------------- helpers ----------------------------------------------------
__device__ __forceinline__ uint32_t su32(const void* p) {
    return (uint32_t)__cvta_generic_to_shared(p);
}
#define CPA16(dst, src) \
    asm volatile("cp.async.ca.shared.global [%0], [%1], 16;" :: "r"(dst), "l"(src))
#define CP_COMMIT() asm volatile("cp.async.commit_group;")
#define CP_WAIT0()  asm volatile("cp.async.wait_group 0;" ::: "memory")

__device__ __forceinline__ uint32_t tf(float x) {
    uint32_t r; asm("cvt.rna.tf32.f32 %0, %1;" : "=r"(r) : "f"(x)); return r;
}
__device__ __forceinline__ void mma8(float c[4], const uint32_t a[4], const uint32_t b[2]) {
    asm volatile("mma.sync.aligned.m16n8k8.row.col.f32.tf32.tf32.f32 "
                 "{%0,%1,%2,%3}, {%4,%5,%6,%7}, {%8,%9}, {%0,%1,%2,%3};"
                 : "+f"(c[0]), "+f"(c[1]), "+f"(c[2]), "+f"(c[3])
                 : "r"(a[0]), "r"(a[1]), "r"(a[2]), "r"(a[3]), "r"(b[0]), "r"(b[1]));
}

// ---------------- scratch ----------------------------------------------------
__device__ float g_nx[B_];
__device__ float g_ns[N_];
__device__ float g_nf1[N_];
__device__ float g_nf2[N_];
__device__ int   g_match[B_];

__device__ float g_fcombT[FC_ROWS][NP];   // tf32: rows 0-63 e^{-ns}f1^T, 64-127 e^{-ns}f2^T, 128 e^{-ns}, 129-135 zero
__device__ float g_slbcT[2][SL_ROWS][NP]; // tf32: rows 0-31 e^{-nf}slb^T, 32 e^{-nf}, 33-39 zero

__device__ float g_esum_part[NSLAB_A][B_];
__device__ float g_acc1_part[NSLAB_A][B_][D_];
__device__ float g_acc2_part[NSLAB_A][B_][D_];

__device__ float g_xt1[B_][D_];
__device__ float g_xt2[B_][D_];
__device__ float g_nxt1[B_];
__device__ float g_nxt2[B_];
__device__ int   g_yidx1[B_];
__device__ int   g_yidx2[B_];

__device__ float g_num1_part[NSLAB_C][B_][DY_];
__device__ float g_num2_part[NSLAB_C][B_][DY_];
__device__ float g_den1_part[NSLAB_C][B_];
__device__ float g_den2_part[NSLAB_C][B_];

// ---------------- K0: norms + match init -------------------------------------
__global__ void k_prep(const float* __restrict__ x, const float* __restrict__ star,
                       const float* __restrict__ f1, const float* __restrict__ f2) {
    int gid = blockIdx.x * blockDim.x + threadIdx.x;
    const float* src;
    float* dst;
    if (gid < B_) {
        g_match[gid] = 0x7fffffff;
        src = x + gid * D_;        dst = &g_nx[gid];
    } else if (gid < B_ + N_) {
        int r = gid - B_;          src = star + r * D_; dst = &g_ns[r];
    } else if (gid < B_ + 2 * N_) {
        int r = gid - B_ - N_;     src = f1 + r * D_;   dst = &g_nf1[r];
    } else if (gid < B_ + 3 * N_) {
        int r = gid - B_ - 2 * N_; src = f2 + r * D_;   dst = &g_nf2[r];
    } else return;
    float s = 0.f;
    const float4* p = reinterpret_cast<const float4*>(src);
#pragma unroll
    for (int i = 0; i < 16; i++) {
        float4 v = p[i];
        s += v.x * v.x + v.y * v.y + v.z * v.z + v.w * v.w;
    }
    *dst = s;
}

// ---------------- K0b: g_fcombT (transposed, tf32) ---------------------------
__global__ void k_tfT(const float* __restrict__ f1, const float* __restrict__ f2) {
    __shared__ float ts[32][33];
    int tx = threadIdx.x, ty = threadIdx.y;
    int i0 = blockIdx.x * 32;
    int by = blockIdx.y;
    int i = i0 + tx;
    float sc = (i < N_) ? __expf(-g_ns[i]) : 0.f;
    if (by == 4) {
        for (int r = 128 + ty; r < FC_ROWS; r += 8)
            g_fcombT[r][i] = (r == 128) ? __uint_as_float(tf(sc)) : 0.f;
        return;
    }
    const float* src = (by < 2) ? f1 : f2;
    int d0 = (by & 1) * 32;
    int rowbase = by * 32;
#pragma unroll
    for (int q = 0; q < 4; q++) {
        int r = ty + q * 8;
        ts[r][tx] = src[(long)min(i0 + r, N_ - 1) * 64 + d0 + tx];
    }
    __syncthreads();
#pragma unroll
    for (int q = 0; q < 4; q++) {
        int d = ty + q * 8;
        g_fcombT[rowbase + d][i] = __uint_as_float(tf(ts[tx][d] * sc));
    }
}

// ---------------- K0c: g_slbcT (transposed, tf32) ----------------------------
__global__ void k_tsT(const float* __restrict__ slb) {
    __shared__ float ts[32][33];
    int tx = threadIdx.x, ty = threadIdx.y;
    int i0 = blockIdx.x * 32;
    int br = blockIdx.z;
    int i = i0 + tx;
    float sc = (i < N_) ? __expf(-(br ? g_nf2[i] : g_nf1[i])) : 0.f;
#pragma unroll
    for (int q = 0; q < 4; q++) {
        int r = ty + q * 8;
        ts[r][tx] = slb[(long)min(i0 + r, N_ - 1) * 32 + tx];
    }
    __syncthreads();
#pragma unroll
    for (int q = 0; q < 4; q++) {
        int d = ty + q * 8;
        g_slbcT[br][d][i] = __uint_as_float(tf(ts[tx][d] * sc));
    }
    if (ty == 0) g_slbcT[br][32][i] = __uint_as_float(tf(sc));
    if (33 + ty < SL_ROWS) g_slbcT[br][33 + ty][i] = 0.f;
}

// ---------------- phase A ----------------------------------------------------
// 128 threads (4 warps, JT=64), 2 CTAs/SM. Single-buffered ST + FC.
// smem (bytes): ST 36864 | FC 73984 | NS 512 = 111360
#define SA_ST 0
#define SA_FC 36864
#define SA_NS 110848
#define SA_SIZE 111360

__global__ __launch_bounds__(128, 2)
void k_phaseA(const float* __restrict__ x, const float* __restrict__ star) {
    extern __shared__ char smem[];
    float* STs = (float*)(smem + SA_ST);
    float* FCs = (float*)(smem + SA_FC);
    float* nsb = (float*)(smem + SA_NS);   // [128]
    const uint32_t STb = su32(STs), FCb = su32(FCs);

    const int tid = threadIdx.x;
    const int w = tid >> 5, lane = tid & 31;
    const int r0 = lane >> 2, c0l = lane & 3;
    const int jw = w * 16;
    const int j0 = blockIdx.x * 64;
    const int slab = blockIdx.y;
    const int ch0 = slab * CPS_A;
    const int ch1 = min(ch0 + CPS_A, NCH_TOT);
    const int nc = ch1 - ch0;

    // A-fragments straight from global X (once)
    uint32_t aF[8][4];
#pragma unroll
    for (int ks = 0; ks < 8; ks++) {
        uint2 p0 = *(const uint2*)(x + (long)(j0 + jw + r0) * 64 + ks * 8 + 2 * c0l);
        uint2 p1 = *(const uint2*)(x + (long)(j0 + jw + r0 + 8) * 64 + ks * 8 + 2 * c0l);
        aF[ks][0] = p0.x; aF[ks][1] = p1.x; aF[ks][2] = p0.y; aF[ks][3] = p1.y;
    }
    const float nx0 = g_nx[j0 + jw + r0];
    const float nx1 = g_nx[j0 + jw + r0 + 8];

    // chunk 0 loads
    {
        const int i0p = ch0 * 128;
        for (int idx = tid; idx < 128 * 16; idx += 128) {
            int r = idx >> 4, g = idx & 15;
            long gi = min(i0p + r, N_ - 1);
            CPA16(STb + r * (XS_STR * 4) + g * 16, (const char*)star + gi * 256 + g * 16);
        }
        for (int idx = tid; idx < FC_ROWS * 32; idx += 128) {
            int r = idx >> 5, g = idx & 31;
            CPA16(FCb + r * (FCS * 4) + g * 16,
                  (const char*)g_fcombT + ((long)r * NP + i0p) * 4 + g * 16);
        }
        { int gi = i0p + tid; nsb[tid] = (gi < N_) ? g_ns[gi] : 1e30f; }
        CP_COMMIT(); CP_WAIT0();
        __syncthreads();
    }

    float acc[17][4];
#pragma unroll
    for (int n = 0; n < 17; n++)
#pragma unroll
        for (int q = 0; q < 4; q++) acc[n][q] = 0.f;

    for (int c = 0; c < nc; c++) {
        const int i0 = (ch0 + c) * 128;

        // MMA1 half -> exp in regs -> fused MMA2
#pragma unroll
        for (int half = 0; half < 2; half++) {
            float cf[8][4];
#pragma unroll
            for (int n = 0; n < 8; n++)
#pragma unroll
                for (int q = 0; q < 4; q++) cf[n][q] = 0.f;
#pragma unroll
            for (int ks = 0; ks < 8; ks++) {
#pragma unroll
                for (int n8 = 0; n8 < 8; n8++) {
                    int nt = half * 8 + n8;
                    uint2 q = *(const uint2*)&STs[(nt * 8 + r0) * XS_STR + ks * 8 + 2 * c0l];
                    uint32_t b[2] = {q.x, q.y};
                    mma8(cf[n8], aF[ks], b);
                }
            }
#pragma unroll
            for (int n8 = 0; n8 < 8; n8++) {
                int nt = half * 8 + n8;
                int ic0 = nt * 8 + 2 * c0l, ic1 = ic0 + 1;
                float ns0 = nsb[ic0], ns1 = nsb[ic1];
                float t00 = 2.f * cf[n8][0] - nx0, t01 = 2.f * cf[n8][1] - nx0;
                float t10 = 2.f * cf[n8][2] - nx1, t11 = 2.f * cf[n8][3] - nx1;
                if (t00 >= ns0) atomicMin(&g_match[j0 + jw + r0], i0 + ic0);
                if (t01 >= ns1) atomicMin(&g_match[j0 + jw + r0], i0 + ic1);
                if (t10 >= ns0) atomicMin(&g_match[j0 + jw + r0 + 8], i0 + ic0);
                if (t11 >= ns1) atomicMin(&g_match[j0 + jw + r0 + 8], i0 + ic1);
                uint32_t a2[4];
                a2[0] = __float_as_uint(__expf(t00));
                a2[1] = __float_as_uint(__expf(t10));
                a2[2] = __float_as_uint(__expf(t01));
                a2[3] = __float_as_uint(__expf(t11));
#pragma unroll
                for (int nt2 = 0; nt2 < 17; nt2++) {
                    uint2 q = *(const uint2*)&FCs[(nt2 * 8 + r0) * FCS + nt * 8 + 2 * c0l];
                    uint32_t b[2] = {q.x, q.y};
                    mma8(acc[nt2], a2, b);
                }
            }
        }

        // reload buffers for next chunk (cross-CTA overlap hides this)
        if (c + 1 < nc) {
            __syncthreads();   // consumers done
            const int i0n = i0 + 128;
            for (int idx = tid; idx < 128 * 16; idx += 128) {
                int r = idx >> 4, g = idx & 15;
                long gi = min(i0n + r, N_ - 1);
                CPA16(STb + r * (XS_STR * 4) + g * 16, (const char*)star + gi * 256 + g * 16);
            }
            for (int idx = tid; idx < FC_ROWS * 32; idx += 128) {
                int r = idx >> 5, g = idx & 31;
                CPA16(FCb + r * (FCS * 4) + g * 16,
                      (const char*)g_fcombT + ((long)r * NP + i0n) * 4 + g * 16);
            }
            { int gi = i0n + tid; nsb[tid] = (gi < N_) ? g_ns[gi] : 1e30f; }
            CP_COMMIT(); CP_WAIT0();
            __syncthreads();
        }
    }

    // writeback
    const int jr0 = j0 + jw + r0, jr1 = jr0 + 8;
#pragma unroll
    for (int nt = 0; nt < 17; nt++) {
        int n = nt * 8 + 2 * c0l;
        if (n < 64) {
            *(float2*)&g_acc1_part[slab][jr0][n] = make_float2(acc[nt][0], acc[nt][1]);
            *(float2*)&g_acc1_part[slab][jr1][n] = make_float2(acc[nt][2], acc[nt][3]);
        } else if (n < 128) {
            *(float2*)&g_acc2_part[slab][jr0][n - 64] = make_float2(acc[nt][0], acc[nt][1]);
            *(float2*)&g_acc2_part[slab][jr1][n - 64] = make_float2(acc[nt][2], acc[nt][3]);
        } else if (n == 128) {
            g_esum_part[slab][jr0] = acc[nt][0];
            g_esum_part[slab][jr1] = acc[nt][2];
        }
    }
}

// ---------------- K2: middle — xt, y = xt@W+b, argmin label ------------------
__global__ __launch_bounds__(128)
void k_mid(const float* __restrict__ f1, const float* __restrict__ f2,
           const float* __restrict__ W1, const float* __restrict__ b1,
           const float* __restrict__ W2, const float* __restrict__ b2,
           const float* __restrict__ u1, const float* __restrict__ u2) {
    int j = blockIdx.x;
    int t = threadIdx.x;

    __shared__ float xts[D_];
    __shared__ float ys[DY_];
    __shared__ float esum_s;
    __shared__ float ny_s;
    __shared__ float redv[128];
    __shared__ int   redi[128];

    int  mi = g_match[j];
    bool hm = (mi != 0x7fffffff);
    if (t == 0) {
        float s = 0.f;
        for (int k = 0; k < NSLAB_A; k++) s += g_esum_part[k][j];
        esum_s = s;
    }
    __syncthreads();

    for (int br = 0; br < 2; br++) {
        const float* f  = br ? f2 : f1;
        const float* W  = br ? W2 : W1;
        const float* bb = br ? b2 : b1;
        const float* u  = br ? u2 : u1;

        if (t < D_) {
            float a = 0.f;
            if (br) { for (int k = 0; k < NSLAB_A; k++) a += g_acc2_part[k][j][t]; }
            else    { for (int k = 0; k < NSLAB_A; k++) a += g_acc1_part[k][j][t]; }
            float v = hm ? f[mi * D_ + t] : a / esum_s;
            xts[t] = v;
            if (br) g_xt2[j][t] = v; else g_xt1[j][t] = v;
        }
        __syncthreads();
        if (t == 0) {
            float s = 0.f;
            for (int d = 0; d < D_; d++) s += xts[d] * xts[d];
            if (br) g_nxt2[j] = s; else g_nxt1[j] = s;
        }
        if (t < DY_) {
            float a = bb[t];
            for (int d = 0; d < D_; d++) a += xts[d] * W[d * DY_ + t];
            ys[t] = a;
        }
        __syncthreads();
        if (t == 0) {
            float s = 0.f;
            for (int dy = 0; dy < DY_; dy++) s += ys[dy] * ys[dy];
            ny_s = s;
        }
        __syncthreads();

        float v = FLT_MAX;
        int   vi = 0x7fffffff;
        if (t < L_) {
            float nu = 0.f, dot = 0.f;
            for (int dy = 0; dy < DY_; dy++) {
                float uu = u[t * DY_ + dy];
                nu += uu * uu;
                dot += uu * ys[dy];
            }
            v = fmaxf(ny_s + nu - 2.f * dot, 0.f);
            vi = t;
        }
        redv[t] = v; redi[t] = vi;
        __syncthreads();
        for (int off = 64; off > 0; off >>= 1) {
            if (t < off) {
                float v2 = redv[t + off]; int i2 = redi[t + off];
                if (v2 < redv[t] || (v2 == redv[t] && i2 < redi[t])) {
                    redv[t] = v2; redi[t] = i2;
                }
            }
            __syncthreads();
        }
        if (t == 0) { if (br) g_yidx2[j] = redi[0]; else g_yidx1[j] = redi[0]; }
        __syncthreads();
    }
}

// ---------------- phase C ----------------------------------------------------
// 128 threads (4 warps, JT=64), 2 CTAs/SM. Single-buffered F + SL.
// smem (bytes): F 36864 | SL 21760 | MT 25856 | LI 512 | YJ 256 = 85248
#define SC_F  0
#define SC_SL 36864
#define SC_MT 58624
#define SC_LI 84480
#define SC_YJ 84992
#define SC_SIZE 85248

__global__ __launch_bounds__(128, 2)
void k_phaseC(const float* __restrict__ f1, const float* __restrict__ f2,
              const float* __restrict__ ld1, const float* __restrict__ ld2,
              const int* __restrict__ li1, const int* __restrict__ li2) {
    extern __shared__ char smem[];
    float* Fs  = (float*)(smem + SC_F);
    float* SLs = (float*)(smem + SC_SL);
    float* mt  = (float*)(smem + SC_MT);    // [64][101]
    int*   lib = (int*)(smem + SC_LI);      // [128]
    int*   yjs = (int*)(smem + SC_YJ);      // [64]
    const uint32_t Fb = su32(Fs), SLb = su32(SLs);

    const int tid = threadIdx.x;
    const int w = tid >> 5, lane = tid & 31;
    const int r0 = lane >> 2, c0l = lane & 3;
    const int jw = w * 16;
    const int j0 = blockIdx.x * 64;
    const int slab = blockIdx.y;
    const int br = blockIdx.z;
    const int ch0 = slab * CPS_C;
    const int ch1 = min(ch0 + CPS_C, NCH_TOT);
    const int nc = ch1 - ch0;

    const float* f  = br ? f2 : f1;
    const float* ld = br ? ld2 : ld1;
    const int*   li = br ? li2 : li1;
    const float (*xt)[D_] = br ? g_xt2 : g_xt1;
    const float* nxt = br ? g_nxt2 : g_nxt1;
    const int*   yix = br ? g_yidx2 : g_yidx1;
    float (*nump)[B_][DY_] = br ? g_num2_part : g_num1_part;
    float (*denp)[B_]      = br ? g_den2_part : g_den1_part;

    // A-fragments straight from global xt (once)
    uint32_t aF[8][4];
#pragma unroll
    for (int ks = 0; ks < 8; ks++) {
        uint2 p0 = *(const uint2*)&xt[j0 + jw + r0][ks * 8 + 2 * c0l];
        uint2 p1 = *(const uint2*)&xt[j0 + jw + r0 + 8][ks * 8 + 2 * c0l];
        aF[ks][0] = p0.x; aF[ks][1] = p1.x; aF[ks][2] = p0.y; aF[ks][3] = p1.y;
    }
    const float nxt0 = nxt[j0 + jw + r0];
    const float nxt1 = nxt[j0 + jw + r0 + 8];
    if (tid < 64) yjs[tid] = yix[j0 + tid];
    __syncthreads();
    // mt[j][l] = exp(-eta * ld[l][yidx_j]) for this block's 64 j's
    for (int idx = tid; idx < 64 * L_; idx += 128) {
        int j = idx / L_, l = idx - j * L_;
        mt[j * 101 + l] = __expf(-ETA_ * ld[l * L_ + yjs[j]]);
    }

    // chunk 0 loads
    {
        const int i0p = ch0 * 128;
        for (int idx = tid; idx < 128 * 16; idx += 128) {
            int r = idx >> 4, g = idx & 15;
            long gi = min(i0p + r, N_ - 1);
            CPA16(Fb + r * (XS_STR * 4) + g * 16, (const char*)f + gi * 256 + g * 16);
        }
        for (int idx = tid; idx < SL_ROWS * 32; idx += 128) {
            int r = idx >> 5, g = idx & 31;
            CPA16(SLb + r * (SLS * 4) + g * 16,
                  (const char*)&g_slbcT[br][0][0] + ((long)r * NP + i0p) * 4 + g * 16);
        }
        lib[tid] = li[min(i0p + tid, N_ - 1)];
        CP_COMMIT(); CP_WAIT0();
        __syncthreads();
    }

    float acc[5][4];
#pragma unroll
    for (int n = 0; n < 5; n++)
#pragma unroll
        for (int q = 0; q < 4; q++) acc[n][q] = 0.f;

    for (int c = 0; c < nc; c++) {
#pragma unroll
        for (int half = 0; half < 2; half++) {
            float cf[8][4];
#pragma unroll
            for (int n = 0; n < 8; n++)
#pragma unroll
                for (int q = 0; q < 4; q++) cf[n][q] = 0.f;
#pragma unroll
            for (int ks = 0; ks < 8; ks++) {
#pragma unroll
                for (int n8 = 0; n8 < 8; n8++) {
                    int nt = half * 8 + n8;
                    uint2 q = *(const uint2*)&Fs[(nt * 8 + r0) * XS_STR + ks * 8 + 2 * c0l];
                    uint32_t b[2] = {q.x, q.y};
                    mma8(cf[n8], aF[ks], b);
                }
            }
#pragma unroll
            for (int n8 = 0; n8 < 8; n8++) {
                int nt = half * 8 + n8;
                int ic0 = nt * 8 + 2 * c0l, ic1 = ic0 + 1;
                int l0 = lib[ic0], l1 = lib[ic1];
                float m00 = mt[(jw + r0) * 101 + l0], m01 = mt[(jw + r0) * 101 + l1];
                float m10 = mt[(jw + r0 + 8) * 101 + l0], m11 = mt[(jw + r0 + 8) * 101 + l1];
                uint32_t a2[4];
                a2[0] = __float_as_uint(__expf(2.f * cf[n8][0] - nxt0) * m00);
                a2[1] = __float_as_uint(__expf(2.f * cf[n8][2] - nxt1) * m10);
                a2[2] = __float_as_uint(__expf(2.f * cf[n8][1] - nxt0) * m01);
                a2[3] = __float_as_uint(__expf(2.f * cf[n8][3] - nxt1) * m11);
#pragma unroll
                for (int nt2 = 0; nt2 < 5; nt2++) {
                    uint2 q = *(const uint2*)&SLs[(nt2 * 8 + r0) * SLS + nt * 8 + 2 * c0l];
                    uint32_t b[2] = {q.x, q.y};
                    mma8(acc[nt2], a2, b);
                }
            }
        }

        if (c + 1 < nc) {
            __syncthreads();
            const int i0n = (ch0 + c + 1) * 128;
            for (int idx = tid; idx < 128 * 16; idx += 128) {
                int r = idx >> 4, g = idx & 15;
                long gi = min(i0n + r, N_ - 1);
                CPA16(Fb + r * (XS_STR * 4) + g * 16, (const char*)f + gi * 256 + g * 16);
            }
            for (int idx = tid; idx < SL_ROWS * 32; idx += 128) {
                int r = idx >> 5, g = idx & 31;
                CPA16(SLb + r * (SLS * 4) + g * 16,
                      (const char*)&g_slbcT[br][0][0] + ((long)r * NP + i0n) * 4 + g * 16);
            }
            lib[tid] = li[min(i0n + tid, N_ - 1)];
            CP_COMMIT(); CP_WAIT0();
            __syncthreads();
        }
    }

    const int jr0 = j0 + jw + r0, jr1 = jr0 + 8;
#pragma unroll
    for (int nt = 0; nt < 5; nt++) {
        int n = nt * 8 + 2 * c0l;
        if (n < 32) {
            *(float2*)&nump[slab][jr0][n] = make_float2(acc[nt][0], acc[nt][1]);
            *(float2*)&nump[slab][jr1][n] = make_float2(acc[nt][2], acc[nt][3]);
        } else if (n == 32) {
            denp[slab][jr0] = acc[nt][0];
            denp[slab][jr1] = acc[nt][2];
        }
    }
}

// ---------------- K4: reduce partials ----------------------------------------
__global__ void k_out(float* __restrict__ out) {
    int gid = blockIdx.x * blockDim.x + threadIdx.x;
    if (gid >= B_ * DY_) return;
    int j = gid >> 5, dy = gid & 31;
    float n1 = 0.f, d1 = 0.f, n2 = 0.f, d2 = 0.f;
    for (int s = 0; s < NSLAB_C; s++) {
        n1 += g_num1_part[s][j][dy];
        d1 += g_den1_part[s][j];
        n2 += g_num2_part[s][j][dy];
        d2 += g_den2_part[s][j];
    }
    out[gid] = 0.5f * (n1 / d1 + n2 / d2);
}

// ---------------- launch -----------------------------------------------------
extern "C" void kernel_launch(void* const* d_in, const int* in_sizes, int n_in,
                              void* d_out, int out_size) {
    const float* x    = (const float*)d_in[0];
    const float* star = (const float*)d_in[1];
    const float* slb  = (const float*)d_in[2];
    const float* f1   = (const float*)d_in[3];
    const float* f2   = (const float*)d_in[4];
    const float* u1   = (const float*)d_in[5];
    const float* u2   = (const float*)d_in[6];
    const float* ld1  = (const float*)d_in[7];
    const float* ld2  = (const float*)d_in[8];
    const float* W1   = (const float*)d_in[9];
    const float* b1   = (const float*)d_in[10];
    const float* W2   = (const float*)d_in[11];
    const float* b2   = (const float*)d_in[12];
    const int*   li1  = (const int*)d_in[13];
    const int*   li2  = (const int*)d_in[14];
    float* out = (float*)d_out;

    cudaFuncSetAttribute(k_phaseA, cudaFuncAttributeMaxDynamicSharedMemorySize, SA_SIZE);
    cudaFuncSetAttribute(k_phaseC, cudaFuncAttributeMaxDynamicSharedMemorySize, SC_SIZE);

    k_prep<<<(B_ + 3 * N_ + 255) / 256, 256>>>(x, star, f1, f2);
    k_tfT<<<dim3(NP / 32, 5), dim3(32, 8)>>>(f1, f2);
    k_tsT<<<dim3(NP / 32, 1, 2), dim3(32, 8)>>>(slb);
    k_phaseA<<<dim3(32, NSLAB_A), 128, SA_SIZE>>>(x, star);
    k_mid<<<B_, 128>>>(f1, f2, W1, b1, W2, b2, u1, u2);
    k_phaseC<<<dim3(32, NSLAB_C, 2), 128, SC_SIZE>>>(f1, f2, ld1, ld2, li1, li2);
    k_out<<<(B_ * DY_ + 255) / 256, 256>>>(out);
}